// round 8
// baseline (speedup 1.0000x reference)
#include <cuda_runtime.h>
#include <cuda_bf16.h>
#include <cstdint>
#include <math.h>

// Problem constants
#define B    4096
#define NF   64
#define KB   48
#define DE   64
#define F    4096
#define E    8
#define H    1024
#define O    512
#define T    2
#define TH   256

// ---------------- low-level helpers (plain sm_80+ PTX only) ----------------
__device__ __forceinline__ uint32_t smem_to_u32(const void* p) {
    uint32_t a;
    asm("{ .reg .u64 t; cvta.to.shared.u64 t, %1; cvt.u32.u64 %0, t; }" : "=r"(a) : "l"(p));
    return a;
}
__device__ __forceinline__ void cp_async16(uint32_t dst, const void* src, int src_bytes) {
    asm volatile("cp.async.cg.shared.global [%0], [%1], 16, %2;"
                 :: "r"(dst), "l"(src), "r"(src_bytes) : "memory");
}
#define CP_COMMIT() asm volatile("cp.async.commit_group;" ::: "memory")
#define CP_WAIT(n)  asm volatile("cp.async.wait_group %0;" :: "n"(n) : "memory")

__device__ __forceinline__ void ldsm_x4(uint32_t* r, uint32_t addr) {
    asm volatile("ldmatrix.sync.aligned.m8n8.x4.shared.b16 {%0,%1,%2,%3}, [%4];"
                 : "=r"(r[0]), "=r"(r[1]), "=r"(r[2]), "=r"(r[3]) : "r"(addr));
}
__device__ __forceinline__ void mma_bf16(float* c, const uint32_t* a, const uint32_t* b) {
    asm volatile(
        "mma.sync.aligned.m16n8k16.row.col.f32.bf16.bf16.f32 "
        "{%0,%1,%2,%3}, {%4,%5,%6,%7}, {%8,%9}, {%0,%1,%2,%3};"
        : "+f"(c[0]), "+f"(c[1]), "+f"(c[2]), "+f"(c[3])
        : "r"(a[0]), "r"(a[1]), "r"(a[2]), "r"(a[3]), "r"(b[0]), "r"(b[1]));
}
__device__ __forceinline__ uint32_t pack_bf16x2(float v0, float v1) {
    __nv_bfloat162 h = __halves2bfloat162(__float2bfloat16(v0), __float2bfloat16(v1));
    return *(uint32_t*)&h;
}

// ---------------- device scratch ----------------
__device__ __nv_bfloat16 g_flat_hi[(size_t)B * F];     // 32 MB
__device__ __nv_bfloat16 g_flat_lo[(size_t)B * F];     // 32 MB
__device__ __nv_bfloat16 g_w1t_hi[(size_t)E * H * F];  // 64 MB  [e][h][f]
__device__ __nv_bfloat16 g_w1t_lo[(size_t)E * H * F];  // 64 MB
__device__ __nv_bfloat16 g_w2t_hi[(size_t)E * O * H];  // 8 MB   [e][o][h]
__device__ __nv_bfloat16 g_w2t_lo[(size_t)E * O * H];  // 8 MB
__device__ __nv_bfloat16 g_h_hi[(size_t)2 * B * H];    // 16 MB
__device__ __nv_bfloat16 g_h_lo[(size_t)2 * B * H];    // 16 MB
__device__ float g_eo[(size_t)2 * B * O];              // 16 MB
__device__ int   g_count[E];
__device__ int   g_base[E];
__device__ int   g_cursor[E];
__device__ int   g_te[B * 2];
__device__ float g_tg[B * 2];
__device__ int   g_rows[2 * B];
__device__ float g_gates[2 * B];
__device__ int   g_pair[B * 2];

// ---------------- init ----------------
__global__ void k_init() {
    if (threadIdx.x < E) g_count[threadIdx.x] = 0;
}

// ---------------- weight split + transpose: W[e][k][n] -> T[e][n][k] bf16 hi/lo ----------------
// grid (Ndim/32, Kdim/32, E), block 256 (flat). Vectorized uint2 stores (4 k per thread).
__global__ __launch_bounds__(256) void k_wsplit(
    const float* __restrict__ W, __nv_bfloat16* __restrict__ Thi,
    __nv_bfloat16* __restrict__ Tlo, int Kdim, int Ndim)
{
    __shared__ float t[32][33];
    int e = blockIdx.z;
    int kb = blockIdx.y * 32;
    int nb = blockIdx.x * 32;
    int tid = threadIdx.x;
    int tx = tid & 31;       // n-local for load
    int ty = tid >> 5;       // 0..7
    const float* Wb = W + (size_t)e * Kdim * Ndim;
    #pragma unroll
    for (int i = ty; i < 32; i += 8)
        t[i][tx] = Wb[(size_t)(kb + i) * Ndim + nb + tx];   // t[k][n]
    __syncthreads();

    // store phase: thread -> (n = tid>>3, k-quad = (tid&7)*4)
    int sn = tid >> 3;            // 0..31
    int sk = (tid & 7) * 4;       // 0,4,...,28
    float v0 = t[sk + 0][sn];
    float v1 = t[sk + 1][sn];
    float v2 = t[sk + 2][sn];
    float v3 = t[sk + 3][sn];
    __nv_bfloat16 h0 = __float2bfloat16(v0), h1 = __float2bfloat16(v1);
    __nv_bfloat16 h2 = __float2bfloat16(v2), h3 = __float2bfloat16(v3);
    float l0 = v0 - __bfloat162float(h0), l1 = v1 - __bfloat162float(h1);
    float l2 = v2 - __bfloat162float(h2), l3 = v3 - __bfloat162float(h3);
    __nv_bfloat162 hp0 = __halves2bfloat162(h0, h1), hp1 = __halves2bfloat162(h2, h3);
    uint2 hv = make_uint2(*(uint32_t*)&hp0, *(uint32_t*)&hp1);
    uint2 lv = make_uint2(pack_bf16x2(l0, l1), pack_bf16x2(l2, l3));
    size_t o = ((size_t)e * Ndim + nb + sn) * Kdim + kb + sk;
    *(uint2*)&Thi[o] = hv;
    *(uint2*)&Tlo[o] = lv;
}

// ---------------- PLE + embedding + ReLU -> flat hi/lo ----------------
// grid (NF, B/64), block 256. 64 rows per block; thread = (4 rows) x (4 d-cols).
__global__ __launch_bounds__(256) void k_ple(
    const float* __restrict__ x, const float* __restrict__ plew,
    const float* __restrict__ pleb, const float* __restrict__ embW,
    const float* __restrict__ embb)
{
    int n = blockIdx.x;
    int b0 = blockIdx.y * 64;
    int tid = threadIdx.x;

    __shared__ float Wsh[KB * DE];      // 12 KB
    __shared__ float wsh[KB], bsh[KB], ebias[DE];
    __shared__ float xs[64];
    __shared__ float enc_sh[64][KB];    // 12 KB

    for (int i = tid; i < KB * DE; i += 256) Wsh[i] = embW[(size_t)n * KB * DE + i];
    if (tid < KB) { wsh[tid] = plew[n * KB + tid]; bsh[tid] = pleb[n * KB + tid]; }
    if (tid < DE) ebias[tid] = embb[n * DE + tid];
    if (tid < 64) xs[tid] = x[(b0 + tid) * NF + n];
    __syncthreads();

    for (int idx = tid; idx < 64 * KB; idx += 256) {
        int bl = idx / KB, k = idx - bl * KB;
        float enc = bsh[k] + wsh[k] * xs[bl];
        if (k == 0)           enc = fminf(enc, 1.f);
        else if (k == KB - 1) enc = fmaxf(enc, 0.f);
        else                  enc = fminf(fmaxf(enc, 0.f), 1.f);
        enc_sh[bl][k] = enc;
    }
    __syncthreads();

    int c0 = (tid & 15) * 4;
    int r0 = (tid >> 4) * 4;

    float acc[4][4];
    #pragma unroll
    for (int r = 0; r < 4; r++)
        #pragma unroll
        for (int j = 0; j < 4; j++) acc[r][j] = ebias[c0 + j];

    #pragma unroll
    for (int k4 = 0; k4 < KB; k4 += 4) {
        float4 wv[4];
        #pragma unroll
        for (int kk = 0; kk < 4; kk++)
            wv[kk] = *(const float4*)&Wsh[(k4 + kk) * DE + c0];
        #pragma unroll
        for (int r = 0; r < 4; r++) {
            float4 ev = *(const float4*)&enc_sh[r0 + r][k4];
            const float* w0 = (const float*)&wv[0];
            const float* w1 = (const float*)&wv[1];
            const float* w2 = (const float*)&wv[2];
            const float* w3 = (const float*)&wv[3];
            #pragma unroll
            for (int j = 0; j < 4; j++)
                acc[r][j] += ev.x * w0[j] + ev.y * w1[j] + ev.z * w2[j] + ev.w * w3[j];
        }
    }

    #pragma unroll
    for (int r = 0; r < 4; r++) {
        int b = b0 + r0 + r;
        uint32_t hw[2], lw[2];
        #pragma unroll
        for (int p = 0; p < 2; p++) {
            float v0 = fmaxf(acc[r][p * 2 + 0], 0.f);
            float v1 = fmaxf(acc[r][p * 2 + 1], 0.f);
            __nv_bfloat16 h0 = __float2bfloat16(v0);
            __nv_bfloat16 h1 = __float2bfloat16(v1);
            hw[p] = pack_bf16x2(v0, v1);
            lw[p] = pack_bf16x2(v0 - __bfloat162float(h0), v1 - __bfloat162float(h1));
        }
        size_t idx = (size_t)b * F + n * DE + c0;
        *(uint2*)&g_flat_hi[idx] = make_uint2(hw[0], hw[1]);
        *(uint2*)&g_flat_lo[idx] = make_uint2(lw[0], lw[1]);
    }
}

// ---------------- gate ----------------
__global__ __launch_bounds__(256) void k_gate(
    const float* __restrict__ gW, const float* __restrict__ gb)
{
    int b = blockIdx.x;
    int tid = threadIdx.x;
    int lane = tid & 31, wid = tid >> 5;

    float acc[E];
    #pragma unroll
    for (int e = 0; e < E; e++) acc[e] = 0.f;

    const __nv_bfloat16* xh = g_flat_hi + (size_t)b * F;
    const __nv_bfloat16* xl = g_flat_lo + (size_t)b * F;
    #pragma unroll
    for (int f0 = 0; f0 < F; f0 += 256 * 4) {
        int f = f0 + tid * 4;
        uint2 hv = *(const uint2*)&xh[f];
        uint2 lv = *(const uint2*)&xl[f];
        __nv_bfloat162 h01 = *(__nv_bfloat162*)&hv.x, h23 = *(__nv_bfloat162*)&hv.y;
        __nv_bfloat162 l01 = *(__nv_bfloat162*)&lv.x, l23 = *(__nv_bfloat162*)&lv.y;
        float xv[4];
        xv[0] = __bfloat162float(__low2bfloat16(h01)) + __bfloat162float(__low2bfloat16(l01));
        xv[1] = __bfloat162float(__high2bfloat16(h01)) + __bfloat162float(__high2bfloat16(l01));
        xv[2] = __bfloat162float(__low2bfloat16(h23)) + __bfloat162float(__low2bfloat16(l23));
        xv[3] = __bfloat162float(__high2bfloat16(h23)) + __bfloat162float(__high2bfloat16(l23));
        #pragma unroll
        for (int q = 0; q < 4; q++) {
            const float4* gwp = (const float4*)&gW[(f + q) * E];
            float4 g0 = gwp[0], g1 = gwp[1];
            acc[0] += xv[q] * g0.x; acc[1] += xv[q] * g0.y;
            acc[2] += xv[q] * g0.z; acc[3] += xv[q] * g0.w;
            acc[4] += xv[q] * g1.x; acc[5] += xv[q] * g1.y;
            acc[6] += xv[q] * g1.z; acc[7] += xv[q] * g1.w;
        }
    }
    #pragma unroll
    for (int e = 0; e < E; e++)
        for (int off = 16; off; off >>= 1)
            acc[e] += __shfl_down_sync(0xffffffffu, acc[e], off);

    __shared__ float sb[E][8];
    __shared__ float slog[E];
    if (lane == 0) {
        #pragma unroll
        for (int e = 0; e < E; e++) sb[e][wid] = acc[e];
    }
    __syncthreads();
    if (tid < E) {
        float s = 0.f;
        #pragma unroll
        for (int w = 0; w < 8; w++) s += sb[tid][w];
        slog[tid] = s + gb[tid];
    }
    __syncthreads();
    if (tid == 0) {
        int i0 = 0;
        #pragma unroll
        for (int e = 1; e < E; e++) if (slog[e] > slog[i0]) i0 = e;
        int i1 = (i0 == 0) ? 1 : 0;
        #pragma unroll
        for (int e = 0; e < E; e++) if (e != i0 && slog[e] > slog[i1]) i1 = e;
        float e1 = __expf(slog[i1] - slog[i0]);
        float inv = 1.f / (1.f + e1);
        g_te[b * 2 + 0] = i0;  g_tg[b * 2 + 0] = inv;
        g_te[b * 2 + 1] = i1;  g_tg[b * 2 + 1] = e1 * inv;
        atomicAdd(&g_count[i0], 1);
        atomicAdd(&g_count[i1], 1);
    }
}

__global__ void k_scan() {
    if (threadIdx.x == 0) {
        int s = 0;
        for (int e = 0; e < E; e++) { g_base[e] = s; g_cursor[e] = s; s += g_count[e]; }
    }
}

__global__ __launch_bounds__(256) void k_assign() {
    int b = blockIdx.x * 256 + threadIdx.x;
    if (b >= B) return;
    #pragma unroll
    for (int j = 0; j < 2; j++) {
        int e = g_te[b * 2 + j];
        int slot = atomicAdd(&g_cursor[e], 1);
        g_rows[slot]  = b;
        g_gates[slot] = g_tg[b * 2 + j];
        g_pair[b * 2 + j] = slot;
    }
}

// ---------------- split-bf16 register-MMA expert GEMM ----------------
// CTA tile 128x128, 8 warps (2m x 4n), warp tile 64x32, k-tile 64, 3-stage cp.async.
#define GBM 128
#define GKT 64
#define STAGE_BYTES 65536
#define OFF_AHI 0
#define OFF_ALO 16384
#define OFF_BHI 32768
#define OFF_BLO 49152

template<int KTOT, int NTOT, int MODE>
__global__ __launch_bounds__(256, 1) void k_mma_gemm(
    const __nv_bfloat16* __restrict__ Ahi, const __nv_bfloat16* __restrict__ Alo,
    const __nv_bfloat16* __restrict__ Whi, const __nv_bfloat16* __restrict__ Wlo,
    const float* __restrict__ bias)
{
    int e = blockIdx.z;
    int cnt = g_count[e];
    int m0 = blockIdx.y * GBM;
    if (m0 >= cnt) return;
    int base = g_base[e];
    int n0 = blockIdx.x * 128;

    extern __shared__ char smem[];
    uint32_t sb = smem_to_u32(smem);
    __shared__ int rows_s[GBM];

    int tid = threadIdx.x;
    int lane = tid & 31, wid = tid >> 5;

    if (MODE == 0 && tid < GBM) {
        int m = m0 + tid;
        rows_s[tid] = (m < cnt) ? g_rows[base + m] : -1;
    }
    __syncthreads();

    // -------- loader setup: thread -> (row 0..127, 4 chunks of 16B) --------
    int lrow = tid >> 1;
    int lcb  = (tid & 1) * 4;
    const __nv_bfloat16 *arow_hi, *arow_lo;
    int abytes;
    if (MODE == 0) {
        int gr = rows_s[lrow];
        abytes = (gr >= 0) ? 16 : 0;
        int r = (gr >= 0) ? gr : 0;
        arow_hi = Ahi + (size_t)r * KTOT;
        arow_lo = Alo + (size_t)r * KTOT;
    } else {
        int m = m0 + lrow;
        abytes = (m < cnt) ? 16 : 0;
        size_t r = (m < cnt) ? (size_t)(base + m) : 0;
        arow_hi = Ahi + r * KTOT;
        arow_lo = Alo + r * KTOT;
    }
    const __nv_bfloat16* brow_hi = Whi + ((size_t)e * NTOT + n0 + lrow) * KTOT;
    const __nv_bfloat16* brow_lo = Wlo + ((size_t)e * NTOT + n0 + lrow) * KTOT;
    uint32_t lsw = (uint32_t)((lrow & 7) << 4);
    uint32_t lbase = (uint32_t)(lrow * 128);

    // -------- mma setup --------
    int wm = wid >> 2;            // 0..1
    int wn = wid & 3;             // 0..3
    int a_row = wm * 64 + (lane & 15);
    uint32_t a_c  = (uint32_t)((lane >> 4) * 16);
    uint32_t asw  = (uint32_t)((a_row & 7) << 4);
    int b_row = wn * 32 + (lane & 7) + ((lane >> 4) << 3);
    uint32_t b_c  = (uint32_t)(((lane >> 3) & 1) * 16);
    uint32_t bsw  = (uint32_t)((b_row & 7) << 4);

    float acc[4][4][4];
    #pragma unroll
    for (int i = 0; i < 4; i++)
        #pragma unroll
        for (int j = 0; j < 4; j++)
            #pragma unroll
            for (int q = 0; q < 4; q++) acc[i][j][q] = 0.f;

    const int NT = KTOT / GKT;

    #define LOAD_STAGE(stg_, kt_) do {                                           \
        uint32_t s_ = sb + (uint32_t)(stg_) * STAGE_BYTES;                        \
        int k0_ = (kt_) * GKT;                                                    \
        _Pragma("unroll")                                                         \
        for (int q = 0; q < 4; q++) {                                             \
            int ch = lcb + q;                                                     \
            uint32_t so = lbase + (((uint32_t)(ch * 16)) ^ lsw);                  \
            cp_async16(s_ + OFF_AHI + so, arow_hi + k0_ + ch * 8, abytes);        \
            cp_async16(s_ + OFF_ALO + so, arow_lo + k0_ + ch * 8, abytes);        \
            cp_async16(s_ + OFF_BHI + so, brow_hi + k0_ + ch * 8, 16);            \
            cp_async16(s_ + OFF_BLO + so, brow_lo + k0_ + ch * 8, 16);            \
        }                                                                         \
        CP_COMMIT();                                                              \
    } while (0)

    // prime stages 0,1
    LOAD_STAGE(0, 0);
    if (NT > 1) LOAD_STAGE(1, 1);

    int stg = 0;
    for (int kt = 0; kt < NT; kt++) {
        if (kt + 2 < NT) {
            int ns = stg + 2; if (ns >= 3) ns -= 3;
            LOAD_STAGE(ns, kt + 2);
            CP_WAIT(2);
        } else if (kt + 1 < NT) {
            CP_WAIT(1);
        } else {
            CP_WAIT(0);
        }
        __syncthreads();

        uint32_t s0 = sb + (uint32_t)stg * STAGE_BYTES;
        #pragma unroll
        for (int kk = 0; kk < 4; kk++) {
            uint32_t ah[4][4], al[4][4], bh[2][4], bl[2][4];
            #pragma unroll
            for (int i = 0; i < 4; i++) {
                uint32_t ro = (uint32_t)((a_row + i * 16) * 128);
                uint32_t addr = s0 + OFF_AHI + ro + ((a_c + kk * 32) ^ asw);
                ldsm_x4(ah[i], addr);
                ldsm_x4(al[i], addr + (OFF_ALO - OFF_AHI));
            }
            #pragma unroll
            for (int p = 0; p < 2; p++) {
                uint32_t ro = (uint32_t)((b_row + p * 16) * 128);
                uint32_t addr = s0 + OFF_BHI + ro + ((b_c + kk * 32) ^ bsw);
                ldsm_x4(bh[p], addr);
                ldsm_x4(bl[p], addr + (OFF_BLO - OFF_BHI));
            }
            #pragma unroll
            for (int i = 0; i < 4; i++)
                #pragma unroll
                for (int j = 0; j < 4; j++) {
                    const uint32_t* bhj = &bh[j >> 1][(j & 1) * 2];
                    const uint32_t* blj = &bl[j >> 1][(j & 1) * 2];
                    mma_bf16(acc[i][j], ah[i], bhj);
                    mma_bf16(acc[i][j], ah[i], blj);
                    mma_bf16(acc[i][j], al[i], bhj);
                }
        }
        __syncthreads();
        stg = (stg == 2) ? 0 : stg + 1;
    }
    #undef LOAD_STAGE

    // -------- epilogue --------
    int g = lane >> 2;
    int cg = (lane & 3) * 2;
    #pragma unroll
    for (int i = 0; i < 4; i++) {
        #pragma unroll
        for (int half = 0; half < 2; half++) {
            int m = m0 + wm * 64 + i * 16 + g + half * 8;
            if (m < cnt) {
                int slot = base + m;
                float gate = (MODE == 1) ? g_gates[slot] : 0.f;
                #pragma unroll
                for (int j = 0; j < 4; j++) {
                    int col = n0 + wn * 32 + j * 8 + cg;
                    float bv0 = bias[(size_t)e * NTOT + col];
                    float bv1 = bias[(size_t)e * NTOT + col + 1];
                    float v0 = acc[i][j][half * 2 + 0] + bv0;
                    float v1 = acc[i][j][half * 2 + 1] + bv1;
                    if (MODE == 0) {
                        v0 = fmaxf(v0, 0.f); v1 = fmaxf(v1, 0.f);
                        __nv_bfloat16 h0 = __float2bfloat16(v0);
                        __nv_bfloat16 h1 = __float2bfloat16(v1);
                        uint32_t hh = pack_bf16x2(v0, v1);
                        uint32_t ll = pack_bf16x2(v0 - __bfloat162float(h0),
                                                  v1 - __bfloat162float(h1));
                        *(uint32_t*)&g_h_hi[(size_t)slot * H + col] = hh;
                        *(uint32_t*)&g_h_lo[(size_t)slot * H + col] = ll;
                    } else {
                        float2 v = make_float2(gate * v0, gate * v1);
                        *(float2*)&g_eo[(size_t)slot * O + col] = v;
                    }
                }
            }
        }
    }
}

// ---------------- task towers ----------------
// 32 rows per block, grid B/32
__global__ __launch_bounds__(256) void k_tower(
    const float* __restrict__ tw1, const float* __restrict__ tb1,
    const float* __restrict__ tw2, const float* __restrict__ tb2,
    float* __restrict__ out)
{
    int b0 = blockIdx.x * 32;
    int tid = threadIdx.x;
    int lane = tid & 31, wid = tid >> 5;

    __shared__ float moe_sh[32][O];    // 64 KB
    __shared__ float sred[32][8];

    // gather: 2 rows in flight per 256 threads (128 float4 per row)
    {
        int rr = tid >> 7;            // 0..1
        int c = (tid & 127) * 4;      // 0..508
        #pragma unroll
        for (int rp = 0; rp < 16; rp++) {
            int r = rp * 2 + rr;
            int b = b0 + r;
            int s0 = g_pair[b * 2 + 0], s1 = g_pair[b * 2 + 1];
            float4 v0 = *(const float4*)&g_eo[(size_t)s0 * O + c];
            float4 v1 = *(const float4*)&g_eo[(size_t)s1 * O + c];
            *(float4*)&moe_sh[r][c] = make_float4(v0.x + v1.x, v0.y + v1.y,
                                                  v0.z + v1.z, v0.w + v1.w);
        }
    }
    __syncthreads();

    for (int t = 0; t < T; t++) {
        float acc[32];
        #pragma unroll
        for (int r = 0; r < 32; r++) acc[r] = 0.f;

        const float* w1 = tw1 + (size_t)t * O * TH + tid;
        for (int o = 0; o < O; o++) {
            float w = w1[(size_t)o * TH];
            #pragma unroll
            for (int r = 0; r < 32; r++) acc[r] += moe_sh[r][o] * w;
        }
        float bb = tb1[t * TH + tid];
        float w2 = tw2[t * TH + tid];

        #pragma unroll
        for (int r = 0; r < 32; r++) {
            float th = fmaxf(acc[r] + bb, 0.f);
            float v = th * w2;
            for (int off = 16; off; off >>= 1)
                v += __shfl_down_sync(0xffffffffu, v, off);
            if (lane == 0) sred[r][wid] = v;
        }
        __syncthreads();
        if (tid < 32) {
            float s = 0.f;
            #pragma unroll
            for (int w = 0; w < 8; w++) s += sred[tid][w];
            out[(b0 + tid) * T + t] = s + tb2[t];
        }
        __syncthreads();
    }
}

// ---------------- launch ----------------
extern "C" void kernel_launch(void* const* d_in, const int* in_sizes, int n_in,
                              void* d_out, int out_size)
{
    const float* x     = (const float*)d_in[0];
    const float* plew  = (const float*)d_in[1];
    const float* pleb  = (const float*)d_in[2];
    const float* embW  = (const float*)d_in[3];
    const float* embb  = (const float*)d_in[4];
    const float* gW    = (const float*)d_in[5];
    const float* gb    = (const float*)d_in[6];
    const float* eW1   = (const float*)d_in[7];
    const float* eb1   = (const float*)d_in[8];
    const float* eW2   = (const float*)d_in[9];
    const float* eb2   = (const float*)d_in[10];
    const float* tw1   = (const float*)d_in[11];
    const float* tb1   = (const float*)d_in[12];
    const float* tw2   = (const float*)d_in[13];
    const float* tb2   = (const float*)d_in[14];
    float* out = (float*)d_out;

    const int SMEM_BYTES = 3 * STAGE_BYTES;   // 196608
    static bool attr_done = false;
    if (!attr_done) {
        cudaFuncSetAttribute(k_mma_gemm<F, H, 0>, cudaFuncAttributeMaxDynamicSharedMemorySize, SMEM_BYTES);
        cudaFuncSetAttribute(k_mma_gemm<H, O, 1>, cudaFuncAttributeMaxDynamicSharedMemorySize, SMEM_BYTES);
        attr_done = true;
    }

    __nv_bfloat16 *w1t_hi, *w1t_lo, *w2t_hi, *w2t_lo, *flat_hi, *flat_lo, *h_hi, *h_lo;
    cudaGetSymbolAddress((void**)&w1t_hi, g_w1t_hi);
    cudaGetSymbolAddress((void**)&w1t_lo, g_w1t_lo);
    cudaGetSymbolAddress((void**)&w2t_hi, g_w2t_hi);
    cudaGetSymbolAddress((void**)&w2t_lo, g_w2t_lo);
    cudaGetSymbolAddress((void**)&flat_hi, g_flat_hi);
    cudaGetSymbolAddress((void**)&flat_lo, g_flat_lo);
    cudaGetSymbolAddress((void**)&h_hi, g_h_hi);
    cudaGetSymbolAddress((void**)&h_lo, g_h_lo);

    k_init<<<1, 32>>>();
    k_wsplit<<<dim3(H / 32, F / 32, E), 256>>>(eW1, w1t_hi, w1t_lo, F, H);
    k_wsplit<<<dim3(O / 32, H / 32, E), 256>>>(eW2, w2t_hi, w2t_lo, H, O);
    k_ple<<<dim3(NF, B / 64), 256>>>(x, plew, pleb, embW, embb);
    k_gate<<<B, 256>>>(gW, gb);
    k_scan<<<1, 32>>>();
    k_assign<<<(B + 255) / 256, 256>>>();

    k_mma_gemm<F, H, 0><<<dim3(H / 128, B / GBM, E), 256, SMEM_BYTES>>>(
        flat_hi, flat_lo, w1t_hi, w1t_lo, eb1);
    k_mma_gemm<H, O, 1><<<dim3(O / 128, B / GBM, E), 256, SMEM_BYTES>>>(
        h_hi, h_lo, w2t_hi, w2t_lo, eb2);

    k_tower<<<B / 32, 256>>>(tw1, tb1, tw2, tb2, out);
}

// round 9
// speedup vs baseline: 1.3143x; 1.3143x over previous
#include <cuda_runtime.h>
#include <cuda_fp16.h>
#include <cstdint>
#include <math.h>

// Problem constants
#define B    4096
#define NF   64
#define KB   48
#define DE   64
#define F    4096
#define E    8
#define H    1024
#define O    512
#define T    2
#define TH   256

// ---------------- low-level helpers (plain sm_80+ PTX only) ----------------
__device__ __forceinline__ uint32_t smem_to_u32(const void* p) {
    uint32_t a;
    asm("{ .reg .u64 t; cvta.to.shared.u64 t, %1; cvt.u32.u64 %0, t; }" : "=r"(a) : "l"(p));
    return a;
}
__device__ __forceinline__ void cp_async16(uint32_t dst, const void* src, int src_bytes) {
    asm volatile("cp.async.cg.shared.global [%0], [%1], 16, %2;"
                 :: "r"(dst), "l"(src), "r"(src_bytes) : "memory");
}
#define CP_COMMIT() asm volatile("cp.async.commit_group;" ::: "memory")
#define CP_WAIT(n)  asm volatile("cp.async.wait_group %0;" :: "n"(n) : "memory")

__device__ __forceinline__ void ldsm_x4(uint32_t* r, uint32_t addr) {
    asm volatile("ldmatrix.sync.aligned.m8n8.x4.shared.b16 {%0,%1,%2,%3}, [%4];"
                 : "=r"(r[0]), "=r"(r[1]), "=r"(r[2]), "=r"(r[3]) : "r"(addr));
}
__device__ __forceinline__ void mma_f16(float* c, const uint32_t* a, const uint32_t* b) {
    asm volatile(
        "mma.sync.aligned.m16n8k16.row.col.f32.f16.f16.f32 "
        "{%0,%1,%2,%3}, {%4,%5,%6,%7}, {%8,%9}, {%0,%1,%2,%3};"
        : "+f"(c[0]), "+f"(c[1]), "+f"(c[2]), "+f"(c[3])
        : "r"(a[0]), "r"(a[1]), "r"(a[2]), "r"(a[3]), "r"(b[0]), "r"(b[1]));
}
__device__ __forceinline__ uint32_t pack_h2(float v0, float v1) {
    __half2 h = __halves2half2(__float2half_rn(v0), __float2half_rn(v1));
    return *(uint32_t*)&h;
}

// ---------------- device scratch ----------------
__device__ __half g_flat_hi[(size_t)B * F];     // 32 MB
__device__ __half g_flat_lo[(size_t)B * F];     // 32 MB
__device__ __half g_w1t[(size_t)E * H * F];     // 64 MB  [e][h][f]  (single fp16)
__device__ __half g_w2t[(size_t)E * O * H];     // 8 MB   [e][o][h]
__device__ __half g_h_hi[(size_t)2 * B * H];    // 16 MB
__device__ __half g_h_lo[(size_t)2 * B * H];    // 16 MB
__device__ float g_eo[(size_t)2 * B * O];       // 16 MB
__device__ int   g_count[E];
__device__ int   g_base[E];
__device__ int   g_cursor[E];
__device__ int   g_te[B * 2];
__device__ float g_tg[B * 2];
__device__ int   g_rows[2 * B];
__device__ float g_gates[2 * B];
__device__ int   g_pair[B * 2];

// ---------------- init ----------------
__global__ void k_init() {
    if (threadIdx.x < E) g_count[threadIdx.x] = 0;
}

// ---------------- weight transpose: W[e][k][n] -> T[e][n][k] fp16 ----------------
__global__ __launch_bounds__(256) void k_wsplit(
    const float* __restrict__ W, __half* __restrict__ Tw, int Kdim, int Ndim)
{
    __shared__ float t[32][33];
    int e = blockIdx.z;
    int kb = blockIdx.y * 32;
    int nb = blockIdx.x * 32;
    int tx = threadIdx.x, ty = threadIdx.y;
    const float* Wb = W + (size_t)e * Kdim * Ndim;
    #pragma unroll
    for (int i = ty; i < 32; i += 8)
        t[i][tx] = Wb[(size_t)(kb + i) * Ndim + nb + tx];
    __syncthreads();
    #pragma unroll
    for (int i = ty; i < 32; i += 8) {
        float v = t[tx][i];
        size_t o = ((size_t)e * Ndim + nb + i) * Kdim + kb + tx;
        Tw[o] = __float2half_rn(v);
    }
}

// ---------------- PLE + embedding + ReLU -> flat hi/lo (fp16 split) ----------------
// grid (NF, B/64), block 256. 64 rows per block; thread = (4 rows) x (4 d-cols).
__global__ __launch_bounds__(256) void k_ple(
    const float* __restrict__ x, const float* __restrict__ plew,
    const float* __restrict__ pleb, const float* __restrict__ embW,
    const float* __restrict__ embb)
{
    int n = blockIdx.x;
    int b0 = blockIdx.y * 64;
    int tid = threadIdx.x;

    __shared__ float Wsh[KB * DE];      // 12 KB
    __shared__ float wsh[KB], bsh[KB], ebias[DE];
    __shared__ float xs[64];
    __shared__ float enc_sh[64][KB];    // 12 KB

    for (int i = tid; i < KB * DE; i += 256) Wsh[i] = embW[(size_t)n * KB * DE + i];
    if (tid < KB) { wsh[tid] = plew[n * KB + tid]; bsh[tid] = pleb[n * KB + tid]; }
    if (tid < DE) ebias[tid] = embb[n * DE + tid];
    if (tid < 64) xs[tid] = x[(b0 + tid) * NF + n];
    __syncthreads();

    for (int idx = tid; idx < 64 * KB; idx += 256) {
        int bl = idx / KB, k = idx - bl * KB;
        float enc = bsh[k] + wsh[k] * xs[bl];
        if (k == 0)           enc = fminf(enc, 1.f);
        else if (k == KB - 1) enc = fmaxf(enc, 0.f);
        else                  enc = fminf(fmaxf(enc, 0.f), 1.f);
        enc_sh[bl][k] = enc;
    }
    __syncthreads();

    int c0 = (tid & 15) * 4;
    int r0 = (tid >> 4) * 4;

    float acc[4][4];
    #pragma unroll
    for (int r = 0; r < 4; r++)
        #pragma unroll
        for (int j = 0; j < 4; j++) acc[r][j] = ebias[c0 + j];

    #pragma unroll
    for (int k4 = 0; k4 < KB; k4 += 4) {
        float4 wv[4];
        #pragma unroll
        for (int kk = 0; kk < 4; kk++)
            wv[kk] = *(const float4*)&Wsh[(k4 + kk) * DE + c0];
        #pragma unroll
        for (int r = 0; r < 4; r++) {
            float4 ev = *(const float4*)&enc_sh[r0 + r][k4];
            const float* w0 = (const float*)&wv[0];
            const float* w1 = (const float*)&wv[1];
            const float* w2 = (const float*)&wv[2];
            const float* w3 = (const float*)&wv[3];
            #pragma unroll
            for (int j = 0; j < 4; j++)
                acc[r][j] += ev.x * w0[j] + ev.y * w1[j] + ev.z * w2[j] + ev.w * w3[j];
        }
    }

    #pragma unroll
    for (int r = 0; r < 4; r++) {
        int b = b0 + r0 + r;
        uint32_t hw[2], lw[2];
        #pragma unroll
        for (int p = 0; p < 2; p++) {
            float v0 = fmaxf(acc[r][p * 2 + 0], 0.f);
            float v1 = fmaxf(acc[r][p * 2 + 1], 0.f);
            __half h0 = __float2half_rn(v0);
            __half h1 = __float2half_rn(v1);
            hw[p] = pack_h2(v0, v1);
            lw[p] = pack_h2(v0 - __half2float(h0), v1 - __half2float(h1));
        }
        size_t idx = (size_t)b * F + n * DE + c0;
        *(uint2*)&g_flat_hi[idx] = make_uint2(hw[0], hw[1]);
        *(uint2*)&g_flat_lo[idx] = make_uint2(lw[0], lw[1]);
    }
}

// ---------------- gate ----------------
__global__ __launch_bounds__(256) void k_gate(
    const float* __restrict__ gW, const float* __restrict__ gb)
{
    int b = blockIdx.x;
    int tid = threadIdx.x;
    int lane = tid & 31, wid = tid >> 5;

    float acc[E];
    #pragma unroll
    for (int e = 0; e < E; e++) acc[e] = 0.f;

    const __half* xh = g_flat_hi + (size_t)b * F;
    const __half* xl = g_flat_lo + (size_t)b * F;
    for (int f = tid; f < F; f += 256) {
        float xv = __half2float(xh[f]) + __half2float(xl[f]);
        #pragma unroll
        for (int e = 0; e < E; e++) acc[e] += xv * gW[f * E + e];
    }
    #pragma unroll
    for (int e = 0; e < E; e++)
        for (int off = 16; off; off >>= 1)
            acc[e] += __shfl_down_sync(0xffffffffu, acc[e], off);

    __shared__ float sb[E][8];
    __shared__ float slog[E];
    if (lane == 0) {
        #pragma unroll
        for (int e = 0; e < E; e++) sb[e][wid] = acc[e];
    }
    __syncthreads();
    if (tid < E) {
        float s = 0.f;
        #pragma unroll
        for (int w = 0; w < 8; w++) s += sb[tid][w];
        slog[tid] = s + gb[tid];
    }
    __syncthreads();
    if (tid == 0) {
        int i0 = 0;
        #pragma unroll
        for (int e = 1; e < E; e++) if (slog[e] > slog[i0]) i0 = e;
        int i1 = (i0 == 0) ? 1 : 0;
        #pragma unroll
        for (int e = 0; e < E; e++) if (e != i0 && slog[e] > slog[i1]) i1 = e;
        float e1 = __expf(slog[i1] - slog[i0]);
        float inv = 1.f / (1.f + e1);
        g_te[b * 2 + 0] = i0;  g_tg[b * 2 + 0] = inv;
        g_te[b * 2 + 1] = i1;  g_tg[b * 2 + 1] = e1 * inv;
        atomicAdd(&g_count[i0], 1);
        atomicAdd(&g_count[i1], 1);
    }
}

__global__ void k_scan() {
    if (threadIdx.x == 0) {
        int s = 0;
        for (int e = 0; e < E; e++) { g_base[e] = s; g_cursor[e] = s; s += g_count[e]; }
    }
}

__global__ __launch_bounds__(256) void k_assign() {
    int b = blockIdx.x * 256 + threadIdx.x;
    if (b >= B) return;
    #pragma unroll
    for (int j = 0; j < 2; j++) {
        int e = g_te[b * 2 + j];
        int slot = atomicAdd(&g_cursor[e], 1);
        g_rows[slot]  = b;
        g_gates[slot] = g_tg[b * 2 + j];
        g_pair[b * 2 + j] = slot;
    }
}

// ---------------- split-fp16 register-MMA expert GEMM (2-term) ----------------
// CTA tile 128x128, 8 warps (2m x 4n), warp tile 64x32, k-tile 64, 3-stage cp.async.
// A = activations as fp16 hi+lo (exact to 2^-23), B = weights single fp16.
#define GBM 128
#define GKT 64
#define STAGE_BYTES 49152
#define OFF_AHI 0
#define OFF_ALO 16384
#define OFF_B   32768

template<int KTOT, int NTOT, int MODE>
__global__ __launch_bounds__(256, 1) void k_mma_gemm(
    const __half* __restrict__ Ahi, const __half* __restrict__ Alo,
    const __half* __restrict__ Wt, const float* __restrict__ bias)
{
    int e = blockIdx.z;
    int cnt = g_count[e];
    int m0 = blockIdx.y * GBM;
    if (m0 >= cnt) return;
    int base = g_base[e];
    int n0 = blockIdx.x * 128;

    extern __shared__ char smem[];
    uint32_t sb = smem_to_u32(smem);
    __shared__ int rows_s[GBM];

    int tid = threadIdx.x;
    int lane = tid & 31, wid = tid >> 5;

    if (MODE == 0 && tid < GBM) {
        int m = m0 + tid;
        rows_s[tid] = (m < cnt) ? g_rows[base + m] : -1;
    }
    __syncthreads();

    // -------- loader setup: thread -> (row 0..127, 4 chunks of 16B) --------
    int lrow = tid >> 1;
    int lcb  = (tid & 1) * 4;
    const __half *arow_hi, *arow_lo;
    int abytes;
    if (MODE == 0) {
        int gr = rows_s[lrow];
        abytes = (gr >= 0) ? 16 : 0;
        int r = (gr >= 0) ? gr : 0;
        arow_hi = Ahi + (size_t)r * KTOT;
        arow_lo = Alo + (size_t)r * KTOT;
    } else {
        int m = m0 + lrow;
        abytes = (m < cnt) ? 16 : 0;
        size_t r = (m < cnt) ? (size_t)(base + m) : 0;
        arow_hi = Ahi + r * KTOT;
        arow_lo = Alo + r * KTOT;
    }
    const __half* brow = Wt + ((size_t)e * NTOT + n0 + lrow) * KTOT;
    uint32_t lsw = (uint32_t)((lrow & 7) << 4);
    uint32_t lbase = (uint32_t)(lrow * 128);

    // -------- mma setup --------
    int wm = wid >> 2;            // 0..1
    int wn = wid & 3;             // 0..3
    int a_row = wm * 64 + (lane & 15);
    uint32_t a_c  = (uint32_t)((lane >> 4) * 16);
    uint32_t asw  = (uint32_t)((a_row & 7) << 4);
    int b_row = wn * 32 + (lane & 7) + ((lane >> 4) << 3);
    uint32_t b_c  = (uint32_t)(((lane >> 3) & 1) * 16);
    uint32_t bsw  = (uint32_t)((b_row & 7) << 4);

    float acc[4][4][4];
    #pragma unroll
    for (int i = 0; i < 4; i++)
        #pragma unroll
        for (int j = 0; j < 4; j++)
            #pragma unroll
            for (int q = 0; q < 4; q++) acc[i][j][q] = 0.f;

    const int NT = KTOT / GKT;

    #define LOAD_STAGE(stg_, kt_) do {                                           \
        uint32_t s_ = sb + (uint32_t)(stg_) * STAGE_BYTES;                        \
        int k0_ = (kt_) * GKT;                                                    \
        _Pragma("unroll")                                                         \
        for (int q = 0; q < 4; q++) {                                             \
            int ch = lcb + q;                                                     \
            uint32_t so = lbase + (((uint32_t)(ch * 16)) ^ lsw);                  \
            cp_async16(s_ + OFF_AHI + so, arow_hi + k0_ + ch * 8, abytes);        \
            cp_async16(s_ + OFF_ALO + so, arow_lo + k0_ + ch * 8, abytes);        \
            cp_async16(s_ + OFF_B   + so, brow    + k0_ + ch * 8, 16);            \
        }                                                                         \
        CP_COMMIT();                                                              \
    } while (0)

    // prime stages 0,1
    LOAD_STAGE(0, 0);
    if (NT > 1) LOAD_STAGE(1, 1);

    int stg = 0;
    for (int kt = 0; kt < NT; kt++) {
        if (kt + 2 < NT) {
            int ns = stg + 2; if (ns >= 3) ns -= 3;
            LOAD_STAGE(ns, kt + 2);
            CP_WAIT(2);
        } else if (kt + 1 < NT) {
            CP_WAIT(1);
        } else {
            CP_WAIT(0);
        }
        __syncthreads();

        uint32_t s0 = sb + (uint32_t)stg * STAGE_BYTES;
        #pragma unroll
        for (int kk = 0; kk < 4; kk++) {
            uint32_t ah[4][4], al[4][4], bh[2][4];
            #pragma unroll
            for (int i = 0; i < 4; i++) {
                uint32_t ro = (uint32_t)((a_row + i * 16) * 128);
                uint32_t addr = s0 + OFF_AHI + ro + ((a_c + kk * 32) ^ asw);
                ldsm_x4(ah[i], addr);
                ldsm_x4(al[i], addr + (OFF_ALO - OFF_AHI));
            }
            #pragma unroll
            for (int p = 0; p < 2; p++) {
                uint32_t ro = (uint32_t)((b_row + p * 16) * 128);
                uint32_t addr = s0 + OFF_B + ro + ((b_c + kk * 32) ^ bsw);
                ldsm_x4(bh[p], addr);
            }
            #pragma unroll
            for (int i = 0; i < 4; i++)
                #pragma unroll
                for (int j = 0; j < 4; j++) {
                    const uint32_t* bj = &bh[j >> 1][(j & 1) * 2];
                    mma_f16(acc[i][j], ah[i], bj);
                    mma_f16(acc[i][j], al[i], bj);
                }
        }
        __syncthreads();
        stg = (stg == 2) ? 0 : stg + 1;
    }
    #undef LOAD_STAGE

    // -------- epilogue --------
    int g = lane >> 2;
    int cg = (lane & 3) * 2;
    #pragma unroll
    for (int i = 0; i < 4; i++) {
        #pragma unroll
        for (int half = 0; half < 2; half++) {
            int m = m0 + wm * 64 + i * 16 + g + half * 8;
            if (m < cnt) {
                int slot = base + m;
                float gate = (MODE == 1) ? g_gates[slot] : 0.f;
                #pragma unroll
                for (int j = 0; j < 4; j++) {
                    int col = n0 + wn * 32 + j * 8 + cg;
                    float bv0 = bias[(size_t)e * NTOT + col];
                    float bv1 = bias[(size_t)e * NTOT + col + 1];
                    float v0 = acc[i][j][half * 2 + 0] + bv0;
                    float v1 = acc[i][j][half * 2 + 1] + bv1;
                    if (MODE == 0) {
                        v0 = fmaxf(v0, 0.f); v1 = fmaxf(v1, 0.f);
                        __half h0 = __float2half_rn(v0);
                        __half h1 = __float2half_rn(v1);
                        uint32_t hh = pack_h2(v0, v1);
                        uint32_t ll = pack_h2(v0 - __half2float(h0),
                                              v1 - __half2float(h1));
                        *(uint32_t*)&g_h_hi[(size_t)slot * H + col] = hh;
                        *(uint32_t*)&g_h_lo[(size_t)slot * H + col] = ll;
                    } else {
                        float2 v = make_float2(gate * v0, gate * v1);
                        *(float2*)&g_eo[(size_t)slot * O + col] = v;
                    }
                }
            }
        }
    }
}

// ---------------- task towers ----------------
__global__ __launch_bounds__(256) void k_tower(
    const float* __restrict__ tw1, const float* __restrict__ tb1,
    const float* __restrict__ tw2, const float* __restrict__ tb2,
    float* __restrict__ out)
{
    int b0 = blockIdx.x * 16;
    int tid = threadIdx.x;
    int lane = tid & 31, wid = tid >> 5;

    __shared__ float moe_sh[16][O];
    __shared__ float sred[16][8];

    #pragma unroll
    for (int r = 0; r < 16; r++) {
        int b = b0 + r;
        int s0 = g_pair[b * 2 + 0], s1 = g_pair[b * 2 + 1];
        for (int c = tid; c < O; c += 256)
            moe_sh[r][c] = g_eo[(size_t)s0 * O + c] + g_eo[(size_t)s1 * O + c];
    }
    __syncthreads();

    for (int t = 0; t < T; t++) {
        float acc[16];
        #pragma unroll
        for (int r = 0; r < 16; r++) acc[r] = 0.f;

        const float* w1 = tw1 + (size_t)t * O * TH + tid;
        for (int o = 0; o < O; o++) {
            float w = w1[(size_t)o * TH];
            #pragma unroll
            for (int r = 0; r < 16; r++) acc[r] += moe_sh[r][o] * w;
        }
        float bb = tb1[t * TH + tid];
        float w2 = tw2[t * TH + tid];

        #pragma unroll
        for (int r = 0; r < 16; r++) {
            float th = fmaxf(acc[r] + bb, 0.f);
            float v = th * w2;
            for (int off = 16; off; off >>= 1)
                v += __shfl_down_sync(0xffffffffu, v, off);
            if (lane == 0) sred[r][wid] = v;
        }
        __syncthreads();
        if (tid < 16) {
            float s = 0.f;
            #pragma unroll
            for (int w = 0; w < 8; w++) s += sred[tid][w];
            out[(b0 + tid) * T + t] = s + tb2[t];
        }
        __syncthreads();
    }
}

// ---------------- launch ----------------
extern "C" void kernel_launch(void* const* d_in, const int* in_sizes, int n_in,
                              void* d_out, int out_size)
{
    const float* x     = (const float*)d_in[0];
    const float* plew  = (const float*)d_in[1];
    const float* pleb  = (const float*)d_in[2];
    const float* embW  = (const float*)d_in[3];
    const float* embb  = (const float*)d_in[4];
    const float* gW    = (const float*)d_in[5];
    const float* gb    = (const float*)d_in[6];
    const float* eW1   = (const float*)d_in[7];
    const float* eb1   = (const float*)d_in[8];
    const float* eW2   = (const float*)d_in[9];
    const float* eb2   = (const float*)d_in[10];
    const float* tw1   = (const float*)d_in[11];
    const float* tb1   = (const float*)d_in[12];
    const float* tw2   = (const float*)d_in[13];
    const float* tb2   = (const float*)d_in[14];
    float* out = (float*)d_out;

    const int SMEM_BYTES = 3 * STAGE_BYTES;   // 147456
    static bool attr_done = false;
    if (!attr_done) {
        cudaFuncSetAttribute(k_mma_gemm<F, H, 0>, cudaFuncAttributeMaxDynamicSharedMemorySize, SMEM_BYTES);
        cudaFuncSetAttribute(k_mma_gemm<H, O, 1>, cudaFuncAttributeMaxDynamicSharedMemorySize, SMEM_BYTES);
        attr_done = true;
    }

    __half *w1t, *w2t, *flat_hi, *flat_lo, *h_hi, *h_lo;
    cudaGetSymbolAddress((void**)&w1t, g_w1t);
    cudaGetSymbolAddress((void**)&w2t, g_w2t);
    cudaGetSymbolAddress((void**)&flat_hi, g_flat_hi);
    cudaGetSymbolAddress((void**)&flat_lo, g_flat_lo);
    cudaGetSymbolAddress((void**)&h_hi, g_h_hi);
    cudaGetSymbolAddress((void**)&h_lo, g_h_lo);

    k_init<<<1, 32>>>();
    k_wsplit<<<dim3(H / 32, F / 32, E), dim3(32, 8)>>>(eW1, w1t, F, H);
    k_wsplit<<<dim3(O / 32, H / 32, E), dim3(32, 8)>>>(eW2, w2t, H, O);
    k_ple<<<dim3(NF, B / 64), 256>>>(x, plew, pleb, embW, embb);
    k_gate<<<B, 256>>>(gW, gb);
    k_scan<<<1, 32>>>();
    k_assign<<<(B + 255) / 256, 256>>>();

    k_mma_gemm<F, H, 0><<<dim3(H / 128, B / GBM, E), 256, SMEM_BYTES>>>(
        flat_hi, flat_lo, w1t, eb1);
    k_mma_gemm<H, O, 1><<<dim3(O / 128, B / GBM, E), 256, SMEM_BYTES>>>(
        h_hi, h_lo, w2t, eb2);

    k_tower<<<B / 16, 256>>>(tw1, tb1, tw2, tb2, out);
}

// round 10
// speedup vs baseline: 1.6697x; 1.2704x over previous
#include <cuda_runtime.h>
#include <cuda_fp16.h>
#include <cstdint>
#include <math.h>

// Problem constants
#define B    4096
#define NF   64
#define KB   48
#define DE   64
#define F    4096
#define E    8
#define H    1024
#define O    512
#define T    2
#define TH   256

// ---------------- low-level helpers (plain sm_80+ PTX only) ----------------
__device__ __forceinline__ uint32_t smem_to_u32(const void* p) {
    uint32_t a;
    asm("{ .reg .u64 t; cvta.to.shared.u64 t, %1; cvt.u32.u64 %0, t; }" : "=r"(a) : "l"(p));
    return a;
}
__device__ __forceinline__ void cp_async16(uint32_t dst, const void* src, int src_bytes) {
    asm volatile("cp.async.cg.shared.global [%0], [%1], 16, %2;"
                 :: "r"(dst), "l"(src), "r"(src_bytes) : "memory");
}
#define CP_COMMIT() asm volatile("cp.async.commit_group;" ::: "memory")
#define CP_WAIT(n)  asm volatile("cp.async.wait_group %0;" :: "n"(n) : "memory")

__device__ __forceinline__ void ldsm_x4(uint32_t* r, uint32_t addr) {
    asm volatile("ldmatrix.sync.aligned.m8n8.x4.shared.b16 {%0,%1,%2,%3}, [%4];"
                 : "=r"(r[0]), "=r"(r[1]), "=r"(r[2]), "=r"(r[3]) : "r"(addr));
}
__device__ __forceinline__ void mma_f16(float* c, const uint32_t* a, const uint32_t* b) {
    asm volatile(
        "mma.sync.aligned.m16n8k16.row.col.f32.f16.f16.f32 "
        "{%0,%1,%2,%3}, {%4,%5,%6,%7}, {%8,%9}, {%0,%1,%2,%3};"
        : "+f"(c[0]), "+f"(c[1]), "+f"(c[2]), "+f"(c[3])
        : "r"(a[0]), "r"(a[1]), "r"(a[2]), "r"(a[3]), "r"(b[0]), "r"(b[1]));
}
__device__ __forceinline__ uint32_t pack_h2(float v0, float v1) {
    __half2 h = __halves2half2(__float2half_rn(v0), __float2half_rn(v1));
    return *(uint32_t*)&h;
}

// ---------------- device scratch ----------------
__device__ __half g_flat_hi[(size_t)B * F];     // 32 MB
__device__ __half g_flat_lo[(size_t)B * F];     // 32 MB (gate exactness only)
__device__ __half g_w1t[(size_t)E * H * F];     // 64 MB  [e][h][f]
__device__ __half g_w2t[(size_t)E * O * H];     // 8 MB   [e][o][h]
__device__ __half g_h_hi[(size_t)2 * B * H];    // 16 MB
__device__ __half g_h_lo[(size_t)2 * B * H];    // 16 MB
__device__ float g_eo[(size_t)2 * B * O];       // 16 MB
__device__ int   g_count[E];
__device__ int   g_base[E];
__device__ int   g_cursor[E];
__device__ int   g_te[B * 2];
__device__ float g_tg[B * 2];
__device__ int   g_rows[2 * B];
__device__ float g_gates[2 * B];
__device__ int   g_pair[B * 2];

// ---------------- init ----------------
__global__ void k_init() {
    if (threadIdx.x < E) g_count[threadIdx.x] = 0;
}

// ---------------- weight transpose: W[e][k][n] -> T[e][n][k] fp16 ----------------
__global__ __launch_bounds__(256) void k_wsplit(
    const float* __restrict__ W, __half* __restrict__ Tw, int Kdim, int Ndim)
{
    __shared__ float t[32][33];
    int e = blockIdx.z;
    int kb = blockIdx.y * 32;
    int nb = blockIdx.x * 32;
    int tx = threadIdx.x, ty = threadIdx.y;
    const float* Wb = W + (size_t)e * Kdim * Ndim;
    #pragma unroll
    for (int i = ty; i < 32; i += 8)
        t[i][tx] = Wb[(size_t)(kb + i) * Ndim + nb + tx];
    __syncthreads();
    #pragma unroll
    for (int i = ty; i < 32; i += 8) {
        float v = t[tx][i];
        size_t o = ((size_t)e * Ndim + nb + i) * Kdim + kb + tx;
        Tw[o] = __float2half_rn(v);
    }
}

// ---------------- PLE + embedding + ReLU -> flat hi/lo (fp16 split) ----------------
__global__ __launch_bounds__(256) void k_ple(
    const float* __restrict__ x, const float* __restrict__ plew,
    const float* __restrict__ pleb, const float* __restrict__ embW,
    const float* __restrict__ embb)
{
    int n = blockIdx.x;
    int b0 = blockIdx.y * 64;
    int tid = threadIdx.x;

    __shared__ float Wsh[KB * DE];
    __shared__ float wsh[KB], bsh[KB], ebias[DE];
    __shared__ float xs[64];
    __shared__ float enc_sh[64][KB];

    for (int i = tid; i < KB * DE; i += 256) Wsh[i] = embW[(size_t)n * KB * DE + i];
    if (tid < KB) { wsh[tid] = plew[n * KB + tid]; bsh[tid] = pleb[n * KB + tid]; }
    if (tid < DE) ebias[tid] = embb[n * DE + tid];
    if (tid < 64) xs[tid] = x[(b0 + tid) * NF + n];
    __syncthreads();

    for (int idx = tid; idx < 64 * KB; idx += 256) {
        int bl = idx / KB, k = idx - bl * KB;
        float enc = bsh[k] + wsh[k] * xs[bl];
        if (k == 0)           enc = fminf(enc, 1.f);
        else if (k == KB - 1) enc = fmaxf(enc, 0.f);
        else                  enc = fminf(fmaxf(enc, 0.f), 1.f);
        enc_sh[bl][k] = enc;
    }
    __syncthreads();

    int c0 = (tid & 15) * 4;
    int r0 = (tid >> 4) * 4;

    float acc[4][4];
    #pragma unroll
    for (int r = 0; r < 4; r++)
        #pragma unroll
        for (int j = 0; j < 4; j++) acc[r][j] = ebias[c0 + j];

    #pragma unroll
    for (int k4 = 0; k4 < KB; k4 += 4) {
        float4 wv[4];
        #pragma unroll
        for (int kk = 0; kk < 4; kk++)
            wv[kk] = *(const float4*)&Wsh[(k4 + kk) * DE + c0];
        #pragma unroll
        for (int r = 0; r < 4; r++) {
            float4 ev = *(const float4*)&enc_sh[r0 + r][k4];
            const float* w0 = (const float*)&wv[0];
            const float* w1 = (const float*)&wv[1];
            const float* w2 = (const float*)&wv[2];
            const float* w3 = (const float*)&wv[3];
            #pragma unroll
            for (int j = 0; j < 4; j++)
                acc[r][j] += ev.x * w0[j] + ev.y * w1[j] + ev.z * w2[j] + ev.w * w3[j];
        }
    }

    #pragma unroll
    for (int r = 0; r < 4; r++) {
        int b = b0 + r0 + r;
        uint32_t hw[2], lw[2];
        #pragma unroll
        for (int p = 0; p < 2; p++) {
            float v0 = fmaxf(acc[r][p * 2 + 0], 0.f);
            float v1 = fmaxf(acc[r][p * 2 + 1], 0.f);
            __half h0 = __float2half_rn(v0);
            __half h1 = __float2half_rn(v1);
            hw[p] = pack_h2(v0, v1);
            lw[p] = pack_h2(v0 - __half2float(h0), v1 - __half2float(h1));
        }
        size_t idx = (size_t)b * F + n * DE + c0;
        *(uint2*)&g_flat_hi[idx] = make_uint2(hw[0], hw[1]);
        *(uint2*)&g_flat_lo[idx] = make_uint2(lw[0], lw[1]);
    }
}

// ---------------- gate (exact activations via hi+lo) ----------------
__global__ __launch_bounds__(256) void k_gate(
    const float* __restrict__ gW, const float* __restrict__ gb)
{
    int b = blockIdx.x;
    int tid = threadIdx.x;
    int lane = tid & 31, wid = tid >> 5;

    float acc[E];
    #pragma unroll
    for (int e = 0; e < E; e++) acc[e] = 0.f;

    const __half* xh = g_flat_hi + (size_t)b * F;
    const __half* xl = g_flat_lo + (size_t)b * F;
    for (int f = tid; f < F; f += 256) {
        float xv = __half2float(xh[f]) + __half2float(xl[f]);
        #pragma unroll
        for (int e = 0; e < E; e++) acc[e] += xv * gW[f * E + e];
    }
    #pragma unroll
    for (int e = 0; e < E; e++)
        for (int off = 16; off; off >>= 1)
            acc[e] += __shfl_down_sync(0xffffffffu, acc[e], off);

    __shared__ float sb[E][8];
    __shared__ float slog[E];
    if (lane == 0) {
        #pragma unroll
        for (int e = 0; e < E; e++) sb[e][wid] = acc[e];
    }
    __syncthreads();
    if (tid < E) {
        float s = 0.f;
        #pragma unroll
        for (int w = 0; w < 8; w++) s += sb[tid][w];
        slog[tid] = s + gb[tid];
    }
    __syncthreads();
    if (tid == 0) {
        int i0 = 0;
        #pragma unroll
        for (int e = 1; e < E; e++) if (slog[e] > slog[i0]) i0 = e;
        int i1 = (i0 == 0) ? 1 : 0;
        #pragma unroll
        for (int e = 0; e < E; e++) if (e != i0 && slog[e] > slog[i1]) i1 = e;
        float e1 = __expf(slog[i1] - slog[i0]);
        float inv = 1.f / (1.f + e1);
        g_te[b * 2 + 0] = i0;  g_tg[b * 2 + 0] = inv;
        g_te[b * 2 + 1] = i1;  g_tg[b * 2 + 1] = e1 * inv;
        atomicAdd(&g_count[i0], 1);
        atomicAdd(&g_count[i1], 1);
    }
}

__global__ void k_scan() {
    if (threadIdx.x == 0) {
        int s = 0;
        for (int e = 0; e < E; e++) { g_base[e] = s; g_cursor[e] = s; s += g_count[e]; }
    }
}

__global__ __launch_bounds__(256) void k_assign() {
    int b = blockIdx.x * 256 + threadIdx.x;
    if (b >= B) return;
    #pragma unroll
    for (int j = 0; j < 2; j++) {
        int e = g_te[b * 2 + j];
        int slot = atomicAdd(&g_cursor[e], 1);
        g_rows[slot]  = b;
        g_gates[slot] = g_tg[b * 2 + j];
        g_pair[b * 2 + j] = slot;
    }
}

// ---------------- fp16 register-MMA expert GEMM ----------------
// CTA tile 128x128, 8 warps (2m x 4n), warp tile 64x32, k-tile 64, 3-stage cp.async.
// TERMS=1: A single plane (GEMM1).  TERMS=2: A hi+lo split (GEMM2).
#define GBM 128
#define GKT 64

template<int KTOT, int NTOT, int MODE, int TERMS>
__global__ __launch_bounds__(256, (TERMS == 1 ? 2 : 1)) void k_mma_gemm(
    const __half* __restrict__ Ahi, const __half* __restrict__ Alo,
    const __half* __restrict__ Wt, const float* __restrict__ bias)
{
    constexpr uint32_t STG_BYTES = (TERMS == 1) ? 32768u : 49152u;
    constexpr uint32_t OFF_ALO_C = 16384u;
    constexpr uint32_t OFF_B_C   = (TERMS == 1) ? 16384u : 32768u;

    int e = blockIdx.z;
    int cnt = g_count[e];
    int m0 = blockIdx.y * GBM;
    if (m0 >= cnt) return;
    int base = g_base[e];
    int n0 = blockIdx.x * 128;

    extern __shared__ char smem[];
    uint32_t sb = smem_to_u32(smem);
    __shared__ int rows_s[GBM];

    int tid = threadIdx.x;
    int lane = tid & 31, wid = tid >> 5;

    if (MODE == 0 && tid < GBM) {
        int m = m0 + tid;
        rows_s[tid] = (m < cnt) ? g_rows[base + m] : -1;
    }
    __syncthreads();

    // -------- loader setup: thread -> (row 0..127, 4 chunks of 16B) --------
    int lrow = tid >> 1;
    int lcb  = (tid & 1) * 4;
    const __half *arow_hi, *arow_lo;
    int abytes;
    if (MODE == 0) {
        int gr = rows_s[lrow];
        abytes = (gr >= 0) ? 16 : 0;
        int r = (gr >= 0) ? gr : 0;
        arow_hi = Ahi + (size_t)r * KTOT;
        arow_lo = Alo + (size_t)r * KTOT;
    } else {
        int m = m0 + lrow;
        abytes = (m < cnt) ? 16 : 0;
        size_t r = (m < cnt) ? (size_t)(base + m) : 0;
        arow_hi = Ahi + r * KTOT;
        arow_lo = Alo + r * KTOT;
    }
    const __half* brow = Wt + ((size_t)e * NTOT + n0 + lrow) * KTOT;
    uint32_t lsw = (uint32_t)((lrow & 7) << 4);
    uint32_t lbase = (uint32_t)(lrow * 128);

    // -------- mma setup --------
    int wm = wid >> 2;            // 0..1
    int wn = wid & 3;             // 0..3
    int a_row = wm * 64 + (lane & 15);
    uint32_t a_c  = (uint32_t)((lane >> 4) * 16);
    uint32_t asw  = (uint32_t)((a_row & 7) << 4);
    int b_row = wn * 32 + (lane & 7) + ((lane >> 4) << 3);
    uint32_t b_c  = (uint32_t)(((lane >> 3) & 1) * 16);
    uint32_t bsw  = (uint32_t)((b_row & 7) << 4);

    float acc[4][4][4];
    #pragma unroll
    for (int i = 0; i < 4; i++)
        #pragma unroll
        for (int j = 0; j < 4; j++)
            #pragma unroll
            for (int q = 0; q < 4; q++) acc[i][j][q] = 0.f;

    const int NT = KTOT / GKT;

    #define LOAD_STAGE(stg_, kt_) do {                                           \
        uint32_t s_ = sb + (uint32_t)(stg_) * STG_BYTES;                          \
        int k0_ = (kt_) * GKT;                                                    \
        _Pragma("unroll")                                                         \
        for (int q = 0; q < 4; q++) {                                             \
            int ch = lcb + q;                                                     \
            uint32_t so = lbase + (((uint32_t)(ch * 16)) ^ lsw);                  \
            cp_async16(s_ + so, arow_hi + k0_ + ch * 8, abytes);                  \
            if (TERMS == 2)                                                       \
                cp_async16(s_ + OFF_ALO_C + so, arow_lo + k0_ + ch * 8, abytes);  \
            cp_async16(s_ + OFF_B_C + so, brow + k0_ + ch * 8, 16);               \
        }                                                                         \
        CP_COMMIT();                                                              \
    } while (0)

    // prime stages 0,1
    LOAD_STAGE(0, 0);
    if (NT > 1) LOAD_STAGE(1, 1);

    int stg = 0;
    for (int kt = 0; kt < NT; kt++) {
        if (kt + 2 < NT) {
            int ns = stg + 2; if (ns >= 3) ns -= 3;
            LOAD_STAGE(ns, kt + 2);
            CP_WAIT(2);
        } else if (kt + 1 < NT) {
            CP_WAIT(1);
        } else {
            CP_WAIT(0);
        }
        __syncthreads();

        uint32_t s0 = sb + (uint32_t)stg * STG_BYTES;
        #pragma unroll
        for (int kk = 0; kk < 4; kk++) {
            uint32_t ah[4][4], al[4][4], bh[2][4];
            #pragma unroll
            for (int i = 0; i < 4; i++) {
                uint32_t ro = (uint32_t)((a_row + i * 16) * 128);
                uint32_t addr = s0 + ro + ((a_c + kk * 32) ^ asw);
                ldsm_x4(ah[i], addr);
                if (TERMS == 2) ldsm_x4(al[i], addr + OFF_ALO_C);
            }
            #pragma unroll
            for (int p = 0; p < 2; p++) {
                uint32_t ro = (uint32_t)((b_row + p * 16) * 128);
                uint32_t addr = s0 + OFF_B_C + ro + ((b_c + kk * 32) ^ bsw);
                ldsm_x4(bh[p], addr);
            }
            #pragma unroll
            for (int i = 0; i < 4; i++)
                #pragma unroll
                for (int j = 0; j < 4; j++) {
                    const uint32_t* bj = &bh[j >> 1][(j & 1) * 2];
                    mma_f16(acc[i][j], ah[i], bj);
                    if (TERMS == 2) mma_f16(acc[i][j], al[i], bj);
                }
        }
        __syncthreads();
        stg = (stg == 2) ? 0 : stg + 1;
    }
    #undef LOAD_STAGE

    // -------- epilogue --------
    int g = lane >> 2;
    int cg = (lane & 3) * 2;
    #pragma unroll
    for (int i = 0; i < 4; i++) {
        #pragma unroll
        for (int half = 0; half < 2; half++) {
            int m = m0 + wm * 64 + i * 16 + g + half * 8;
            if (m < cnt) {
                int slot = base + m;
                float gate = (MODE == 1) ? g_gates[slot] : 0.f;
                #pragma unroll
                for (int j = 0; j < 4; j++) {
                    int col = n0 + wn * 32 + j * 8 + cg;
                    float bv0 = bias[(size_t)e * NTOT + col];
                    float bv1 = bias[(size_t)e * NTOT + col + 1];
                    float v0 = acc[i][j][half * 2 + 0] + bv0;
                    float v1 = acc[i][j][half * 2 + 1] + bv1;
                    if (MODE == 0) {
                        v0 = fmaxf(v0, 0.f); v1 = fmaxf(v1, 0.f);
                        __half h0 = __float2half_rn(v0);
                        __half h1 = __float2half_rn(v1);
                        uint32_t hh = pack_h2(v0, v1);
                        uint32_t ll = pack_h2(v0 - __half2float(h0),
                                              v1 - __half2float(h1));
                        *(uint32_t*)&g_h_hi[(size_t)slot * H + col] = hh;
                        *(uint32_t*)&g_h_lo[(size_t)slot * H + col] = ll;
                    } else {
                        float2 v = make_float2(gate * v0, gate * v1);
                        *(float2*)&g_eo[(size_t)slot * O + col] = v;
                    }
                }
            }
        }
    }
}

// ---------------- task towers ----------------
__global__ __launch_bounds__(256) void k_tower(
    const float* __restrict__ tw1, const float* __restrict__ tb1,
    const float* __restrict__ tw2, const float* __restrict__ tb2,
    float* __restrict__ out)
{
    int b0 = blockIdx.x * 16;
    int tid = threadIdx.x;
    int lane = tid & 31, wid = tid >> 5;

    __shared__ float moe_sh[16][O];
    __shared__ float sred[16][8];

    #pragma unroll
    for (int r = 0; r < 16; r++) {
        int b = b0 + r;
        int s0 = g_pair[b * 2 + 0], s1 = g_pair[b * 2 + 1];
        for (int c = tid; c < O; c += 256)
            moe_sh[r][c] = g_eo[(size_t)s0 * O + c] + g_eo[(size_t)s1 * O + c];
    }
    __syncthreads();

    for (int t = 0; t < T; t++) {
        float acc[16];
        #pragma unroll
        for (int r = 0; r < 16; r++) acc[r] = 0.f;

        const float* w1 = tw1 + (size_t)t * O * TH + tid;
        for (int o = 0; o < O; o++) {
            float w = w1[(size_t)o * TH];
            #pragma unroll
            for (int r = 0; r < 16; r++) acc[r] += moe_sh[r][o] * w;
        }
        float bb = tb1[t * TH + tid];
        float w2 = tw2[t * TH + tid];

        #pragma unroll
        for (int r = 0; r < 16; r++) {
            float th = fmaxf(acc[r] + bb, 0.f);
            float v = th * w2;
            for (int off = 16; off; off >>= 1)
                v += __shfl_down_sync(0xffffffffu, v, off);
            if (lane == 0) sred[r][wid] = v;
        }
        __syncthreads();
        if (tid < 16) {
            float s = 0.f;
            #pragma unroll
            for (int w = 0; w < 8; w++) s += sred[tid][w];
            out[(b0 + tid) * T + t] = s + tb2[t];
        }
        __syncthreads();
    }
}

// ---------------- launch ----------------
extern "C" void kernel_launch(void* const* d_in, const int* in_sizes, int n_in,
                              void* d_out, int out_size)
{
    const float* x     = (const float*)d_in[0];
    const float* plew  = (const float*)d_in[1];
    const float* pleb  = (const float*)d_in[2];
    const float* embW  = (const float*)d_in[3];
    const float* embb  = (const float*)d_in[4];
    const float* gW    = (const float*)d_in[5];
    const float* gb    = (const float*)d_in[6];
    const float* eW1   = (const float*)d_in[7];
    const float* eb1   = (const float*)d_in[8];
    const float* eW2   = (const float*)d_in[9];
    const float* eb2   = (const float*)d_in[10];
    const float* tw1   = (const float*)d_in[11];
    const float* tb1   = (const float*)d_in[12];
    const float* tw2   = (const float*)d_in[13];
    const float* tb2   = (const float*)d_in[14];
    float* out = (float*)d_out;

    const int SMEM1 = 3 * 32768;    // 98304  (TERMS=1)
    const int SMEM2 = 3 * 49152;    // 147456 (TERMS=2)
    static bool attr_done = false;
    if (!attr_done) {
        cudaFuncSetAttribute(k_mma_gemm<F, H, 0, 1>, cudaFuncAttributeMaxDynamicSharedMemorySize, SMEM1);
        cudaFuncSetAttribute(k_mma_gemm<H, O, 1, 2>, cudaFuncAttributeMaxDynamicSharedMemorySize, SMEM2);
        attr_done = true;
    }

    __half *w1t, *w2t, *flat_hi, *flat_lo, *h_hi, *h_lo;
    cudaGetSymbolAddress((void**)&w1t, g_w1t);
    cudaGetSymbolAddress((void**)&w2t, g_w2t);
    cudaGetSymbolAddress((void**)&flat_hi, g_flat_hi);
    cudaGetSymbolAddress((void**)&flat_lo, g_flat_lo);
    cudaGetSymbolAddress((void**)&h_hi, g_h_hi);
    cudaGetSymbolAddress((void**)&h_lo, g_h_lo);

    k_init<<<1, 32>>>();
    k_wsplit<<<dim3(H / 32, F / 32, E), dim3(32, 8)>>>(eW1, w1t, F, H);
    k_wsplit<<<dim3(O / 32, H / 32, E), dim3(32, 8)>>>(eW2, w2t, H, O);
    k_ple<<<dim3(NF, B / 64), 256>>>(x, plew, pleb, embW, embb);
    k_gate<<<B, 256>>>(gW, gb);
    k_scan<<<1, 32>>>();
    k_assign<<<(B + 255) / 256, 256>>>();

    k_mma_gemm<F, H, 0, 1><<<dim3(H / 128, B / GBM, E), 256, SMEM1>>>(
        flat_hi, flat_lo, w1t, eb1);
    k_mma_gemm<H, O, 1, 2><<<dim3(O / 128, B / GBM, E), 256, SMEM2>>>(
        h_hi, h_lo, w2t, eb2);

    k_tower<<<B / 16, 256>>>(tw1, tb1, tw2, tb2, out);
}

// round 11
// speedup vs baseline: 1.7636x; 1.0563x over previous
#include <cuda_runtime.h>
#include <cuda_fp16.h>
#include <cstdint>
#include <math.h>

// Problem constants
#define B    4096
#define NF   64
#define KB   48
#define DE   64
#define F    4096
#define E    8
#define H    1024
#define O    512
#define T    2
#define TH   256

// ---------------- low-level helpers (plain sm_80+ PTX only) ----------------
__device__ __forceinline__ uint32_t smem_to_u32(const void* p) {
    uint32_t a;
    asm("{ .reg .u64 t; cvta.to.shared.u64 t, %1; cvt.u32.u64 %0, t; }" : "=r"(a) : "l"(p));
    return a;
}
__device__ __forceinline__ void cp_async16(uint32_t dst, const void* src, int src_bytes) {
    asm volatile("cp.async.cg.shared.global [%0], [%1], 16, %2;"
                 :: "r"(dst), "l"(src), "r"(src_bytes) : "memory");
}
#define CP_COMMIT() asm volatile("cp.async.commit_group;" ::: "memory")
#define CP_WAIT(n)  asm volatile("cp.async.wait_group %0;" :: "n"(n) : "memory")

__device__ __forceinline__ void ldsm_x4(uint32_t* r, uint32_t addr) {
    asm volatile("ldmatrix.sync.aligned.m8n8.x4.shared.b16 {%0,%1,%2,%3}, [%4];"
                 : "=r"(r[0]), "=r"(r[1]), "=r"(r[2]), "=r"(r[3]) : "r"(addr));
}
__device__ __forceinline__ void mma_f16(float* c, const uint32_t* a, const uint32_t* b) {
    asm volatile(
        "mma.sync.aligned.m16n8k16.row.col.f32.f16.f16.f32 "
        "{%0,%1,%2,%3}, {%4,%5,%6,%7}, {%8,%9}, {%0,%1,%2,%3};"
        : "+f"(c[0]), "+f"(c[1]), "+f"(c[2]), "+f"(c[3])
        : "r"(a[0]), "r"(a[1]), "r"(a[2]), "r"(a[3]), "r"(b[0]), "r"(b[1]));
}
__device__ __forceinline__ uint32_t pack_h2(float v0, float v1) {
    __half2 h = __halves2half2(__float2half_rn(v0), __float2half_rn(v1));
    return *(uint32_t*)&h;
}

// ---------------- device scratch ----------------
__device__ __half g_flat_hi[(size_t)B * F];     // 32 MB
__device__ __half g_flat_lo[(size_t)B * F];     // 32 MB (gate exactness only)
__device__ __half g_w1t[(size_t)E * H * F];     // 64 MB  [e][h][f]
__device__ __half g_w2t[(size_t)E * O * H];     // 8 MB   [e][o][h]
__device__ __half g_h[(size_t)2 * B * H];       // 16 MB
__device__ float g_eo[(size_t)2 * B * O];       // 16 MB
__device__ int   g_count[E];
__device__ int   g_base[E];
__device__ int   g_cursor[E];
__device__ int   g_te[B * 2];
__device__ float g_tg[B * 2];
__device__ int   g_rows[2 * B];
__device__ float g_gates[2 * B];
__device__ int   g_pair[B * 2];

// ---------------- init ----------------
__global__ void k_init() {
    if (threadIdx.x < E) g_count[threadIdx.x] = 0;
}

// ---------------- weight transpose: W[e][k][n] -> T[e][n][k] fp16 ----------------
__global__ __launch_bounds__(256) void k_wsplit(
    const float* __restrict__ W, __half* __restrict__ Tw, int Kdim, int Ndim)
{
    __shared__ float t[32][33];
    int e = blockIdx.z;
    int kb = blockIdx.y * 32;
    int nb = blockIdx.x * 32;
    int tx = threadIdx.x, ty = threadIdx.y;
    const float* Wb = W + (size_t)e * Kdim * Ndim;
    #pragma unroll
    for (int i = ty; i < 32; i += 8)
        t[i][tx] = Wb[(size_t)(kb + i) * Ndim + nb + tx];
    __syncthreads();
    #pragma unroll
    for (int i = ty; i < 32; i += 8) {
        float v = t[tx][i];
        size_t o = ((size_t)e * Ndim + nb + i) * Kdim + kb + tx;
        Tw[o] = __float2half_rn(v);
    }
}

// ---------------- PLE + embedding + ReLU -> flat hi/lo (fp16 split) ----------------
__global__ __launch_bounds__(256) void k_ple(
    const float* __restrict__ x, const float* __restrict__ plew,
    const float* __restrict__ pleb, const float* __restrict__ embW,
    const float* __restrict__ embb)
{
    int n = blockIdx.x;
    int b0 = blockIdx.y * 64;
    int tid = threadIdx.x;

    __shared__ float Wsh[KB * DE];
    __shared__ float wsh[KB], bsh[KB], ebias[DE];
    __shared__ float xs[64];
    __shared__ float enc_sh[64][KB];

    for (int i = tid; i < KB * DE; i += 256) Wsh[i] = embW[(size_t)n * KB * DE + i];
    if (tid < KB) { wsh[tid] = plew[n * KB + tid]; bsh[tid] = pleb[n * KB + tid]; }
    if (tid < DE) ebias[tid] = embb[n * DE + tid];
    if (tid < 64) xs[tid] = x[(b0 + tid) * NF + n];
    __syncthreads();

    for (int idx = tid; idx < 64 * KB; idx += 256) {
        int bl = idx / KB, k = idx - bl * KB;
        float enc = bsh[k] + wsh[k] * xs[bl];
        if (k == 0)           enc = fminf(enc, 1.f);
        else if (k == KB - 1) enc = fmaxf(enc, 0.f);
        else                  enc = fminf(fmaxf(enc, 0.f), 1.f);
        enc_sh[bl][k] = enc;
    }
    __syncthreads();

    int c0 = (tid & 15) * 4;
    int r0 = (tid >> 4) * 4;

    float acc[4][4];
    #pragma unroll
    for (int r = 0; r < 4; r++)
        #pragma unroll
        for (int j = 0; j < 4; j++) acc[r][j] = ebias[c0 + j];

    #pragma unroll
    for (int k4 = 0; k4 < KB; k4 += 4) {
        float4 wv[4];
        #pragma unroll
        for (int kk = 0; kk < 4; kk++)
            wv[kk] = *(const float4*)&Wsh[(k4 + kk) * DE + c0];
        #pragma unroll
        for (int r = 0; r < 4; r++) {
            float4 ev = *(const float4*)&enc_sh[r0 + r][k4];
            const float* w0 = (const float*)&wv[0];
            const float* w1 = (const float*)&wv[1];
            const float* w2 = (const float*)&wv[2];
            const float* w3 = (const float*)&wv[3];
            #pragma unroll
            for (int j = 0; j < 4; j++)
                acc[r][j] += ev.x * w0[j] + ev.y * w1[j] + ev.z * w2[j] + ev.w * w3[j];
        }
    }

    #pragma unroll
    for (int r = 0; r < 4; r++) {
        int b = b0 + r0 + r;
        uint32_t hw[2], lw[2];
        #pragma unroll
        for (int p = 0; p < 2; p++) {
            float v0 = fmaxf(acc[r][p * 2 + 0], 0.f);
            float v1 = fmaxf(acc[r][p * 2 + 1], 0.f);
            __half h0 = __float2half_rn(v0);
            __half h1 = __float2half_rn(v1);
            hw[p] = pack_h2(v0, v1);
            lw[p] = pack_h2(v0 - __half2float(h0), v1 - __half2float(h1));
        }
        size_t idx = (size_t)b * F + n * DE + c0;
        *(uint2*)&g_flat_hi[idx] = make_uint2(hw[0], hw[1]);
        *(uint2*)&g_flat_lo[idx] = make_uint2(lw[0], lw[1]);
    }
}

// ---------------- gate (exact activations via hi+lo) ----------------
__global__ __launch_bounds__(256) void k_gate(
    const float* __restrict__ gW, const float* __restrict__ gb)
{
    int b = blockIdx.x;
    int tid = threadIdx.x;
    int lane = tid & 31, wid = tid >> 5;

    float acc[E];
    #pragma unroll
    for (int e = 0; e < E; e++) acc[e] = 0.f;

    const __half* xh = g_flat_hi + (size_t)b * F;
    const __half* xl = g_flat_lo + (size_t)b * F;
    for (int f = tid; f < F; f += 256) {
        float xv = __half2float(xh[f]) + __half2float(xl[f]);
        #pragma unroll
        for (int e = 0; e < E; e++) acc[e] += xv * gW[f * E + e];
    }
    #pragma unroll
    for (int e = 0; e < E; e++)
        for (int off = 16; off; off >>= 1)
            acc[e] += __shfl_down_sync(0xffffffffu, acc[e], off);

    __shared__ float sb[E][8];
    __shared__ float slog[E];
    if (lane == 0) {
        #pragma unroll
        for (int e = 0; e < E; e++) sb[e][wid] = acc[e];
    }
    __syncthreads();
    if (tid < E) {
        float s = 0.f;
        #pragma unroll
        for (int w = 0; w < 8; w++) s += sb[tid][w];
        slog[tid] = s + gb[tid];
    }
    __syncthreads();
    if (tid == 0) {
        int i0 = 0;
        #pragma unroll
        for (int e = 1; e < E; e++) if (slog[e] > slog[i0]) i0 = e;
        int i1 = (i0 == 0) ? 1 : 0;
        #pragma unroll
        for (int e = 0; e < E; e++) if (e != i0 && slog[e] > slog[i1]) i1 = e;
        float e1 = __expf(slog[i1] - slog[i0]);
        float inv = 1.f / (1.f + e1);
        g_te[b * 2 + 0] = i0;  g_tg[b * 2 + 0] = inv;
        g_te[b * 2 + 1] = i1;  g_tg[b * 2 + 1] = e1 * inv;
        atomicAdd(&g_count[i0], 1);
        atomicAdd(&g_count[i1], 1);
    }
}

__global__ void k_scan() {
    if (threadIdx.x == 0) {
        int s = 0;
        for (int e = 0; e < E; e++) { g_base[e] = s; g_cursor[e] = s; s += g_count[e]; }
    }
}

__global__ __launch_bounds__(256) void k_assign() {
    int b = blockIdx.x * 256 + threadIdx.x;
    if (b >= B) return;
    #pragma unroll
    for (int j = 0; j < 2; j++) {
        int e = g_te[b * 2 + j];
        int slot = atomicAdd(&g_cursor[e], 1);
        g_rows[slot]  = b;
        g_gates[slot] = g_tg[b * 2 + j];
        g_pair[b * 2 + j] = slot;
    }
}

// ---------------- fp16 register-MMA expert GEMM (single A plane) ----------------
// CTA tile 128x128, 8 warps (2m x 4n), warp tile 64x32, k-tile 64, 3-stage cp.async,
// 32KB/stage -> 96KB -> 2 CTAs/SM.
#define GBM 128
#define GKT 64
#define STG_BYTES 32768u
#define OFF_B_C   16384u

template<int KTOT, int NTOT, int MODE>
__global__ __launch_bounds__(256, 2) void k_mma_gemm(
    const __half* __restrict__ A, const __half* __restrict__ Wt,
    const float* __restrict__ bias)
{
    int e = blockIdx.z;
    int cnt = g_count[e];
    int m0 = blockIdx.y * GBM;
    if (m0 >= cnt) return;
    int base = g_base[e];
    int n0 = blockIdx.x * 128;

    extern __shared__ char smem[];
    uint32_t sb = smem_to_u32(smem);
    __shared__ int rows_s[GBM];

    int tid = threadIdx.x;
    int lane = tid & 31, wid = tid >> 5;

    if (MODE == 0 && tid < GBM) {
        int m = m0 + tid;
        rows_s[tid] = (m < cnt) ? g_rows[base + m] : -1;
    }
    __syncthreads();

    // -------- loader setup: thread -> (row 0..127, 4 chunks of 16B) --------
    int lrow = tid >> 1;
    int lcb  = (tid & 1) * 4;
    const __half* arow;
    int abytes;
    if (MODE == 0) {
        int gr = rows_s[lrow];
        abytes = (gr >= 0) ? 16 : 0;
        int r = (gr >= 0) ? gr : 0;
        arow = A + (size_t)r * KTOT;
    } else {
        int m = m0 + lrow;
        abytes = (m < cnt) ? 16 : 0;
        size_t r = (m < cnt) ? (size_t)(base + m) : 0;
        arow = A + r * KTOT;
    }
    const __half* brow = Wt + ((size_t)e * NTOT + n0 + lrow) * KTOT;
    uint32_t lsw = (uint32_t)((lrow & 7) << 4);
    uint32_t lbase = (uint32_t)(lrow * 128);

    // -------- mma setup --------
    int wm = wid >> 2;            // 0..1
    int wn = wid & 3;             // 0..3
    int a_row = wm * 64 + (lane & 15);
    uint32_t a_c  = (uint32_t)((lane >> 4) * 16);
    uint32_t asw  = (uint32_t)((a_row & 7) << 4);
    int b_row = wn * 32 + (lane & 7) + ((lane >> 4) << 3);
    uint32_t b_c  = (uint32_t)(((lane >> 3) & 1) * 16);
    uint32_t bsw  = (uint32_t)((b_row & 7) << 4);

    float acc[4][4][4];
    #pragma unroll
    for (int i = 0; i < 4; i++)
        #pragma unroll
        for (int j = 0; j < 4; j++)
            #pragma unroll
            for (int q = 0; q < 4; q++) acc[i][j][q] = 0.f;

    const int NT = KTOT / GKT;

    #define LOAD_STAGE(stg_, kt_) do {                                           \
        uint32_t s_ = sb + (uint32_t)(stg_) * STG_BYTES;                          \
        int k0_ = (kt_) * GKT;                                                    \
        _Pragma("unroll")                                                         \
        for (int q = 0; q < 4; q++) {                                             \
            int ch = lcb + q;                                                     \
            uint32_t so = lbase + (((uint32_t)(ch * 16)) ^ lsw);                  \
            cp_async16(s_ + so, arow + k0_ + ch * 8, abytes);                     \
            cp_async16(s_ + OFF_B_C + so, brow + k0_ + ch * 8, 16);               \
        }                                                                         \
        CP_COMMIT();                                                              \
    } while (0)

    // prime stages 0,1
    LOAD_STAGE(0, 0);
    if (NT > 1) LOAD_STAGE(1, 1);

    int stg = 0;
    for (int kt = 0; kt < NT; kt++) {
        if (kt + 2 < NT) {
            int ns = stg + 2; if (ns >= 3) ns -= 3;
            LOAD_STAGE(ns, kt + 2);
            CP_WAIT(2);
        } else if (kt + 1 < NT) {
            CP_WAIT(1);
        } else {
            CP_WAIT(0);
        }
        __syncthreads();

        uint32_t s0 = sb + (uint32_t)stg * STG_BYTES;
        #pragma unroll
        for (int kk = 0; kk < 4; kk++) {
            uint32_t ah[4][4], bh[2][4];
            #pragma unroll
            for (int i = 0; i < 4; i++) {
                uint32_t ro = (uint32_t)((a_row + i * 16) * 128);
                ldsm_x4(ah[i], s0 + ro + ((a_c + kk * 32) ^ asw));
            }
            #pragma unroll
            for (int p = 0; p < 2; p++) {
                uint32_t ro = (uint32_t)((b_row + p * 16) * 128);
                ldsm_x4(bh[p], s0 + OFF_B_C + ro + ((b_c + kk * 32) ^ bsw));
            }
            #pragma unroll
            for (int i = 0; i < 4; i++)
                #pragma unroll
                for (int j = 0; j < 4; j++) {
                    const uint32_t* bj = &bh[j >> 1][(j & 1) * 2];
                    mma_f16(acc[i][j], ah[i], bj);
                }
        }
        __syncthreads();
        stg = (stg == 2) ? 0 : stg + 1;
    }
    #undef LOAD_STAGE

    // -------- epilogue --------
    int g = lane >> 2;
    int cg = (lane & 3) * 2;
    #pragma unroll
    for (int i = 0; i < 4; i++) {
        #pragma unroll
        for (int half = 0; half < 2; half++) {
            int m = m0 + wm * 64 + i * 16 + g + half * 8;
            if (m < cnt) {
                int slot = base + m;
                float gate = (MODE == 1) ? g_gates[slot] : 0.f;
                #pragma unroll
                for (int j = 0; j < 4; j++) {
                    int col = n0 + wn * 32 + j * 8 + cg;
                    float bv0 = bias[(size_t)e * NTOT + col];
                    float bv1 = bias[(size_t)e * NTOT + col + 1];
                    float v0 = acc[i][j][half * 2 + 0] + bv0;
                    float v1 = acc[i][j][half * 2 + 1] + bv1;
                    if (MODE == 0) {
                        v0 = fmaxf(v0, 0.f); v1 = fmaxf(v1, 0.f);
                        *(uint32_t*)&g_h[(size_t)slot * H + col] = pack_h2(v0, v1);
                    } else {
                        float2 v = make_float2(gate * v0, gate * v1);
                        *(float2*)&g_eo[(size_t)slot * O + col] = v;
                    }
                }
            }
        }
    }
}

// ---------------- task towers ----------------
__global__ __launch_bounds__(256) void k_tower(
    const float* __restrict__ tw1, const float* __restrict__ tb1,
    const float* __restrict__ tw2, const float* __restrict__ tb2,
    float* __restrict__ out)
{
    int b0 = blockIdx.x * 16;
    int tid = threadIdx.x;
    int lane = tid & 31, wid = tid >> 5;

    __shared__ float moe_sh[16][O];
    __shared__ float sred[16][8];

    #pragma unroll
    for (int r = 0; r < 16; r++) {
        int b = b0 + r;
        int s0 = g_pair[b * 2 + 0], s1 = g_pair[b * 2 + 1];
        for (int c = tid; c < O; c += 256)
            moe_sh[r][c] = g_eo[(size_t)s0 * O + c] + g_eo[(size_t)s1 * O + c];
    }
    __syncthreads();

    for (int t = 0; t < T; t++) {
        float acc[16];
        #pragma unroll
        for (int r = 0; r < 16; r++) acc[r] = 0.f;

        const float* w1 = tw1 + (size_t)t * O * TH + tid;
        for (int o = 0; o < O; o++) {
            float w = w1[(size_t)o * TH];
            #pragma unroll
            for (int r = 0; r < 16; r++) acc[r] += moe_sh[r][o] * w;
        }
        float bb = tb1[t * TH + tid];
        float w2 = tw2[t * TH + tid];

        #pragma unroll
        for (int r = 0; r < 16; r++) {
            float th = fmaxf(acc[r] + bb, 0.f);
            float v = th * w2;
            for (int off = 16; off; off >>= 1)
                v += __shfl_down_sync(0xffffffffu, v, off);
            if (lane == 0) sred[r][wid] = v;
        }
        __syncthreads();
        if (tid < 16) {
            float s = 0.f;
            #pragma unroll
            for (int w = 0; w < 8; w++) s += sred[tid][w];
            out[(b0 + tid) * T + t] = s + tb2[t];
        }
        __syncthreads();
    }
}

// ---------------- launch ----------------
extern "C" void kernel_launch(void* const* d_in, const int* in_sizes, int n_in,
                              void* d_out, int out_size)
{
    const float* x     = (const float*)d_in[0];
    const float* plew  = (const float*)d_in[1];
    const float* pleb  = (const float*)d_in[2];
    const float* embW  = (const float*)d_in[3];
    const float* embb  = (const float*)d_in[4];
    const float* gW    = (const float*)d_in[5];
    const float* gb    = (const float*)d_in[6];
    const float* eW1   = (const float*)d_in[7];
    const float* eb1   = (const float*)d_in[8];
    const float* eW2   = (const float*)d_in[9];
    const float* eb2   = (const float*)d_in[10];
    const float* tw1   = (const float*)d_in[11];
    const float* tb1   = (const float*)d_in[12];
    const float* tw2   = (const float*)d_in[13];
    const float* tb2   = (const float*)d_in[14];
    float* out = (float*)d_out;

    const int SMEM_BYTES = 3 * (int)STG_BYTES;   // 98304
    static bool attr_done = false;
    if (!attr_done) {
        cudaFuncSetAttribute(k_mma_gemm<F, H, 0>, cudaFuncAttributeMaxDynamicSharedMemorySize, SMEM_BYTES);
        cudaFuncSetAttribute(k_mma_gemm<H, O, 1>, cudaFuncAttributeMaxDynamicSharedMemorySize, SMEM_BYTES);
        attr_done = true;
    }

    __half *w1t, *w2t, *flat_hi, *h_buf;
    cudaGetSymbolAddress((void**)&w1t, g_w1t);
    cudaGetSymbolAddress((void**)&w2t, g_w2t);
    cudaGetSymbolAddress((void**)&flat_hi, g_flat_hi);
    cudaGetSymbolAddress((void**)&h_buf, g_h);

    k_init<<<1, 32>>>();
    k_wsplit<<<dim3(H / 32, F / 32, E), dim3(32, 8)>>>(eW1, w1t, F, H);
    k_wsplit<<<dim3(O / 32, H / 32, E), dim3(32, 8)>>>(eW2, w2t, H, O);
    k_ple<<<dim3(NF, B / 64), 256>>>(x, plew, pleb, embW, embb);
    k_gate<<<B, 256>>>(gW, gb);
    k_scan<<<1, 32>>>();
    k_assign<<<(B + 255) / 256, 256>>>();

    k_mma_gemm<F, H, 0><<<dim3(H / 128, B / GBM, E), 256, SMEM_BYTES>>>(flat_hi, w1t, eb1);
    k_mma_gemm<H, O, 1><<<dim3(O / 128, B / GBM, E), 256, SMEM_BYTES>>>(h_buf, w2t, eb2);

    k_tower<<<B / 16, 256>>>(tw1, tb1, tw2, tb2, out);
}

// round 12
// speedup vs baseline: 1.7785x; 1.0085x over previous
#include <cuda_runtime.h>
#include <cuda_fp16.h>
#include <cstdint>
#include <math.h>

// Problem constants
#define B    4096
#define NF   64
#define KB   48
#define DE   64
#define F    4096
#define E    8
#define H    1024
#define O    512
#define T    2
#define TH   256

// ---------------- low-level helpers (plain sm_80+ PTX only) ----------------
__device__ __forceinline__ uint32_t smem_to_u32(const void* p) {
    uint32_t a;
    asm("{ .reg .u64 t; cvta.to.shared.u64 t, %1; cvt.u32.u64 %0, t; }" : "=r"(a) : "l"(p));
    return a;
}
__device__ __forceinline__ void cp_async16(uint32_t dst, const void* src, int src_bytes) {
    asm volatile("cp.async.cg.shared.global [%0], [%1], 16, %2;"
                 :: "r"(dst), "l"(src), "r"(src_bytes) : "memory");
}
#define CP_COMMIT() asm volatile("cp.async.commit_group;" ::: "memory")
#define CP_WAIT(n)  asm volatile("cp.async.wait_group %0;" :: "n"(n) : "memory")

__device__ __forceinline__ void ldsm_x4(uint32_t* r, uint32_t addr) {
    asm volatile("ldmatrix.sync.aligned.m8n8.x4.shared.b16 {%0,%1,%2,%3}, [%4];"
                 : "=r"(r[0]), "=r"(r[1]), "=r"(r[2]), "=r"(r[3]) : "r"(addr));
}
__device__ __forceinline__ void mma_f16(float* c, const uint32_t* a, const uint32_t* b) {
    asm volatile(
        "mma.sync.aligned.m16n8k16.row.col.f32.f16.f16.f32 "
        "{%0,%1,%2,%3}, {%4,%5,%6,%7}, {%8,%9}, {%0,%1,%2,%3};"
        : "+f"(c[0]), "+f"(c[1]), "+f"(c[2]), "+f"(c[3])
        : "r"(a[0]), "r"(a[1]), "r"(a[2]), "r"(a[3]), "r"(b[0]), "r"(b[1]));
}
__device__ __forceinline__ uint32_t pack_h2(float v0, float v1) {
    __half2 h = __halves2half2(__float2half_rn(v0), __float2half_rn(v1));
    return *(uint32_t*)&h;
}

// ---------------- device scratch ----------------
__device__ __half g_flat_hi[(size_t)B * F];     // 32 MB
__device__ __half g_flat_lo[(size_t)B * F];     // 32 MB (gate exactness only)
__device__ __half g_w1t[(size_t)E * H * F];     // 64 MB  [e][h][f]
__device__ __half g_w2t[(size_t)E * O * H];     // 8 MB   [e][o][h]
__device__ __half g_h[(size_t)2 * B * H];       // 16 MB
__device__ float g_eo[(size_t)2 * B * O];       // 16 MB
__device__ int   g_count[E];
__device__ int   g_base[E];
__device__ int   g_cursor[E];
__device__ int   g_te[B * 2];
__device__ float g_tg[B * 2];
__device__ int   g_rows[2 * B];
__device__ float g_gates[2 * B];
__device__ int   g_pair[B * 2];

// ---------------- init ----------------
__global__ void k_init() {
    if (threadIdx.x < E) g_count[threadIdx.x] = 0;
}

// ---------------- weight transpose: W[e][k][n] -> T[e][n][k] fp16 ----------------
__global__ __launch_bounds__(256) void k_wsplit(
    const float* __restrict__ W, __half* __restrict__ Tw, int Kdim, int Ndim)
{
    __shared__ float t[32][33];
    int e = blockIdx.z;
    int kb = blockIdx.y * 32;
    int nb = blockIdx.x * 32;
    int tx = threadIdx.x, ty = threadIdx.y;
    const float* Wb = W + (size_t)e * Kdim * Ndim;
    #pragma unroll
    for (int i = ty; i < 32; i += 8)
        t[i][tx] = Wb[(size_t)(kb + i) * Ndim + nb + tx];
    __syncthreads();
    #pragma unroll
    for (int i = ty; i < 32; i += 8) {
        float v = t[tx][i];
        size_t o = ((size_t)e * Ndim + nb + i) * Kdim + kb + tx;
        Tw[o] = __float2half_rn(v);
    }
}

// ---------------- PLE + embedding + ReLU -> flat hi/lo (fp16 split) ----------------
__global__ __launch_bounds__(256) void k_ple(
    const float* __restrict__ x, const float* __restrict__ plew,
    const float* __restrict__ pleb, const float* __restrict__ embW,
    const float* __restrict__ embb)
{
    int n = blockIdx.x;
    int b0 = blockIdx.y * 64;
    int tid = threadIdx.x;

    __shared__ float Wsh[KB * DE];
    __shared__ float wsh[KB], bsh[KB], ebias[DE];
    __shared__ float xs[64];
    __shared__ float enc_sh[64][KB];

    for (int i = tid; i < KB * DE; i += 256) Wsh[i] = embW[(size_t)n * KB * DE + i];
    if (tid < KB) { wsh[tid] = plew[n * KB + tid]; bsh[tid] = pleb[n * KB + tid]; }
    if (tid < DE) ebias[tid] = embb[n * DE + tid];
    if (tid < 64) xs[tid] = x[(b0 + tid) * NF + n];
    __syncthreads();

    for (int idx = tid; idx < 64 * KB; idx += 256) {
        int bl = idx / KB, k = idx - bl * KB;
        float enc = bsh[k] + wsh[k] * xs[bl];
        if (k == 0)           enc = fminf(enc, 1.f);
        else if (k == KB - 1) enc = fmaxf(enc, 0.f);
        else                  enc = fminf(fmaxf(enc, 0.f), 1.f);
        enc_sh[bl][k] = enc;
    }
    __syncthreads();

    int c0 = (tid & 15) * 4;
    int r0 = (tid >> 4) * 4;

    float acc[4][4];
    #pragma unroll
    for (int r = 0; r < 4; r++)
        #pragma unroll
        for (int j = 0; j < 4; j++) acc[r][j] = ebias[c0 + j];

    #pragma unroll
    for (int k4 = 0; k4 < KB; k4 += 4) {
        float4 wv[4];
        #pragma unroll
        for (int kk = 0; kk < 4; kk++)
            wv[kk] = *(const float4*)&Wsh[(k4 + kk) * DE + c0];
        #pragma unroll
        for (int r = 0; r < 4; r++) {
            float4 ev = *(const float4*)&enc_sh[r0 + r][k4];
            const float* w0 = (const float*)&wv[0];
            const float* w1 = (const float*)&wv[1];
            const float* w2 = (const float*)&wv[2];
            const float* w3 = (const float*)&wv[3];
            #pragma unroll
            for (int j = 0; j < 4; j++)
                acc[r][j] += ev.x * w0[j] + ev.y * w1[j] + ev.z * w2[j] + ev.w * w3[j];
        }
    }

    #pragma unroll
    for (int r = 0; r < 4; r++) {
        int b = b0 + r0 + r;
        uint32_t hw[2], lw[2];
        #pragma unroll
        for (int p = 0; p < 2; p++) {
            float v0 = fmaxf(acc[r][p * 2 + 0], 0.f);
            float v1 = fmaxf(acc[r][p * 2 + 1], 0.f);
            __half h0 = __float2half_rn(v0);
            __half h1 = __float2half_rn(v1);
            hw[p] = pack_h2(v0, v1);
            lw[p] = pack_h2(v0 - __half2float(h0), v1 - __half2float(h1));
        }
        size_t idx = (size_t)b * F + n * DE + c0;
        *(uint2*)&g_flat_hi[idx] = make_uint2(hw[0], hw[1]);
        *(uint2*)&g_flat_lo[idx] = make_uint2(lw[0], lw[1]);
    }
}

// ---------------- gate (exact activations via hi+lo, vectorized) ----------------
__global__ __launch_bounds__(256) void k_gate(
    const float* __restrict__ gW, const float* __restrict__ gb)
{
    int b = blockIdx.x;
    int tid = threadIdx.x;
    int lane = tid & 31, wid = tid >> 5;

    float acc[E];
    #pragma unroll
    for (int e = 0; e < E; e++) acc[e] = 0.f;

    const __half* xh = g_flat_hi + (size_t)b * F;
    const __half* xl = g_flat_lo + (size_t)b * F;
    #pragma unroll
    for (int f0 = 0; f0 < F; f0 += 256 * 4) {
        int f = f0 + tid * 4;
        uint2 hv = *(const uint2*)&xh[f];
        uint2 lv = *(const uint2*)&xl[f];
        __half2 h01 = *(__half2*)&hv.x, h23 = *(__half2*)&hv.y;
        __half2 l01 = *(__half2*)&lv.x, l23 = *(__half2*)&lv.y;
        float xv[4];
        xv[0] = __half2float(__low2half(h01)) + __half2float(__low2half(l01));
        xv[1] = __half2float(__high2half(h01)) + __half2float(__high2half(l01));
        xv[2] = __half2float(__low2half(h23)) + __half2float(__low2half(l23));
        xv[3] = __half2float(__high2half(h23)) + __half2float(__high2half(l23));
        #pragma unroll
        for (int q = 0; q < 4; q++) {
            const float4* gwp = (const float4*)&gW[(f + q) * E];
            float4 g0 = gwp[0], g1 = gwp[1];
            acc[0] += xv[q] * g0.x; acc[1] += xv[q] * g0.y;
            acc[2] += xv[q] * g0.z; acc[3] += xv[q] * g0.w;
            acc[4] += xv[q] * g1.x; acc[5] += xv[q] * g1.y;
            acc[6] += xv[q] * g1.z; acc[7] += xv[q] * g1.w;
        }
    }
    #pragma unroll
    for (int e = 0; e < E; e++)
        for (int off = 16; off; off >>= 1)
            acc[e] += __shfl_down_sync(0xffffffffu, acc[e], off);

    __shared__ float sb[E][8];
    __shared__ float slog[E];
    if (lane == 0) {
        #pragma unroll
        for (int e = 0; e < E; e++) sb[e][wid] = acc[e];
    }
    __syncthreads();
    if (tid < E) {
        float s = 0.f;
        #pragma unroll
        for (int w = 0; w < 8; w++) s += sb[tid][w];
        slog[tid] = s + gb[tid];
    }
    __syncthreads();
    if (tid == 0) {
        int i0 = 0;
        #pragma unroll
        for (int e = 1; e < E; e++) if (slog[e] > slog[i0]) i0 = e;
        int i1 = (i0 == 0) ? 1 : 0;
        #pragma unroll
        for (int e = 0; e < E; e++) if (e != i0 && slog[e] > slog[i1]) i1 = e;
        float e1 = __expf(slog[i1] - slog[i0]);
        float inv = 1.f / (1.f + e1);
        g_te[b * 2 + 0] = i0;  g_tg[b * 2 + 0] = inv;
        g_te[b * 2 + 1] = i1;  g_tg[b * 2 + 1] = e1 * inv;
        atomicAdd(&g_count[i0], 1);
        atomicAdd(&g_count[i1], 1);
    }
}

__global__ void k_scan() {
    if (threadIdx.x == 0) {
        int s = 0;
        for (int e = 0; e < E; e++) { g_base[e] = s; g_cursor[e] = s; s += g_count[e]; }
    }
}

__global__ __launch_bounds__(256) void k_assign() {
    int b = blockIdx.x * 256 + threadIdx.x;
    if (b >= B) return;
    #pragma unroll
    for (int j = 0; j < 2; j++) {
        int e = g_te[b * 2 + j];
        int slot = atomicAdd(&g_cursor[e], 1);
        g_rows[slot]  = b;
        g_gates[slot] = g_tg[b * 2 + j];
        g_pair[b * 2 + j] = slot;
    }
}

// ---------------- fp16 register-MMA expert GEMM (single A plane) ----------------
// CTA tile 128x128, 8 warps (2m x 4n), warp tile 64x32, k-tile 64, 3-stage cp.async,
// 32KB/stage -> 96KB -> 2 CTAs/SM.
#define GBM 128
#define GKT 64
#define STG_BYTES 32768u
#define OFF_B_C   16384u

template<int KTOT, int NTOT, int MODE>
__global__ __launch_bounds__(256, 2) void k_mma_gemm(
    const __half* __restrict__ A, const __half* __restrict__ Wt,
    const float* __restrict__ bias)
{
    int e = blockIdx.z;
    int cnt = g_count[e];
    int m0 = blockIdx.y * GBM;
    if (m0 >= cnt) return;
    int base = g_base[e];
    int n0 = blockIdx.x * 128;

    extern __shared__ char smem[];
    uint32_t sb = smem_to_u32(smem);
    __shared__ int rows_s[GBM];

    int tid = threadIdx.x;
    int lane = tid & 31, wid = tid >> 5;

    if (MODE == 0 && tid < GBM) {
        int m = m0 + tid;
        rows_s[tid] = (m < cnt) ? g_rows[base + m] : -1;
    }
    __syncthreads();

    // -------- loader setup: thread -> (row 0..127, 4 chunks of 16B) --------
    int lrow = tid >> 1;
    int lcb  = (tid & 1) * 4;
    const __half* arow;
    int abytes;
    if (MODE == 0) {
        int gr = rows_s[lrow];
        abytes = (gr >= 0) ? 16 : 0;
        int r = (gr >= 0) ? gr : 0;
        arow = A + (size_t)r * KTOT;
    } else {
        int m = m0 + lrow;
        abytes = (m < cnt) ? 16 : 0;
        size_t r = (m < cnt) ? (size_t)(base + m) : 0;
        arow = A + r * KTOT;
    }
    const __half* brow = Wt + ((size_t)e * NTOT + n0 + lrow) * KTOT;
    uint32_t lsw = (uint32_t)((lrow & 7) << 4);
    uint32_t lbase = (uint32_t)(lrow * 128);

    // -------- mma setup --------
    int wm = wid >> 2;            // 0..1
    int wn = wid & 3;             // 0..3
    int a_row = wm * 64 + (lane & 15);
    uint32_t a_c  = (uint32_t)((lane >> 4) * 16);
    uint32_t asw  = (uint32_t)((a_row & 7) << 4);
    int b_row = wn * 32 + (lane & 7) + ((lane >> 4) << 3);
    uint32_t b_c  = (uint32_t)(((lane >> 3) & 1) * 16);
    uint32_t bsw  = (uint32_t)((b_row & 7) << 4);

    float acc[4][4][4];
    #pragma unroll
    for (int i = 0; i < 4; i++)
        #pragma unroll
        for (int j = 0; j < 4; j++)
            #pragma unroll
            for (int q = 0; q < 4; q++) acc[i][j][q] = 0.f;

    const int NT = KTOT / GKT;

    #define LOAD_STAGE(stg_, kt_) do {                                           \
        uint32_t s_ = sb + (uint32_t)(stg_) * STG_BYTES;                          \
        int k0_ = (kt_) * GKT;                                                    \
        _Pragma("unroll")                                                         \
        for (int q = 0; q < 4; q++) {                                             \
            int ch = lcb + q;                                                     \
            uint32_t so = lbase + (((uint32_t)(ch * 16)) ^ lsw);                  \
            cp_async16(s_ + so, arow + k0_ + ch * 8, abytes);                     \
            cp_async16(s_ + OFF_B_C + so, brow + k0_ + ch * 8, 16);               \
        }                                                                         \
        CP_COMMIT();                                                              \
    } while (0)

    // prime stages 0,1
    LOAD_STAGE(0, 0);
    if (NT > 1) LOAD_STAGE(1, 1);

    int stg = 0;
    for (int kt = 0; kt < NT; kt++) {
        if (kt + 2 < NT) {
            int ns = stg + 2; if (ns >= 3) ns -= 3;
            LOAD_STAGE(ns, kt + 2);
            CP_WAIT(2);
        } else if (kt + 1 < NT) {
            CP_WAIT(1);
        } else {
            CP_WAIT(0);
        }
        __syncthreads();

        uint32_t s0 = sb + (uint32_t)stg * STG_BYTES;
        #pragma unroll
        for (int kk = 0; kk < 4; kk++) {
            uint32_t ah[4][4], bh[2][4];
            #pragma unroll
            for (int i = 0; i < 4; i++) {
                uint32_t ro = (uint32_t)((a_row + i * 16) * 128);
                ldsm_x4(ah[i], s0 + ro + ((a_c + kk * 32) ^ asw));
            }
            #pragma unroll
            for (int p = 0; p < 2; p++) {
                uint32_t ro = (uint32_t)((b_row + p * 16) * 128);
                ldsm_x4(bh[p], s0 + OFF_B_C + ro + ((b_c + kk * 32) ^ bsw));
            }
            #pragma unroll
            for (int i = 0; i < 4; i++)
                #pragma unroll
                for (int j = 0; j < 4; j++) {
                    const uint32_t* bj = &bh[j >> 1][(j & 1) * 2];
                    mma_f16(acc[i][j], ah[i], bj);
                }
        }
        __syncthreads();
        stg = (stg == 2) ? 0 : stg + 1;
    }
    #undef LOAD_STAGE

    // -------- epilogue --------
    int g = lane >> 2;
    int cg = (lane & 3) * 2;
    #pragma unroll
    for (int i = 0; i < 4; i++) {
        #pragma unroll
        for (int half = 0; half < 2; half++) {
            int m = m0 + wm * 64 + i * 16 + g + half * 8;
            if (m < cnt) {
                int slot = base + m;
                float gate = (MODE == 1) ? g_gates[slot] : 0.f;
                #pragma unroll
                for (int j = 0; j < 4; j++) {
                    int col = n0 + wn * 32 + j * 8 + cg;
                    float bv0 = bias[(size_t)e * NTOT + col];
                    float bv1 = bias[(size_t)e * NTOT + col + 1];
                    float v0 = acc[i][j][half * 2 + 0] + bv0;
                    float v1 = acc[i][j][half * 2 + 1] + bv1;
                    if (MODE == 0) {
                        v0 = fmaxf(v0, 0.f); v1 = fmaxf(v1, 0.f);
                        *(uint32_t*)&g_h[(size_t)slot * H + col] = pack_h2(v0, v1);
                    } else {
                        float2 v = make_float2(gate * v0, gate * v1);
                        *(float2*)&g_eo[(size_t)slot * O + col] = v;
                    }
                }
            }
        }
    }
}

// ---------------- task towers ----------------
__global__ __launch_bounds__(256) void k_tower(
    const float* __restrict__ tw1, const float* __restrict__ tb1,
    const float* __restrict__ tw2, const float* __restrict__ tb2,
    float* __restrict__ out)
{
    int b0 = blockIdx.x * 16;
    int tid = threadIdx.x;
    int lane = tid & 31, wid = tid >> 5;

    __shared__ float moe_sh[16][O];
    __shared__ float sred[16][8];

    #pragma unroll
    for (int r = 0; r < 16; r++) {
        int b = b0 + r;
        int s0 = g_pair[b * 2 + 0], s1 = g_pair[b * 2 + 1];
        for (int c = tid; c < O; c += 256)
            moe_sh[r][c] = g_eo[(size_t)s0 * O + c] + g_eo[(size_t)s1 * O + c];
    }
    __syncthreads();

    for (int t = 0; t < T; t++) {
        float acc[16];
        #pragma unroll
        for (int r = 0; r < 16; r++) acc[r] = 0.f;

        const float* w1 = tw1 + (size_t)t * O * TH + tid;
        for (int o = 0; o < O; o++) {
            float w = w1[(size_t)o * TH];
            #pragma unroll
            for (int r = 0; r < 16; r++) acc[r] += moe_sh[r][o] * w;
        }
        float bb = tb1[t * TH + tid];
        float w2 = tw2[t * TH + tid];

        #pragma unroll
        for (int r = 0; r < 16; r++) {
            float th = fmaxf(acc[r] + bb, 0.f);
            float v = th * w2;
            for (int off = 16; off; off >>= 1)
                v += __shfl_down_sync(0xffffffffu, v, off);
            if (lane == 0) sred[r][wid] = v;
        }
        __syncthreads();
        if (tid < 16) {
            float s = 0.f;
            #pragma unroll
            for (int w = 0; w < 8; w++) s += sred[tid][w];
            out[(b0 + tid) * T + t] = s + tb2[t];
        }
        __syncthreads();
    }
}

// ---------------- launch ----------------
extern "C" void kernel_launch(void* const* d_in, const int* in_sizes, int n_in,
                              void* d_out, int out_size)
{
    const float* x     = (const float*)d_in[0];
    const float* plew  = (const float*)d_in[1];
    const float* pleb  = (const float*)d_in[2];
    const float* embW  = (const float*)d_in[3];
    const float* embb  = (const float*)d_in[4];
    const float* gW    = (const float*)d_in[5];
    const float* gb    = (const float*)d_in[6];
    const float* eW1   = (const float*)d_in[7];
    const float* eb1   = (const float*)d_in[8];
    const float* eW2   = (const float*)d_in[9];
    const float* eb2   = (const float*)d_in[10];
    const float* tw1   = (const float*)d_in[11];
    const float* tb1   = (const float*)d_in[12];
    const float* tw2   = (const float*)d_in[13];
    const float* tb2   = (const float*)d_in[14];
    float* out = (float*)d_out;

    const int SMEM_BYTES = 3 * (int)STG_BYTES;   // 98304
    static cudaStream_t s2 = nullptr;
    static cudaEvent_t ev_fork = nullptr, ev_join = nullptr;
    if (!s2) {
        cudaFuncSetAttribute(k_mma_gemm<F, H, 0>, cudaFuncAttributeMaxDynamicSharedMemorySize, SMEM_BYTES);
        cudaFuncSetAttribute(k_mma_gemm<H, O, 1>, cudaFuncAttributeMaxDynamicSharedMemorySize, SMEM_BYTES);
        cudaStreamCreateWithFlags(&s2, cudaStreamNonBlocking);
        cudaEventCreateWithFlags(&ev_fork, cudaEventDisableTiming);
        cudaEventCreateWithFlags(&ev_join, cudaEventDisableTiming);
    }

    __half *w1t, *w2t, *flat_hi, *h_buf;
    cudaGetSymbolAddress((void**)&w1t, g_w1t);
    cudaGetSymbolAddress((void**)&w2t, g_w2t);
    cudaGetSymbolAddress((void**)&flat_hi, g_flat_hi);
    cudaGetSymbolAddress((void**)&h_buf, g_h);

    k_init<<<1, 32>>>();

    // fork: weight convert/transpose runs concurrently with PLE->gate->assign
    cudaEventRecord(ev_fork, 0);
    cudaStreamWaitEvent(s2, ev_fork, 0);
    k_wsplit<<<dim3(H / 32, F / 32, E), dim3(32, 8), 0, s2>>>(eW1, w1t, F, H);
    k_wsplit<<<dim3(O / 32, H / 32, E), dim3(32, 8), 0, s2>>>(eW2, w2t, H, O);
    cudaEventRecord(ev_join, s2);

    k_ple<<<dim3(NF, B / 64), 256>>>(x, plew, pleb, embW, embb);
    k_gate<<<B, 256>>>(gW, gb);
    k_scan<<<1, 32>>>();
    k_assign<<<(B + 255) / 256, 256>>>();

    // join before GEMM1 consumes weights
    cudaStreamWaitEvent(0, ev_join, 0);

    k_mma_gemm<F, H, 0><<<dim3(H / 128, B / GBM, E), 256, SMEM_BYTES>>>(flat_hi, w1t, eb1);
    k_mma_gemm<H, O, 1><<<dim3(O / 128, B / GBM, E), 256, SMEM_BYTES>>>(h_buf, w2t, eb2);

    k_tower<<<B / 16, 256>>>(tw1, tb1, tw2, tb2, out);
}

// round 13
// speedup vs baseline: 1.9786x; 1.1125x over previous
#include <cuda_runtime.h>
#include <cuda_fp16.h>
#include <cstdint>
#include <math.h>

// Problem constants
#define B    4096
#define NF   64
#define KB   48
#define DE   64
#define F    4096
#define E    8
#define H    1024
#define O    512
#define T    2
#define TH   256

// ---------------- low-level helpers (plain sm_80+ PTX only) ----------------
__device__ __forceinline__ uint32_t smem_to_u32(const void* p) {
    uint32_t a;
    asm("{ .reg .u64 t; cvta.to.shared.u64 t, %1; cvt.u32.u64 %0, t; }" : "=r"(a) : "l"(p));
    return a;
}
__device__ __forceinline__ void cp_async16(uint32_t dst, const void* src, int src_bytes) {
    asm volatile("cp.async.cg.shared.global [%0], [%1], 16, %2;"
                 :: "r"(dst), "l"(src), "r"(src_bytes) : "memory");
}
#define CP_COMMIT() asm volatile("cp.async.commit_group;" ::: "memory")
#define CP_WAIT(n)  asm volatile("cp.async.wait_group %0;" :: "n"(n) : "memory")

__device__ __forceinline__ void ldsm_x4(uint32_t* r, uint32_t addr) {
    asm volatile("ldmatrix.sync.aligned.m8n8.x4.shared.b16 {%0,%1,%2,%3}, [%4];"
                 : "=r"(r[0]), "=r"(r[1]), "=r"(r[2]), "=r"(r[3]) : "r"(addr));
}
__device__ __forceinline__ void mma_f16(float* c, const uint32_t* a, const uint32_t* b) {
    asm volatile(
        "mma.sync.aligned.m16n8k16.row.col.f32.f16.f16.f32 "
        "{%0,%1,%2,%3}, {%4,%5,%6,%7}, {%8,%9}, {%0,%1,%2,%3};"
        : "+f"(c[0]), "+f"(c[1]), "+f"(c[2]), "+f"(c[3])
        : "r"(a[0]), "r"(a[1]), "r"(a[2]), "r"(a[3]), "r"(b[0]), "r"(b[1]));
}
__device__ __forceinline__ uint32_t pack_h2(float v0, float v1) {
    __half2 h = __halves2half2(__float2half_rn(v0), __float2half_rn(v1));
    return *(uint32_t*)&h;
}

// ---------------- device scratch ----------------
__device__ __half g_flat[(size_t)B * F];        // 32 MB (fp16 activations)
__device__ float  g_pl[(size_t)B * NF * E];     // 8 MB  per-(row,feature) gate partials
__device__ __half g_w1t[(size_t)E * H * F];     // 64 MB  [e][h][f]
__device__ __half g_w2t[(size_t)E * O * H];     // 8 MB   [e][o][h]
__device__ __half g_h[(size_t)2 * B * H];       // 16 MB
__device__ float g_eo[(size_t)2 * B * O];       // 16 MB
__device__ int   g_count[E];
__device__ int   g_base[E];
__device__ int   g_cursor[E];
__device__ int   g_te[B * 2];
__device__ float g_tg[B * 2];
__device__ int   g_rows[2 * B];
__device__ float g_gates[2 * B];
__device__ int   g_pair[B * 2];

// ---------------- init ----------------
__global__ void k_init() {
    if (threadIdx.x < E) g_count[threadIdx.x] = 0;
}

// ---------------- weight transpose: W[e][k][n] -> T[e][n][k] fp16 ----------------
__global__ __launch_bounds__(256) void k_wsplit(
    const float* __restrict__ W, __half* __restrict__ Tw, int Kdim, int Ndim)
{
    __shared__ float t[32][33];
    int e = blockIdx.z;
    int kb = blockIdx.y * 32;
    int nb = blockIdx.x * 32;
    int tx = threadIdx.x, ty = threadIdx.y;
    const float* Wb = W + (size_t)e * Kdim * Ndim;
    #pragma unroll
    for (int i = ty; i < 32; i += 8)
        t[i][tx] = Wb[(size_t)(kb + i) * Ndim + nb + tx];
    __syncthreads();
    #pragma unroll
    for (int i = ty; i < 32; i += 8) {
        float v = t[tx][i];
        size_t o = ((size_t)e * Ndim + nb + i) * Kdim + kb + tx;
        Tw[o] = __float2half_rn(v);
    }
}

// ---------------- PLE + embedding + ReLU -> flat fp16, + fused gate partials ----------------
// grid (NF, B/64), block 256. thread = (4 rows) x (4 d-cols).
__global__ __launch_bounds__(256) void k_ple(
    const float* __restrict__ x, const float* __restrict__ plew,
    const float* __restrict__ pleb, const float* __restrict__ embW,
    const float* __restrict__ embb, const float* __restrict__ gW)
{
    int n = blockIdx.x;
    int b0 = blockIdx.y * 64;
    int tid = threadIdx.x;

    __shared__ float Wsh[KB * DE];      // 12 KB
    __shared__ float wsh[KB], bsh[KB], ebias[DE];
    __shared__ float xs[64];
    __shared__ float enc_sh[64][KB];    // 12 KB
    __shared__ float gwsh[DE][E];       // 2 KB  gW slice for feature n

    for (int i = tid; i < KB * DE; i += 256) Wsh[i] = embW[(size_t)n * KB * DE + i];
    if (tid < KB) { wsh[tid] = plew[n * KB + tid]; bsh[tid] = pleb[n * KB + tid]; }
    if (tid < DE) ebias[tid] = embb[n * DE + tid];
    if (tid < 64) xs[tid] = x[(b0 + tid) * NF + n];
    for (int i = tid; i < DE * E; i += 256)
        ((float*)gwsh)[i] = gW[(size_t)(n * DE) * E + i];
    __syncthreads();

    for (int idx = tid; idx < 64 * KB; idx += 256) {
        int bl = idx / KB, k = idx - bl * KB;
        float enc = bsh[k] + wsh[k] * xs[bl];
        if (k == 0)           enc = fminf(enc, 1.f);
        else if (k == KB - 1) enc = fmaxf(enc, 0.f);
        else                  enc = fminf(fmaxf(enc, 0.f), 1.f);
        enc_sh[bl][k] = enc;
    }
    __syncthreads();

    int c0 = (tid & 15) * 4;
    int r0 = (tid >> 4) * 4;
    int lane = tid & 31;

    float acc[4][4];
    #pragma unroll
    for (int r = 0; r < 4; r++)
        #pragma unroll
        for (int j = 0; j < 4; j++) acc[r][j] = ebias[c0 + j];

    #pragma unroll
    for (int k4 = 0; k4 < KB; k4 += 4) {
        float4 wv[4];
        #pragma unroll
        for (int kk = 0; kk < 4; kk++)
            wv[kk] = *(const float4*)&Wsh[(k4 + kk) * DE + c0];
        #pragma unroll
        for (int r = 0; r < 4; r++) {
            float4 ev = *(const float4*)&enc_sh[r0 + r][k4];
            const float* w0 = (const float*)&wv[0];
            const float* w1 = (const float*)&wv[1];
            const float* w2 = (const float*)&wv[2];
            const float* w3 = (const float*)&wv[3];
            #pragma unroll
            for (int j = 0; j < 4; j++)
                acc[r][j] += ev.x * w0[j] + ev.y * w1[j] + ev.z * w2[j] + ev.w * w3[j];
        }
    }

    // ReLU, store fp16 flat, and accumulate gate partials in fp32
    float p[4][E];
    #pragma unroll
    for (int r = 0; r < 4; r++)
        #pragma unroll
        for (int e = 0; e < E; e++) p[r][e] = 0.f;

    #pragma unroll
    for (int r = 0; r < 4; r++) {
        int b = b0 + r0 + r;
        float v[4];
        #pragma unroll
        for (int j = 0; j < 4; j++) {
            v[j] = fmaxf(acc[r][j], 0.f);
            #pragma unroll
            for (int e = 0; e < E; e++)
                p[r][e] += v[j] * gwsh[c0 + j][e];
        }
        size_t idx = (size_t)b * F + n * DE + c0;
        *(uint2*)&g_flat[idx] = make_uint2(pack_h2(v[0], v[1]), pack_h2(v[2], v[3]));
    }

    // width-16 xor-shuffle reduction across the 16 col-thread groups (fixed order)
    #pragma unroll
    for (int off = 8; off; off >>= 1)
        #pragma unroll
        for (int r = 0; r < 4; r++)
            #pragma unroll
            for (int e = 0; e < E; e++)
                p[r][e] += __shfl_xor_sync(0xffffffffu, p[r][e], off);

    if ((lane & 15) == 0) {
        #pragma unroll
        for (int r = 0; r < 4; r++) {
            int b = b0 + r0 + r;
            float* dst = &g_pl[((size_t)b * NF + n) * E];
            *(float4*)&dst[0] = make_float4(p[r][0], p[r][1], p[r][2], p[r][3]);
            *(float4*)&dst[4] = make_float4(p[r][4], p[r][5], p[r][6], p[r][7]);
        }
    }
}

// ---------------- gate reduce + top-2 (deterministic fixed-order sums) ----------------
// grid B/32, block 256: thread = (row 0..31, expert 0..7)
__global__ __launch_bounds__(256) void k_gate2(const float* __restrict__ gb)
{
    int b0 = blockIdx.x * 32;
    int tid = threadIdx.x;
    int r = tid >> 3;
    int e = tid & 7;
    int b = b0 + r;

    const float* p = &g_pl[((size_t)b * NF) * E + e];
    float s = 0.f;
    #pragma unroll
    for (int n = 0; n < NF; n++) s += p[n * E];
    s += gb[e];

    __shared__ float sl[32][E];
    sl[r][e] = s;
    __syncthreads();

    if (e == 0) {
        int i0 = 0;
        #pragma unroll
        for (int q = 1; q < E; q++) if (sl[r][q] > sl[r][i0]) i0 = q;
        int i1 = (i0 == 0) ? 1 : 0;
        #pragma unroll
        for (int q = 0; q < E; q++) if (q != i0 && sl[r][q] > sl[r][i1]) i1 = q;
        float e1 = __expf(sl[r][i1] - sl[r][i0]);
        float inv = 1.f / (1.f + e1);
        g_te[b * 2 + 0] = i0;  g_tg[b * 2 + 0] = inv;
        g_te[b * 2 + 1] = i1;  g_tg[b * 2 + 1] = e1 * inv;
        atomicAdd(&g_count[i0], 1);
        atomicAdd(&g_count[i1], 1);
    }
}

__global__ void k_scan() {
    if (threadIdx.x == 0) {
        int s = 0;
        for (int e = 0; e < E; e++) { g_base[e] = s; g_cursor[e] = s; s += g_count[e]; }
    }
}

__global__ __launch_bounds__(256) void k_assign() {
    int b = blockIdx.x * 256 + threadIdx.x;
    if (b >= B) return;
    #pragma unroll
    for (int j = 0; j < 2; j++) {
        int e = g_te[b * 2 + j];
        int slot = atomicAdd(&g_cursor[e], 1);
        g_rows[slot]  = b;
        g_gates[slot] = g_tg[b * 2 + j];
        g_pair[b * 2 + j] = slot;
    }
}

// ---------------- fp16 register-MMA expert GEMM (single A plane) ----------------
// CTA tile 128x128, 8 warps (2m x 4n), warp tile 64x32, k-tile 64, 3-stage cp.async,
// 32KB/stage -> 96KB -> 2 CTAs/SM.
#define GBM 128
#define GKT 64
#define STG_BYTES 32768u
#define OFF_B_C   16384u

template<int KTOT, int NTOT, int MODE>
__global__ __launch_bounds__(256, 2) void k_mma_gemm(
    const __half* __restrict__ A, const __half* __restrict__ Wt,
    const float* __restrict__ bias)
{
    int e = blockIdx.z;
    int cnt = g_count[e];
    int m0 = blockIdx.y * GBM;
    if (m0 >= cnt) return;
    int base = g_base[e];
    int n0 = blockIdx.x * 128;

    extern __shared__ char smem[];
    uint32_t sb = smem_to_u32(smem);
    __shared__ int rows_s[GBM];

    int tid = threadIdx.x;
    int lane = tid & 31, wid = tid >> 5;

    if (MODE == 0 && tid < GBM) {
        int m = m0 + tid;
        rows_s[tid] = (m < cnt) ? g_rows[base + m] : -1;
    }
    __syncthreads();

    // -------- loader setup: thread -> (row 0..127, 4 chunks of 16B) --------
    int lrow = tid >> 1;
    int lcb  = (tid & 1) * 4;
    const __half* arow;
    int abytes;
    if (MODE == 0) {
        int gr = rows_s[lrow];
        abytes = (gr >= 0) ? 16 : 0;
        int r = (gr >= 0) ? gr : 0;
        arow = A + (size_t)r * KTOT;
    } else {
        int m = m0 + lrow;
        abytes = (m < cnt) ? 16 : 0;
        size_t r = (m < cnt) ? (size_t)(base + m) : 0;
        arow = A + r * KTOT;
    }
    const __half* brow = Wt + ((size_t)e * NTOT + n0 + lrow) * KTOT;
    uint32_t lsw = (uint32_t)((lrow & 7) << 4);
    uint32_t lbase = (uint32_t)(lrow * 128);

    // -------- mma setup --------
    int wm = wid >> 2;            // 0..1
    int wn = wid & 3;             // 0..3
    int a_row = wm * 64 + (lane & 15);
    uint32_t a_c  = (uint32_t)((lane >> 4) * 16);
    uint32_t asw  = (uint32_t)((a_row & 7) << 4);
    int b_row = wn * 32 + (lane & 7) + ((lane >> 4) << 3);
    uint32_t b_c  = (uint32_t)(((lane >> 3) & 1) * 16);
    uint32_t bsw  = (uint32_t)((b_row & 7) << 4);

    float acc[4][4][4];
    #pragma unroll
    for (int i = 0; i < 4; i++)
        #pragma unroll
        for (int j = 0; j < 4; j++)
            #pragma unroll
            for (int q = 0; q < 4; q++) acc[i][j][q] = 0.f;

    const int NT = KTOT / GKT;

    #define LOAD_STAGE(stg_, kt_) do {                                           \
        uint32_t s_ = sb + (uint32_t)(stg_) * STG_BYTES;                          \
        int k0_ = (kt_) * GKT;                                                    \
        _Pragma("unroll")                                                         \
        for (int q = 0; q < 4; q++) {                                             \
            int ch = lcb + q;                                                     \
            uint32_t so = lbase + (((uint32_t)(ch * 16)) ^ lsw);                  \
            cp_async16(s_ + so, arow + k0_ + ch * 8, abytes);                     \
            cp_async16(s_ + OFF_B_C + so, brow + k0_ + ch * 8, 16);               \
        }                                                                         \
        CP_COMMIT();                                                              \
    } while (0)

    // prime stages 0,1
    LOAD_STAGE(0, 0);
    if (NT > 1) LOAD_STAGE(1, 1);

    int stg = 0;
    for (int kt = 0; kt < NT; kt++) {
        if (kt + 2 < NT) {
            int ns = stg + 2; if (ns >= 3) ns -= 3;
            LOAD_STAGE(ns, kt + 2);
            CP_WAIT(2);
        } else if (kt + 1 < NT) {
            CP_WAIT(1);
        } else {
            CP_WAIT(0);
        }
        __syncthreads();

        uint32_t s0 = sb + (uint32_t)stg * STG_BYTES;
        #pragma unroll
        for (int kk = 0; kk < 4; kk++) {
            uint32_t ah[4][4], bh[2][4];
            #pragma unroll
            for (int i = 0; i < 4; i++) {
                uint32_t ro = (uint32_t)((a_row + i * 16) * 128);
                ldsm_x4(ah[i], s0 + ro + ((a_c + kk * 32) ^ asw));
            }
            #pragma unroll
            for (int p = 0; p < 2; p++) {
                uint32_t ro = (uint32_t)((b_row + p * 16) * 128);
                ldsm_x4(bh[p], s0 + OFF_B_C + ro + ((b_c + kk * 32) ^ bsw));
            }
            #pragma unroll
            for (int i = 0; i < 4; i++)
                #pragma unroll
                for (int j = 0; j < 4; j++) {
                    const uint32_t* bj = &bh[j >> 1][(j & 1) * 2];
                    mma_f16(acc[i][j], ah[i], bj);
                }
        }
        __syncthreads();
        stg = (stg == 2) ? 0 : stg + 1;
    }
    #undef LOAD_STAGE

    // -------- epilogue --------
    int g = lane >> 2;
    int cg = (lane & 3) * 2;
    #pragma unroll
    for (int i = 0; i < 4; i++) {
        #pragma unroll
        for (int half = 0; half < 2; half++) {
            int m = m0 + wm * 64 + i * 16 + g + half * 8;
            if (m < cnt) {
                int slot = base + m;
                float gate = (MODE == 1) ? g_gates[slot] : 0.f;
                #pragma unroll
                for (int j = 0; j < 4; j++) {
                    int col = n0 + wn * 32 + j * 8 + cg;
                    float bv0 = bias[(size_t)e * NTOT + col];
                    float bv1 = bias[(size_t)e * NTOT + col + 1];
                    float v0 = acc[i][j][half * 2 + 0] + bv0;
                    float v1 = acc[i][j][half * 2 + 1] + bv1;
                    if (MODE == 0) {
                        v0 = fmaxf(v0, 0.f); v1 = fmaxf(v1, 0.f);
                        *(uint32_t*)&g_h[(size_t)slot * H + col] = pack_h2(v0, v1);
                    } else {
                        float2 v = make_float2(gate * v0, gate * v1);
                        *(float2*)&g_eo[(size_t)slot * O + col] = v;
                    }
                }
            }
        }
    }
}

// ---------------- task towers ----------------
__global__ __launch_bounds__(256) void k_tower(
    const float* __restrict__ tw1, const float* __restrict__ tb1,
    const float* __restrict__ tw2, const float* __restrict__ tb2,
    float* __restrict__ out)
{
    int b0 = blockIdx.x * 16;
    int tid = threadIdx.x;
    int lane = tid & 31, wid = tid >> 5;

    __shared__ float moe_sh[16][O];
    __shared__ float sred[16][8];

    #pragma unroll
    for (int r = 0; r < 16; r++) {
        int b = b0 + r;
        int s0 = g_pair[b * 2 + 0], s1 = g_pair[b * 2 + 1];
        for (int c = tid; c < O; c += 256)
            moe_sh[r][c] = g_eo[(size_t)s0 * O + c] + g_eo[(size_t)s1 * O + c];
    }
    __syncthreads();

    for (int t = 0; t < T; t++) {
        float acc[16];
        #pragma unroll
        for (int r = 0; r < 16; r++) acc[r] = 0.f;

        const float* w1 = tw1 + (size_t)t * O * TH + tid;
        for (int o = 0; o < O; o++) {
            float w = w1[(size_t)o * TH];
            #pragma unroll
            for (int r = 0; r < 16; r++) acc[r] += moe_sh[r][o] * w;
        }
        float bb = tb1[t * TH + tid];
        float w2 = tw2[t * TH + tid];

        #pragma unroll
        for (int r = 0; r < 16; r++) {
            float th = fmaxf(acc[r] + bb, 0.f);
            float v = th * w2;
            for (int off = 16; off; off >>= 1)
                v += __shfl_down_sync(0xffffffffu, v, off);
            if (lane == 0) sred[r][wid] = v;
        }
        __syncthreads();
        if (tid < 16) {
            float s = 0.f;
            #pragma unroll
            for (int w = 0; w < 8; w++) s += sred[tid][w];
            out[(b0 + tid) * T + t] = s + tb2[t];
        }
        __syncthreads();
    }
}

// ---------------- launch ----------------
extern "C" void kernel_launch(void* const* d_in, const int* in_sizes, int n_in,
                              void* d_out, int out_size)
{
    const float* x     = (const float*)d_in[0];
    const float* plew  = (const float*)d_in[1];
    const float* pleb  = (const float*)d_in[2];
    const float* embW  = (const float*)d_in[3];
    const float* embb  = (const float*)d_in[4];
    const float* gW    = (const float*)d_in[5];
    const float* gb    = (const float*)d_in[6];
    const float* eW1   = (const float*)d_in[7];
    const float* eb1   = (const float*)d_in[8];
    const float* eW2   = (const float*)d_in[9];
    const float* eb2   = (const float*)d_in[10];
    const float* tw1   = (const float*)d_in[11];
    const float* tb1   = (const float*)d_in[12];
    const float* tw2   = (const float*)d_in[13];
    const float* tb2   = (const float*)d_in[14];
    float* out = (float*)d_out;

    const int SMEM_BYTES = 3 * (int)STG_BYTES;   // 98304
    static cudaStream_t s2 = nullptr;
    static cudaEvent_t ev_fork = nullptr, ev_join = nullptr;
    if (!s2) {
        cudaFuncSetAttribute(k_mma_gemm<F, H, 0>, cudaFuncAttributeMaxDynamicSharedMemorySize, SMEM_BYTES);
        cudaFuncSetAttribute(k_mma_gemm<H, O, 1>, cudaFuncAttributeMaxDynamicSharedMemorySize, SMEM_BYTES);
        cudaStreamCreateWithFlags(&s2, cudaStreamNonBlocking);
        cudaEventCreateWithFlags(&ev_fork, cudaEventDisableTiming);
        cudaEventCreateWithFlags(&ev_join, cudaEventDisableTiming);
    }

    __half *w1t, *w2t, *flat, *h_buf;
    cudaGetSymbolAddress((void**)&w1t, g_w1t);
    cudaGetSymbolAddress((void**)&w2t, g_w2t);
    cudaGetSymbolAddress((void**)&flat, g_flat);
    cudaGetSymbolAddress((void**)&h_buf, g_h);

    k_init<<<1, 32>>>();

    // fork: weight convert/transpose runs concurrently with PLE->gate->assign
    cudaEventRecord(ev_fork, 0);
    cudaStreamWaitEvent(s2, ev_fork, 0);
    k_wsplit<<<dim3(H / 32, F / 32, E), dim3(32, 8), 0, s2>>>(eW1, w1t, F, H);
    k_wsplit<<<dim3(O / 32, H / 32, E), dim3(32, 8), 0, s2>>>(eW2, w2t, H, O);
    cudaEventRecord(ev_join, s2);

    k_ple<<<dim3(NF, B / 64), 256>>>(x, plew, pleb, embW, embb, gW);
    k_gate2<<<B / 32, 256>>>(gb);
    k_scan<<<1, 32>>>();
    k_assign<<<(B + 255) / 256, 256>>>();

    // join before GEMM1 consumes weights
    cudaStreamWaitEvent(0, ev_join, 0);

    k_mma_gemm<F, H, 0><<<dim3(H / 128, B / GBM, E), 256, SMEM_BYTES>>>(flat, w1t, eb1);
    k_mma_gemm<H, O, 1><<<dim3(O / 128, B / GBM, E), 256, SMEM_BYTES>>>(h_buf, w2t, eb2);

    k_tower<<<B / 16, 256>>>(tw1, tb1, tw2, tb2, out);
}

// round 14
// speedup vs baseline: 2.3342x; 1.1797x over previous
#include <cuda_runtime.h>
#include <cuda_fp16.h>
#include <cstdint>
#include <math.h>

// Problem constants
#define B    4096
#define NF   64
#define KB   48
#define DE   64
#define F    4096
#define E    8
#define H    1024
#define O    512
#define T    2
#define TH   256

// ---------------- low-level helpers (plain sm_80+ PTX only) ----------------
__device__ __forceinline__ uint32_t smem_to_u32(const void* p) {
    uint32_t a;
    asm("{ .reg .u64 t; cvta.to.shared.u64 t, %1; cvt.u32.u64 %0, t; }" : "=r"(a) : "l"(p));
    return a;
}
__device__ __forceinline__ void cp_async16(uint32_t dst, const void* src, int src_bytes) {
    asm volatile("cp.async.cg.shared.global [%0], [%1], 16, %2;"
                 :: "r"(dst), "l"(src), "r"(src_bytes) : "memory");
}
#define CP_COMMIT() asm volatile("cp.async.commit_group;" ::: "memory")
#define CP_WAIT(n)  asm volatile("cp.async.wait_group %0;" :: "n"(n) : "memory")

__device__ __forceinline__ void ldsm_x4(uint32_t* r, uint32_t addr) {
    asm volatile("ldmatrix.sync.aligned.m8n8.x4.shared.b16 {%0,%1,%2,%3}, [%4];"
                 : "=r"(r[0]), "=r"(r[1]), "=r"(r[2]), "=r"(r[3]) : "r"(addr));
}
__device__ __forceinline__ void mma_f16(float* c, const uint32_t* a, const uint32_t* b) {
    asm volatile(
        "mma.sync.aligned.m16n8k16.row.col.f32.f16.f16.f32 "
        "{%0,%1,%2,%3}, {%4,%5,%6,%7}, {%8,%9}, {%0,%1,%2,%3};"
        : "+f"(c[0]), "+f"(c[1]), "+f"(c[2]), "+f"(c[3])
        : "r"(a[0]), "r"(a[1]), "r"(a[2]), "r"(a[3]), "r"(b[0]), "r"(b[1]));
}
__device__ __forceinline__ uint32_t pack_h2(float v0, float v1) {
    __half2 h = __halves2half2(__float2half_rn(v0), __float2half_rn(v1));
    return *(uint32_t*)&h;
}

// ---------------- device scratch ----------------
__device__ __half g_flat[(size_t)B * F];        // 32 MB (fp16 activations)
__device__ float  g_pl[(size_t)B * NF * E];     // 8 MB  per-(row,feature) gate partials
__device__ __half g_w1t[(size_t)E * H * F];     // 64 MB  [e][h][f]
__device__ __half g_w2t[(size_t)E * O * H];     // 8 MB   [e][o][h]
__device__ __half g_h[(size_t)2 * B * H];       // 16 MB
__device__ float g_eo[(size_t)2 * B * O];       // 16 MB
__device__ int   g_count[E];
__device__ int   g_base[E];
__device__ int   g_cursor[E];
__device__ int   g_te[B * 2];
__device__ float g_tg[B * 2];
__device__ int   g_rows[2 * B];
__device__ float g_gates[2 * B];
__device__ int   g_pair[B * 2];

// ---------------- init ----------------
__global__ void k_init() {
    if (threadIdx.x < E) g_count[threadIdx.x] = 0;
}

// ---------------- weight transpose: W[e][k][n] -> T[e][n][k] fp16 ----------------
__global__ __launch_bounds__(256) void k_wsplit(
    const float* __restrict__ W, __half* __restrict__ Tw, int Kdim, int Ndim)
{
    __shared__ float t[32][33];
    int e = blockIdx.z;
    int kb = blockIdx.y * 32;
    int nb = blockIdx.x * 32;
    int tx = threadIdx.x, ty = threadIdx.y;
    const float* Wb = W + (size_t)e * Kdim * Ndim;
    #pragma unroll
    for (int i = ty; i < 32; i += 8)
        t[i][tx] = Wb[(size_t)(kb + i) * Ndim + nb + tx];
    __syncthreads();
    #pragma unroll
    for (int i = ty; i < 32; i += 8) {
        float v = t[tx][i];
        size_t o = ((size_t)e * Ndim + nb + i) * Kdim + kb + tx;
        Tw[o] = __float2half_rn(v);
    }
}

// ---------------- PLE + embedding + ReLU -> flat fp16, + fused gate partials ----------------
// grid (NF, B/64), block 256. thread = (4 rows) x (4 d-cols).
__global__ __launch_bounds__(256) void k_ple(
    const float* __restrict__ x, const float* __restrict__ plew,
    const float* __restrict__ pleb, const float* __restrict__ embW,
    const float* __restrict__ embb, const float* __restrict__ gW)
{
    int n = blockIdx.x;
    int b0 = blockIdx.y * 64;
    int tid = threadIdx.x;

    __shared__ float Wsh[KB * DE];      // 12 KB
    __shared__ float wsh[KB], bsh[KB], ebias[DE];
    __shared__ float xs[64];
    __shared__ float enc_sh[64][KB];    // 12 KB
    __shared__ float gwsh[DE][E];       // 2 KB  gW slice for feature n

    for (int i = tid; i < KB * DE; i += 256) Wsh[i] = embW[(size_t)n * KB * DE + i];
    if (tid < KB) { wsh[tid] = plew[n * KB + tid]; bsh[tid] = pleb[n * KB + tid]; }
    if (tid < DE) ebias[tid] = embb[n * DE + tid];
    if (tid < 64) xs[tid] = x[(b0 + tid) * NF + n];
    for (int i = tid; i < DE * E; i += 256)
        ((float*)gwsh)[i] = gW[(size_t)(n * DE) * E + i];
    __syncthreads();

    for (int idx = tid; idx < 64 * KB; idx += 256) {
        int bl = idx / KB, k = idx - bl * KB;
        float enc = bsh[k] + wsh[k] * xs[bl];
        if (k == 0)           enc = fminf(enc, 1.f);
        else if (k == KB - 1) enc = fmaxf(enc, 0.f);
        else                  enc = fminf(fmaxf(enc, 0.f), 1.f);
        enc_sh[bl][k] = enc;
    }
    __syncthreads();

    int c0 = (tid & 15) * 4;
    int r0 = (tid >> 4) * 4;
    int lane = tid & 31;

    float acc[4][4];
    #pragma unroll
    for (int r = 0; r < 4; r++)
        #pragma unroll
        for (int j = 0; j < 4; j++) acc[r][j] = ebias[c0 + j];

    #pragma unroll
    for (int k4 = 0; k4 < KB; k4 += 4) {
        float4 wv[4];
        #pragma unroll
        for (int kk = 0; kk < 4; kk++)
            wv[kk] = *(const float4*)&Wsh[(k4 + kk) * DE + c0];
        #pragma unroll
        for (int r = 0; r < 4; r++) {
            float4 ev = *(const float4*)&enc_sh[r0 + r][k4];
            const float* w0 = (const float*)&wv[0];
            const float* w1 = (const float*)&wv[1];
            const float* w2 = (const float*)&wv[2];
            const float* w3 = (const float*)&wv[3];
            #pragma unroll
            for (int j = 0; j < 4; j++)
                acc[r][j] += ev.x * w0[j] + ev.y * w1[j] + ev.z * w2[j] + ev.w * w3[j];
        }
    }

    // ReLU + store fp16 flat
    float v[4][4];
    #pragma unroll
    for (int r = 0; r < 4; r++) {
        int b = b0 + r0 + r;
        #pragma unroll
        for (int j = 0; j < 4; j++) v[r][j] = fmaxf(acc[r][j], 0.f);
        size_t idx = (size_t)b * F + n * DE + c0;
        *(uint2*)&g_flat[idx] = make_uint2(pack_h2(v[r][0], v[r][1]),
                                           pack_h2(v[r][2], v[r][3]));
    }

    // gate partials: j outer (hoists gwsh loads out of r/e loops; same per-(r,e) order)
    float p[4][E];
    #pragma unroll
    for (int r = 0; r < 4; r++)
        #pragma unroll
        for (int e = 0; e < E; e++) p[r][e] = 0.f;

    #pragma unroll
    for (int j = 0; j < 4; j++) {
        float gw[E];
        #pragma unroll
        for (int e = 0; e < E; e++) gw[e] = gwsh[c0 + j][e];
        #pragma unroll
        for (int r = 0; r < 4; r++)
            #pragma unroll
            for (int e = 0; e < E; e++)
                p[r][e] += v[r][j] * gw[e];
    }

    // width-16 xor-shuffle reduction across the 16 col-thread groups (fixed order)
    #pragma unroll
    for (int off = 8; off; off >>= 1)
        #pragma unroll
        for (int r = 0; r < 4; r++)
            #pragma unroll
            for (int e = 0; e < E; e++)
                p[r][e] += __shfl_xor_sync(0xffffffffu, p[r][e], off);

    if ((lane & 15) == 0) {
        #pragma unroll
        for (int r = 0; r < 4; r++) {
            int b = b0 + r0 + r;
            float* dst = &g_pl[((size_t)b * NF + n) * E];
            *(float4*)&dst[0] = make_float4(p[r][0], p[r][1], p[r][2], p[r][3]);
            *(float4*)&dst[4] = make_float4(p[r][4], p[r][5], p[r][6], p[r][7]);
        }
    }
}

// ---------------- gate reduce + top-2 (deterministic fixed-order sums) ----------------
// grid B/32, block 256: thread = (row 0..31, expert 0..7)
__global__ __launch_bounds__(256) void k_gate2(const float* __restrict__ gb)
{
    int b0 = blockIdx.x * 32;
    int tid = threadIdx.x;
    int r = tid >> 3;
    int e = tid & 7;
    int b = b0 + r;

    const float* p = &g_pl[((size_t)b * NF) * E + e];
    float s = 0.f;
    #pragma unroll
    for (int n = 0; n < NF; n++) s += p[n * E];
    s += gb[e];

    __shared__ float sl[32][E];
    sl[r][e] = s;
    __syncthreads();

    if (e == 0) {
        int i0 = 0;
        #pragma unroll
        for (int q = 1; q < E; q++) if (sl[r][q] > sl[r][i0]) i0 = q;
        int i1 = (i0 == 0) ? 1 : 0;
        #pragma unroll
        for (int q = 0; q < E; q++) if (q != i0 && sl[r][q] > sl[r][i1]) i1 = q;
        float e1 = __expf(sl[r][i1] - sl[r][i0]);
        float inv = 1.f / (1.f + e1);
        g_te[b * 2 + 0] = i0;  g_tg[b * 2 + 0] = inv;
        g_te[b * 2 + 1] = i1;  g_tg[b * 2 + 1] = e1 * inv;
        atomicAdd(&g_count[i0], 1);
        atomicAdd(&g_count[i1], 1);
    }
}

__global__ void k_scan() {
    if (threadIdx.x == 0) {
        int s = 0;
        for (int e = 0; e < E; e++) { g_base[e] = s; g_cursor[e] = s; s += g_count[e]; }
    }
}

__global__ __launch_bounds__(256) void k_assign() {
    int b = blockIdx.x * 256 + threadIdx.x;
    if (b >= B) return;
    #pragma unroll
    for (int j = 0; j < 2; j++) {
        int e = g_te[b * 2 + j];
        int slot = atomicAdd(&g_cursor[e], 1);
        g_rows[slot]  = b;
        g_gates[slot] = g_tg[b * 2 + j];
        g_pair[b * 2 + j] = slot;
    }
}

// ---------------- fp16 register-MMA expert GEMM (single A plane) ----------------
// CTA tile 128x128, 8 warps (2m x 4n), warp tile 64x32, k-tile 64, 3-stage cp.async,
// 32KB/stage -> 96KB -> 2 CTAs/SM.
#define GBM 128
#define GKT 64
#define STG_BYTES 32768u
#define OFF_B_C   16384u

template<int KTOT, int NTOT, int MODE>
__global__ __launch_bounds__(256, 2) void k_mma_gemm(
    const __half* __restrict__ A, const __half* __restrict__ Wt,
    const float* __restrict__ bias)
{
    int e = blockIdx.z;
    int cnt = g_count[e];
    int m0 = blockIdx.y * GBM;
    if (m0 >= cnt) return;
    int base = g_base[e];
    int n0 = blockIdx.x * 128;

    extern __shared__ char smem[];
    uint32_t sb = smem_to_u32(smem);
    __shared__ int rows_s[GBM];

    int tid = threadIdx.x;
    int lane = tid & 31, wid = tid >> 5;

    if (MODE == 0 && tid < GBM) {
        int m = m0 + tid;
        rows_s[tid] = (m < cnt) ? g_rows[base + m] : -1;
    }
    __syncthreads();

    // -------- loader setup: thread -> (row 0..127, 4 chunks of 16B) --------
    int lrow = tid >> 1;
    int lcb  = (tid & 1) * 4;
    const __half* arow;
    int abytes;
    if (MODE == 0) {
        int gr = rows_s[lrow];
        abytes = (gr >= 0) ? 16 : 0;
        int r = (gr >= 0) ? gr : 0;
        arow = A + (size_t)r * KTOT;
    } else {
        int m = m0 + lrow;
        abytes = (m < cnt) ? 16 : 0;
        size_t r = (m < cnt) ? (size_t)(base + m) : 0;
        arow = A + r * KTOT;
    }
    const __half* brow = Wt + ((size_t)e * NTOT + n0 + lrow) * KTOT;
    uint32_t lsw = (uint32_t)((lrow & 7) << 4);
    uint32_t lbase = (uint32_t)(lrow * 128);

    // -------- mma setup --------
    int wm = wid >> 2;            // 0..1
    int wn = wid & 3;             // 0..3
    int a_row = wm * 64 + (lane & 15);
    uint32_t a_c  = (uint32_t)((lane >> 4) * 16);
    uint32_t asw  = (uint32_t)((a_row & 7) << 4);
    int b_row = wn * 32 + (lane & 7) + ((lane >> 4) << 3);
    uint32_t b_c  = (uint32_t)(((lane >> 3) & 1) * 16);
    uint32_t bsw  = (uint32_t)((b_row & 7) << 4);

    float acc[4][4][4];
    #pragma unroll
    for (int i = 0; i < 4; i++)
        #pragma unroll
        for (int j = 0; j < 4; j++)
            #pragma unroll
            for (int q = 0; q < 4; q++) acc[i][j][q] = 0.f;

    const int NT = KTOT / GKT;

    #define LOAD_STAGE(stg_, kt_) do {                                           \
        uint32_t s_ = sb + (uint32_t)(stg_) * STG_BYTES;                          \
        int k0_ = (kt_) * GKT;                                                    \
        _Pragma("unroll")                                                         \
        for (int q = 0; q < 4; q++) {                                             \
            int ch = lcb + q;                                                     \
            uint32_t so = lbase + (((uint32_t)(ch * 16)) ^ lsw);                  \
            cp_async16(s_ + so, arow + k0_ + ch * 8, abytes);                     \
            cp_async16(s_ + OFF_B_C + so, brow + k0_ + ch * 8, 16);               \
        }                                                                         \
        CP_COMMIT();                                                              \
    } while (0)

    // prime stages 0,1
    LOAD_STAGE(0, 0);
    if (NT > 1) LOAD_STAGE(1, 1);

    int stg = 0;
    for (int kt = 0; kt < NT; kt++) {
        if (kt + 2 < NT) {
            int ns = stg + 2; if (ns >= 3) ns -= 3;
            LOAD_STAGE(ns, kt + 2);
            CP_WAIT(2);
        } else if (kt + 1 < NT) {
            CP_WAIT(1);
        } else {
            CP_WAIT(0);
        }
        __syncthreads();

        uint32_t s0 = sb + (uint32_t)stg * STG_BYTES;
        #pragma unroll
        for (int kk = 0; kk < 4; kk++) {
            uint32_t ah[4][4], bh[2][4];
            #pragma unroll
            for (int i = 0; i < 4; i++) {
                uint32_t ro = (uint32_t)((a_row + i * 16) * 128);
                ldsm_x4(ah[i], s0 + ro + ((a_c + kk * 32) ^ asw));
            }
            #pragma unroll
            for (int p = 0; p < 2; p++) {
                uint32_t ro = (uint32_t)((b_row + p * 16) * 128);
                ldsm_x4(bh[p], s0 + OFF_B_C + ro + ((b_c + kk * 32) ^ bsw));
            }
            #pragma unroll
            for (int i = 0; i < 4; i++)
                #pragma unroll
                for (int j = 0; j < 4; j++) {
                    const uint32_t* bj = &bh[j >> 1][(j & 1) * 2];
                    mma_f16(acc[i][j], ah[i], bj);
                }
        }
        __syncthreads();
        stg = (stg == 2) ? 0 : stg + 1;
    }
    #undef LOAD_STAGE

    // -------- epilogue --------
    int g = lane >> 2;
    int cg = (lane & 3) * 2;
    #pragma unroll
    for (int i = 0; i < 4; i++) {
        #pragma unroll
        for (int half = 0; half < 2; half++) {
            int m = m0 + wm * 64 + i * 16 + g + half * 8;
            if (m < cnt) {
                int slot = base + m;
                float gate = (MODE == 1) ? g_gates[slot] : 0.f;
                #pragma unroll
                for (int j = 0; j < 4; j++) {
                    int col = n0 + wn * 32 + j * 8 + cg;
                    float bv0 = bias[(size_t)e * NTOT + col];
                    float bv1 = bias[(size_t)e * NTOT + col + 1];
                    float v0 = acc[i][j][half * 2 + 0] + bv0;
                    float v1 = acc[i][j][half * 2 + 1] + bv1;
                    if (MODE == 0) {
                        v0 = fmaxf(v0, 0.f); v1 = fmaxf(v1, 0.f);
                        *(uint32_t*)&g_h[(size_t)slot * H + col] = pack_h2(v0, v1);
                    } else {
                        float2 v = make_float2(gate * v0, gate * v1);
                        *(float2*)&g_eo[(size_t)slot * O + col] = v;
                    }
                }
            }
        }
    }
}

// ---------------- task towers ----------------
// grid (B/16, T): each block does one task for 16 rows
__global__ __launch_bounds__(256) void k_tower(
    const float* __restrict__ tw1, const float* __restrict__ tb1,
    const float* __restrict__ tw2, const float* __restrict__ tb2,
    float* __restrict__ out)
{
    int b0 = blockIdx.x * 16;
    int t = blockIdx.y;
    int tid = threadIdx.x;
    int lane = tid & 31, wid = tid >> 5;

    __shared__ float moe_sh[16][O];
    __shared__ float sred[16][8];

    #pragma unroll
    for (int r = 0; r < 16; r++) {
        int b = b0 + r;
        int s0 = g_pair[b * 2 + 0], s1 = g_pair[b * 2 + 1];
        for (int c = tid; c < O; c += 256)
            moe_sh[r][c] = g_eo[(size_t)s0 * O + c] + g_eo[(size_t)s1 * O + c];
    }
    __syncthreads();

    float acc[16];
    #pragma unroll
    for (int r = 0; r < 16; r++) acc[r] = 0.f;

    const float* w1 = tw1 + (size_t)t * O * TH + tid;
    for (int o = 0; o < O; o++) {
        float w = w1[(size_t)o * TH];
        #pragma unroll
        for (int r = 0; r < 16; r++) acc[r] += moe_sh[r][o] * w;
    }
    float bb = tb1[t * TH + tid];
    float w2 = tw2[t * TH + tid];

    #pragma unroll
    for (int r = 0; r < 16; r++) {
        float th = fmaxf(acc[r] + bb, 0.f);
        float v = th * w2;
        for (int off = 16; off; off >>= 1)
            v += __shfl_down_sync(0xffffffffu, v, off);
        if (lane == 0) sred[r][wid] = v;
    }
    __syncthreads();
    if (tid < 16) {
        float s = 0.f;
        #pragma unroll
        for (int w = 0; w < 8; w++) s += sred[tid][w];
        out[(b0 + tid) * T + t] = s + tb2[t];
    }
}

// ---------------- launch ----------------
extern "C" void kernel_launch(void* const* d_in, const int* in_sizes, int n_in,
                              void* d_out, int out_size)
{
    const float* x     = (const float*)d_in[0];
    const float* plew  = (const float*)d_in[1];
    const float* pleb  = (const float*)d_in[2];
    const float* embW  = (const float*)d_in[3];
    const float* embb  = (const float*)d_in[4];
    const float* gW    = (const float*)d_in[5];
    const float* gb    = (const float*)d_in[6];
    const float* eW1   = (const float*)d_in[7];
    const float* eb1   = (const float*)d_in[8];
    const float* eW2   = (const float*)d_in[9];
    const float* eb2   = (const float*)d_in[10];
    const float* tw1   = (const float*)d_in[11];
    const float* tb1   = (const float*)d_in[12];
    const float* tw2   = (const float*)d_in[13];
    const float* tb2   = (const float*)d_in[14];
    float* out = (float*)d_out;

    const int SMEM_BYTES = 3 * (int)STG_BYTES;   // 98304
    static cudaStream_t s2 = nullptr;
    static cudaEvent_t ev_fork = nullptr, ev_join = nullptr;
    if (!s2) {
        cudaFuncSetAttribute(k_mma_gemm<F, H, 0>, cudaFuncAttributeMaxDynamicSharedMemorySize, SMEM_BYTES);
        cudaFuncSetAttribute(k_mma_gemm<H, O, 1>, cudaFuncAttributeMaxDynamicSharedMemorySize, SMEM_BYTES);
        cudaStreamCreateWithFlags(&s2, cudaStreamNonBlocking);
        cudaEventCreateWithFlags(&ev_fork, cudaEventDisableTiming);
        cudaEventCreateWithFlags(&ev_join, cudaEventDisableTiming);
    }

    __half *w1t, *w2t, *flat, *h_buf;
    cudaGetSymbolAddress((void**)&w1t, g_w1t);
    cudaGetSymbolAddress((void**)&w2t, g_w2t);
    cudaGetSymbolAddress((void**)&flat, g_flat);
    cudaGetSymbolAddress((void**)&h_buf, g_h);

    k_init<<<1, 32>>>();

    // fork: weight convert/transpose runs concurrently with PLE->gate->assign
    cudaEventRecord(ev_fork, 0);
    cudaStreamWaitEvent(s2, ev_fork, 0);
    k_wsplit<<<dim3(H / 32, F / 32, E), dim3(32, 8), 0, s2>>>(eW1, w1t, F, H);
    k_wsplit<<<dim3(O / 32, H / 32, E), dim3(32, 8), 0, s2>>>(eW2, w2t, H, O);
    cudaEventRecord(ev_join, s2);

    k_ple<<<dim3(NF, B / 64), 256>>>(x, plew, pleb, embW, embb, gW);
    k_gate2<<<B / 32, 256>>>(gb);
    k_scan<<<1, 32>>>();
    k_assign<<<(B + 255) / 256, 256>>>();

    // join before GEMM1 consumes weights
    cudaStreamWaitEvent(0, ev_join, 0);

    k_mma_gemm<F, H, 0><<<dim3(H / 128, B / GBM, E), 256, SMEM_BYTES>>>(flat, w1t, eb1);
    k_mma_gemm<H, O, 1><<<dim3(O / 128, B / GBM, E), 256, SMEM_BYTES>>>(h_buf, w2t, eb2);

    k_tower<<<dim3(B / 16, T), 256>>>(tw1, tb1, tw2, tb2, out);
}

// round 15
// speedup vs baseline: 2.4680x; 1.0573x over previous
#include <cuda_runtime.h>
#include <cuda_fp16.h>
#include <cstdint>
#include <math.h>

// Problem constants
#define B    4096
#define NF   64
#define KB   48
#define DE   64
#define F    4096
#define E    8
#define H    1024
#define O    512
#define T    2
#define TH   256

// ---------------- low-level helpers (plain sm_80+ PTX only) ----------------
__device__ __forceinline__ uint32_t smem_to_u32(const void* p) {
    uint32_t a;
    asm("{ .reg .u64 t; cvta.to.shared.u64 t, %1; cvt.u32.u64 %0, t; }" : "=r"(a) : "l"(p));
    return a;
}
__device__ __forceinline__ void cp_async16(uint32_t dst, const void* src, int src_bytes) {
    asm volatile("cp.async.cg.shared.global [%0], [%1], 16, %2;"
                 :: "r"(dst), "l"(src), "r"(src_bytes) : "memory");
}
#define CP_COMMIT() asm volatile("cp.async.commit_group;" ::: "memory")
#define CP_WAIT(n)  asm volatile("cp.async.wait_group %0;" :: "n"(n) : "memory")

__device__ __forceinline__ void ldsm_x4(uint32_t* r, uint32_t addr) {
    asm volatile("ldmatrix.sync.aligned.m8n8.x4.shared.b16 {%0,%1,%2,%3}, [%4];"
                 : "=r"(r[0]), "=r"(r[1]), "=r"(r[2]), "=r"(r[3]) : "r"(addr));
}
__device__ __forceinline__ void mma_f16(float* c, const uint32_t* a, const uint32_t* b) {
    asm volatile(
        "mma.sync.aligned.m16n8k16.row.col.f32.f16.f16.f32 "
        "{%0,%1,%2,%3}, {%4,%5,%6,%7}, {%8,%9}, {%0,%1,%2,%3};"
        : "+f"(c[0]), "+f"(c[1]), "+f"(c[2]), "+f"(c[3])
        : "r"(a[0]), "r"(a[1]), "r"(a[2]), "r"(a[3]), "r"(b[0]), "r"(b[1]));
}
__device__ __forceinline__ uint32_t pack_h2(float v0, float v1) {
    __half2 h = __halves2half2(__float2half_rn(v0), __float2half_rn(v1));
    return *(uint32_t*)&h;
}

// ---------------- device scratch ----------------
__device__ __half g_flat[(size_t)B * F];        // 32 MB (fp16 activations)
__device__ float  g_pl[(size_t)B * NF * E];     // 8 MB  per-(row,feature) gate partials
__device__ float  g_cw[(size_t)NF * KB * DE];   // 786 KB prefix sums (bias folded)
__device__ __half g_w1t[(size_t)E * H * F];     // 64 MB  [e][h][f]
__device__ __half g_w2t[(size_t)E * O * H];     // 8 MB   [e][o][h]
__device__ __half g_h[(size_t)2 * B * H];       // 16 MB
__device__ float g_eo[(size_t)2 * B * O];       // 16 MB
__device__ int   g_count[E];
__device__ int   g_base[E];
__device__ int   g_cursor[E];
__device__ int   g_te[B * 2];
__device__ float g_tg[B * 2];
__device__ int   g_rows[2 * B];
__device__ float g_gates[2 * B];
__device__ int   g_pair[B * 2];

// ---------------- init ----------------
__global__ void k_init() {
    if (threadIdx.x < E) g_count[threadIdx.x] = 0;
}

// ---------------- prefix-sum embW: CW[n][j][d] = embb[n][d] + sum_{k<j} embW[n][k][d] ----------------
// grid NF, block 64
__global__ void k_cumw(const float* __restrict__ embW, const float* __restrict__ embb)
{
    int n = blockIdx.x;
    int d = threadIdx.x;
    float s = embb[n * DE + d];
    #pragma unroll 4
    for (int k = 0; k < KB; k++) {
        g_cw[((size_t)n * KB + k) * DE + d] = s;
        s += embW[((size_t)n * KB + k) * DE + d];
    }
}

// ---------------- weight transpose: W[e][k][n] -> T[e][n][k] fp16 ----------------
__global__ __launch_bounds__(256) void k_wsplit(
    const float* __restrict__ W, __half* __restrict__ Tw, int Kdim, int Ndim)
{
    __shared__ float t[32][33];
    int e = blockIdx.z;
    int kb = blockIdx.y * 32;
    int nb = blockIdx.x * 32;
    int tx = threadIdx.x, ty = threadIdx.y;
    const float* Wb = W + (size_t)e * Kdim * Ndim;
    #pragma unroll
    for (int i = ty; i < 32; i += 8)
        t[i][tx] = Wb[(size_t)(kb + i) * Ndim + nb + tx];
    __syncthreads();
    #pragma unroll
    for (int i = ty; i < 32; i += 8) {
        float v = t[tx][i];
        size_t o = ((size_t)e * Ndim + nb + i) * Kdim + kb + tx;
        Tw[o] = __float2half_rn(v);
    }
}

// ---------------- PLE via prefix-sum + ReLU -> flat fp16, + fused gate partials ----------------
// grid (NF, B/64), block 256. Phase A: 64 threads find (bin j, frac) per row.
// Phase B: thread = (4 rows) x (4 d-cols): emb = CW[j] + frac*W[j].
__global__ __launch_bounds__(256) void k_ple(
    const float* __restrict__ x, const float* __restrict__ plew,
    const float* __restrict__ pleb, const float* __restrict__ embW,
    const float* __restrict__ gW)
{
    int n = blockIdx.x;
    int b0 = blockIdx.y * 64;
    int tid = threadIdx.x;

    __shared__ float wsh[KB], bsh[KB];
    __shared__ int   jr[64];
    __shared__ float fr[64];
    __shared__ float gwsh[DE][E];       // 2 KB gW slice for feature n

    if (tid < KB) { wsh[tid] = plew[n * KB + tid]; bsh[tid] = pleb[n * KB + tid]; }
    for (int i = tid; i < DE * E; i += 256)
        ((float*)gwsh)[i] = gW[(size_t)(n * DE) * E + i];
    __syncthreads();

    // Phase A: per-row bin index + fraction (enc monotone decreasing in k)
    if (tid < 64) {
        float xv = x[(b0 + tid) * NF + n];
        int j = 0;
        #pragma unroll
        for (int k = 0; k < KB; k++) {
            float enc = bsh[k] + wsh[k] * xv;
            j += (enc >= 1.f) ? 1 : 0;
        }
        if (j > KB - 1) j = KB - 1;
        float enc = bsh[j] + wsh[j] * xv;
        jr[tid] = j;
        fr[tid] = fmaxf(fminf(enc, 1.f), 0.f);
    }
    __syncthreads();

    int c0 = (tid & 15) * 4;
    int r0 = (tid >> 4) * 4;
    int lane = tid & 31;

    // Phase B: emb = CW[j] + frac*W[j]; ReLU; fp16 store
    float v[4][4];
    #pragma unroll
    for (int r = 0; r < 4; r++) {
        int row = r0 + r;
        int j = jr[row];
        float f = fr[row];
        size_t base = ((size_t)n * KB + j) * DE + c0;
        float4 cw = *(const float4*)&g_cw[base];
        float4 w  = *(const float4*)&embW[base];
        v[r][0] = fmaxf(cw.x + f * w.x, 0.f);
        v[r][1] = fmaxf(cw.y + f * w.y, 0.f);
        v[r][2] = fmaxf(cw.z + f * w.z, 0.f);
        v[r][3] = fmaxf(cw.w + f * w.w, 0.f);
        size_t idx = (size_t)(b0 + row) * F + n * DE + c0;
        *(uint2*)&g_flat[idx] = make_uint2(pack_h2(v[r][0], v[r][1]),
                                           pack_h2(v[r][2], v[r][3]));
    }

    // gate partials: j outer (register-resident gw row)
    float p[4][E];
    #pragma unroll
    for (int r = 0; r < 4; r++)
        #pragma unroll
        for (int e = 0; e < E; e++) p[r][e] = 0.f;

    #pragma unroll
    for (int j = 0; j < 4; j++) {
        float gw[E];
        #pragma unroll
        for (int e = 0; e < E; e++) gw[e] = gwsh[c0 + j][e];
        #pragma unroll
        for (int r = 0; r < 4; r++)
            #pragma unroll
            for (int e = 0; e < E; e++)
                p[r][e] += v[r][j] * gw[e];
    }

    // width-16 xor-shuffle reduction (fixed order)
    #pragma unroll
    for (int off = 8; off; off >>= 1)
        #pragma unroll
        for (int r = 0; r < 4; r++)
            #pragma unroll
            for (int e = 0; e < E; e++)
                p[r][e] += __shfl_xor_sync(0xffffffffu, p[r][e], off);

    if ((lane & 15) == 0) {
        #pragma unroll
        for (int r = 0; r < 4; r++) {
            int b = b0 + r0 + r;
            float* dst = &g_pl[((size_t)b * NF + n) * E];
            *(float4*)&dst[0] = make_float4(p[r][0], p[r][1], p[r][2], p[r][3]);
            *(float4*)&dst[4] = make_float4(p[r][4], p[r][5], p[r][6], p[r][7]);
        }
    }
}

// ---------------- gate reduce + top-2 ----------------
// grid B/32, block 256: thread = (row 0..31, expert 0..7)
__global__ __launch_bounds__(256) void k_gate2(const float* __restrict__ gb)
{
    int b0 = blockIdx.x * 32;
    int tid = threadIdx.x;
    int r = tid >> 3;
    int e = tid & 7;
    int b = b0 + r;

    const float* p = &g_pl[((size_t)b * NF) * E + e];
    float s = 0.f;
    #pragma unroll
    for (int n = 0; n < NF; n++) s += p[n * E];
    s += gb[e];

    __shared__ float sl[32][E];
    sl[r][e] = s;
    __syncthreads();

    if (e == 0) {
        int i0 = 0;
        #pragma unroll
        for (int q = 1; q < E; q++) if (sl[r][q] > sl[r][i0]) i0 = q;
        int i1 = (i0 == 0) ? 1 : 0;
        #pragma unroll
        for (int q = 0; q < E; q++) if (q != i0 && sl[r][q] > sl[r][i1]) i1 = q;
        float e1 = __expf(sl[r][i1] - sl[r][i0]);
        float inv = 1.f / (1.f + e1);
        g_te[b * 2 + 0] = i0;  g_tg[b * 2 + 0] = inv;
        g_te[b * 2 + 1] = i1;  g_tg[b * 2 + 1] = e1 * inv;
        atomicAdd(&g_count[i0], 1);
        atomicAdd(&g_count[i1], 1);
    }
}

__global__ void k_scan() {
    if (threadIdx.x == 0) {
        int s = 0;
        for (int e = 0; e < E; e++) { g_base[e] = s; g_cursor[e] = s; s += g_count[e]; }
    }
}

__global__ __launch_bounds__(256) void k_assign() {
    int b = blockIdx.x * 256 + threadIdx.x;
    if (b >= B) return;
    #pragma unroll
    for (int j = 0; j < 2; j++) {
        int e = g_te[b * 2 + j];
        int slot = atomicAdd(&g_cursor[e], 1);
        g_rows[slot]  = b;
        g_gates[slot] = g_tg[b * 2 + j];
        g_pair[b * 2 + j] = slot;
    }
}

// ---------------- fp16 register-MMA expert GEMM (single A plane) ----------------
// CTA tile 128x128, 8 warps (2m x 4n), warp tile 64x32, k-tile 64, 3-stage cp.async,
// 32KB/stage -> 96KB -> 2 CTAs/SM.
#define GBM 128
#define GKT 64
#define STG_BYTES 32768u
#define OFF_B_C   16384u

template<int KTOT, int NTOT, int MODE>
__global__ __launch_bounds__(256, 2) void k_mma_gemm(
    const __half* __restrict__ A, const __half* __restrict__ Wt,
    const float* __restrict__ bias)
{
    int e = blockIdx.z;
    int cnt = g_count[e];
    int m0 = blockIdx.y * GBM;
    if (m0 >= cnt) return;
    int base = g_base[e];
    int n0 = blockIdx.x * 128;

    extern __shared__ char smem[];
    uint32_t sb = smem_to_u32(smem);
    __shared__ int rows_s[GBM];

    int tid = threadIdx.x;
    int lane = tid & 31, wid = tid >> 5;

    if (MODE == 0 && tid < GBM) {
        int m = m0 + tid;
        rows_s[tid] = (m < cnt) ? g_rows[base + m] : -1;
    }
    __syncthreads();

    // -------- loader setup --------
    int lrow = tid >> 1;
    int lcb  = (tid & 1) * 4;
    const __half* arow;
    int abytes;
    if (MODE == 0) {
        int gr = rows_s[lrow];
        abytes = (gr >= 0) ? 16 : 0;
        int r = (gr >= 0) ? gr : 0;
        arow = A + (size_t)r * KTOT;
    } else {
        int m = m0 + lrow;
        abytes = (m < cnt) ? 16 : 0;
        size_t r = (m < cnt) ? (size_t)(base + m) : 0;
        arow = A + r * KTOT;
    }
    const __half* brow = Wt + ((size_t)e * NTOT + n0 + lrow) * KTOT;
    uint32_t lsw = (uint32_t)((lrow & 7) << 4);
    uint32_t lbase = (uint32_t)(lrow * 128);

    // -------- mma setup --------
    int wm = wid >> 2;
    int wn = wid & 3;
    int a_row = wm * 64 + (lane & 15);
    uint32_t a_c  = (uint32_t)((lane >> 4) * 16);
    uint32_t asw  = (uint32_t)((a_row & 7) << 4);
    int b_row = wn * 32 + (lane & 7) + ((lane >> 4) << 3);
    uint32_t b_c  = (uint32_t)(((lane >> 3) & 1) * 16);
    uint32_t bsw  = (uint32_t)((b_row & 7) << 4);

    float acc[4][4][4];
    #pragma unroll
    for (int i = 0; i < 4; i++)
        #pragma unroll
        for (int j = 0; j < 4; j++)
            #pragma unroll
            for (int q = 0; q < 4; q++) acc[i][j][q] = 0.f;

    const int NT = KTOT / GKT;

    #define LOAD_STAGE(stg_, kt_) do {                                           \
        uint32_t s_ = sb + (uint32_t)(stg_) * STG_BYTES;                          \
        int k0_ = (kt_) * GKT;                                                    \
        _Pragma("unroll")                                                         \
        for (int q = 0; q < 4; q++) {                                             \
            int ch = lcb + q;                                                     \
            uint32_t so = lbase + (((uint32_t)(ch * 16)) ^ lsw);                  \
            cp_async16(s_ + so, arow + k0_ + ch * 8, abytes);                     \
            cp_async16(s_ + OFF_B_C + so, brow + k0_ + ch * 8, 16);               \
        }                                                                         \
        CP_COMMIT();                                                              \
    } while (0)

    LOAD_STAGE(0, 0);
    if (NT > 1) LOAD_STAGE(1, 1);

    int stg = 0;
    for (int kt = 0; kt < NT; kt++) {
        if (kt + 2 < NT) {
            int ns = stg + 2; if (ns >= 3) ns -= 3;
            LOAD_STAGE(ns, kt + 2);
            CP_WAIT(2);
        } else if (kt + 1 < NT) {
            CP_WAIT(1);
        } else {
            CP_WAIT(0);
        }
        __syncthreads();

        uint32_t s0 = sb + (uint32_t)stg * STG_BYTES;
        #pragma unroll
        for (int kk = 0; kk < 4; kk++) {
            uint32_t ah[4][4], bh[2][4];
            #pragma unroll
            for (int i = 0; i < 4; i++) {
                uint32_t ro = (uint32_t)((a_row + i * 16) * 128);
                ldsm_x4(ah[i], s0 + ro + ((a_c + kk * 32) ^ asw));
            }
            #pragma unroll
            for (int p = 0; p < 2; p++) {
                uint32_t ro = (uint32_t)((b_row + p * 16) * 128);
                ldsm_x4(bh[p], s0 + OFF_B_C + ro + ((b_c + kk * 32) ^ bsw));
            }
            #pragma unroll
            for (int i = 0; i < 4; i++)
                #pragma unroll
                for (int j = 0; j < 4; j++) {
                    const uint32_t* bj = &bh[j >> 1][(j & 1) * 2];
                    mma_f16(acc[i][j], ah[i], bj);
                }
        }
        __syncthreads();
        stg = (stg == 2) ? 0 : stg + 1;
    }
    #undef LOAD_STAGE

    // -------- epilogue --------
    int g = lane >> 2;
    int cg = (lane & 3) * 2;
    #pragma unroll
    for (int i = 0; i < 4; i++) {
        #pragma unroll
        for (int half = 0; half < 2; half++) {
            int m = m0 + wm * 64 + i * 16 + g + half * 8;
            if (m < cnt) {
                int slot = base + m;
                float gate = (MODE == 1) ? g_gates[slot] : 0.f;
                #pragma unroll
                for (int j = 0; j < 4; j++) {
                    int col = n0 + wn * 32 + j * 8 + cg;
                    float bv0 = bias[(size_t)e * NTOT + col];
                    float bv1 = bias[(size_t)e * NTOT + col + 1];
                    float v0 = acc[i][j][half * 2 + 0] + bv0;
                    float v1 = acc[i][j][half * 2 + 1] + bv1;
                    if (MODE == 0) {
                        v0 = fmaxf(v0, 0.f); v1 = fmaxf(v1, 0.f);
                        *(uint32_t*)&g_h[(size_t)slot * H + col] = pack_h2(v0, v1);
                    } else {
                        float2 v = make_float2(gate * v0, gate * v1);
                        *(float2*)&g_eo[(size_t)slot * O + col] = v;
                    }
                }
            }
        }
    }
}

// ---------------- task towers ----------------
// grid (B/16, T): each block does one task for 16 rows
__global__ __launch_bounds__(256) void k_tower(
    const float* __restrict__ tw1, const float* __restrict__ tb1,
    const float* __restrict__ tw2, const float* __restrict__ tb2,
    float* __restrict__ out)
{
    int b0 = blockIdx.x * 16;
    int t = blockIdx.y;
    int tid = threadIdx.x;
    int lane = tid & 31, wid = tid >> 5;

    __shared__ float moe_sh[16][O];
    __shared__ float sred[16][8];

    #pragma unroll
    for (int r = 0; r < 16; r++) {
        int b = b0 + r;
        int s0 = g_pair[b * 2 + 0], s1 = g_pair[b * 2 + 1];
        for (int c = tid; c < O; c += 256)
            moe_sh[r][c] = g_eo[(size_t)s0 * O + c] + g_eo[(size_t)s1 * O + c];
    }
    __syncthreads();

    float acc[16];
    #pragma unroll
    for (int r = 0; r < 16; r++) acc[r] = 0.f;

    const float* w1 = tw1 + (size_t)t * O * TH + tid;
    for (int o = 0; o < O; o++) {
        float w = w1[(size_t)o * TH];
        #pragma unroll
        for (int r = 0; r < 16; r++) acc[r] += moe_sh[r][o] * w;
    }
    float bb = tb1[t * TH + tid];
    float w2 = tw2[t * TH + tid];

    #pragma unroll
    for (int r = 0; r < 16; r++) {
        float th = fmaxf(acc[r] + bb, 0.f);
        float v = th * w2;
        for (int off = 16; off; off >>= 1)
            v += __shfl_down_sync(0xffffffffu, v, off);
        if (lane == 0) sred[r][wid] = v;
    }
    __syncthreads();
    if (tid < 16) {
        float s = 0.f;
        #pragma unroll
        for (int w = 0; w < 8; w++) s += sred[tid][w];
        out[(b0 + tid) * T + t] = s + tb2[t];
    }
}

// ---------------- launch ----------------
extern "C" void kernel_launch(void* const* d_in, const int* in_sizes, int n_in,
                              void* d_out, int out_size)
{
    const float* x     = (const float*)d_in[0];
    const float* plew  = (const float*)d_in[1];
    const float* pleb  = (const float*)d_in[2];
    const float* embW  = (const float*)d_in[3];
    const float* embb  = (const float*)d_in[4];
    const float* gW    = (const float*)d_in[5];
    const float* gb    = (const float*)d_in[6];
    const float* eW1   = (const float*)d_in[7];
    const float* eb1   = (const float*)d_in[8];
    const float* eW2   = (const float*)d_in[9];
    const float* eb2   = (const float*)d_in[10];
    const float* tw1   = (const float*)d_in[11];
    const float* tb1   = (const float*)d_in[12];
    const float* tw2   = (const float*)d_in[13];
    const float* tb2   = (const float*)d_in[14];
    float* out = (float*)d_out;

    const int SMEM_BYTES = 3 * (int)STG_BYTES;   // 98304
    static cudaStream_t s2 = nullptr;
    static cudaEvent_t ev_fork = nullptr, ev_join = nullptr;
    if (!s2) {
        cudaFuncSetAttribute(k_mma_gemm<F, H, 0>, cudaFuncAttributeMaxDynamicSharedMemorySize, SMEM_BYTES);
        cudaFuncSetAttribute(k_mma_gemm<H, O, 1>, cudaFuncAttributeMaxDynamicSharedMemorySize, SMEM_BYTES);
        cudaStreamCreateWithFlags(&s2, cudaStreamNonBlocking);
        cudaEventCreateWithFlags(&ev_fork, cudaEventDisableTiming);
        cudaEventCreateWithFlags(&ev_join, cudaEventDisableTiming);
    }

    __half *w1t, *w2t, *flat, *h_buf;
    cudaGetSymbolAddress((void**)&w1t, g_w1t);
    cudaGetSymbolAddress((void**)&w2t, g_w2t);
    cudaGetSymbolAddress((void**)&flat, g_flat);
    cudaGetSymbolAddress((void**)&h_buf, g_h);

    k_init<<<1, 32>>>();

    // fork: weight convert/transpose runs concurrently with PLE->gate->assign
    cudaEventRecord(ev_fork, 0);
    cudaStreamWaitEvent(s2, ev_fork, 0);
    k_wsplit<<<dim3(H / 32, F / 32, E), dim3(32, 8), 0, s2>>>(eW1, w1t, F, H);
    k_wsplit<<<dim3(O / 32, H / 32, E), dim3(32, 8), 0, s2>>>(eW2, w2t, H, O);
    cudaEventRecord(ev_join, s2);

    k_cumw<<<NF, DE>>>(embW, embb);
    k_ple<<<dim3(NF, B / 64), 256>>>(x, plew, pleb, embW, gW);
    k_gate2<<<B / 32, 256>>>(gb);
    k_scan<<<1, 32>>>();
    k_assign<<<(B + 255) / 256, 256>>>();

    // join before GEMM1 consumes weights
    cudaStreamWaitEvent(0, ev_join, 0);

    k_mma_gemm<F, H, 0><<<dim3(H / 128, B / GBM, E), 256, SMEM_BYTES>>>(flat, w1t, eb1);
    k_mma_gemm<H, O, 1><<<dim3(O / 128, B / GBM, E), 256, SMEM_BYTES>>>(h_buf, w2t, eb2);

    k_tower<<<dim3(B / 16, T), 256>>>(tw1, tb1, tw2, tb2, out);
}

// round 16
// speedup vs baseline: 2.9549x; 1.1973x over previous
#include <cuda_runtime.h>
#include <cuda_fp16.h>
#include <cstdint>
#include <math.h>

// Problem constants
#define B    4096
#define NF   64
#define KB   48
#define DE   64
#define F    4096
#define E    8
#define H    1024
#define O    512
#define T    2
#define TH   256

// ---------------- low-level helpers (plain sm_80+ PTX only) ----------------
__device__ __forceinline__ uint32_t smem_to_u32(const void* p) {
    uint32_t a;
    asm("{ .reg .u64 t; cvta.to.shared.u64 t, %1; cvt.u32.u64 %0, t; }" : "=r"(a) : "l"(p));
    return a;
}
__device__ __forceinline__ void cp_async16(uint32_t dst, const void* src, int src_bytes) {
    asm volatile("cp.async.cg.shared.global [%0], [%1], 16, %2;"
                 :: "r"(dst), "l"(src), "r"(src_bytes) : "memory");
}
#define CP_COMMIT() asm volatile("cp.async.commit_group;" ::: "memory")
#define CP_WAIT(n)  asm volatile("cp.async.wait_group %0;" :: "n"(n) : "memory")

__device__ __forceinline__ void ldsm_x4(uint32_t* r, uint32_t addr) {
    asm volatile("ldmatrix.sync.aligned.m8n8.x4.shared.b16 {%0,%1,%2,%3}, [%4];"
                 : "=r"(r[0]), "=r"(r[1]), "=r"(r[2]), "=r"(r[3]) : "r"(addr));
}
__device__ __forceinline__ void mma_f16(float* c, const uint32_t* a, const uint32_t* b) {
    asm volatile(
        "mma.sync.aligned.m16n8k16.row.col.f32.f16.f16.f32 "
        "{%0,%1,%2,%3}, {%4,%5,%6,%7}, {%8,%9}, {%0,%1,%2,%3};"
        : "+f"(c[0]), "+f"(c[1]), "+f"(c[2]), "+f"(c[3])
        : "r"(a[0]), "r"(a[1]), "r"(a[2]), "r"(a[3]), "r"(b[0]), "r"(b[1]));
}
__device__ __forceinline__ uint32_t pack_h2(float v0, float v1) {
    __half2 h = __halves2half2(__float2half_rn(v0), __float2half_rn(v1));
    return *(uint32_t*)&h;
}

// ---------------- device scratch ----------------
__device__ __half g_flat[(size_t)B * F];        // 32 MB (fp16 activations)
__device__ float  g_pl[(size_t)B * NF * E];     // 8 MB  per-(row,feature) gate partials
__device__ float  g_cw[(size_t)NF * KB * DE];   // 786 KB prefix sums (bias folded)
__device__ __half g_w1t[(size_t)E * H * F];     // 64 MB  [e][h][f]
__device__ __half g_w2t[(size_t)E * O * H];     // 8 MB   [e][o][h]
__device__ __half g_w3t[(size_t)T * TH * O];    // 512 KB [t][th][o]
__device__ __half g_h[(size_t)2 * B * H];       // 16 MB
__device__ float  g_eo[(size_t)2 * B * O];      // 16 MB
__device__ __half g_moe[(size_t)B * O];         // 4 MB
__device__ __half g_th[(size_t)T * B * TH];     // 4 MB
__device__ int   g_count[E];
__device__ int   g_base[E];
__device__ int   g_cursor[E];
__device__ int   g_te[B * 2];
__device__ float g_tg[B * 2];
__device__ int   g_rows[2 * B];
__device__ float g_gates[2 * B];
__device__ int   g_pair[B * 2];

// ---------------- init ----------------
__global__ void k_init() {
    if (threadIdx.x < E) g_count[threadIdx.x] = 0;
}

// ---------------- prefix-sum embW via smem staging ----------------
// grid NF, block 256
__global__ __launch_bounds__(256) void k_cumw(
    const float* __restrict__ embW, const float* __restrict__ embb)
{
    __shared__ float w[KB * DE];    // 12 KB
    int n = blockIdx.x;
    int tid = threadIdx.x;
    for (int i = tid; i < KB * DE; i += 256)
        w[i] = embW[(size_t)n * KB * DE + i];
    __syncthreads();
    if (tid < DE) {
        float s = embb[n * DE + tid];
        #pragma unroll
        for (int k = 0; k < KB; k++) {
            g_cw[((size_t)n * KB + k) * DE + tid] = s;
            s += w[k * DE + tid];
        }
    }
}

// ---------------- weight transpose: W[e][k][n] -> T[e][n][k] fp16 ----------------
__global__ __launch_bounds__(256) void k_wsplit(
    const float* __restrict__ W, __half* __restrict__ Tw, int Kdim, int Ndim)
{
    __shared__ float t[32][33];
    int e = blockIdx.z;
    int kb = blockIdx.y * 32;
    int nb = blockIdx.x * 32;
    int tx = threadIdx.x, ty = threadIdx.y;
    const float* Wb = W + (size_t)e * Kdim * Ndim;
    #pragma unroll
    for (int i = ty; i < 32; i += 8)
        t[i][tx] = Wb[(size_t)(kb + i) * Ndim + nb + tx];
    __syncthreads();
    #pragma unroll
    for (int i = ty; i < 32; i += 8) {
        float v = t[tx][i];
        size_t o = ((size_t)e * Ndim + nb + i) * Kdim + kb + tx;
        Tw[o] = __float2half_rn(v);
    }
}

// ---------------- PLE via prefix-sum + ReLU -> flat fp16, + fused gate partials ----------------
__global__ __launch_bounds__(256) void k_ple(
    const float* __restrict__ x, const float* __restrict__ plew,
    const float* __restrict__ pleb, const float* __restrict__ embW,
    const float* __restrict__ gW)
{
    int n = blockIdx.x;
    int b0 = blockIdx.y * 64;
    int tid = threadIdx.x;

    __shared__ float wsh[KB], bsh[KB];
    __shared__ int   jr[64];
    __shared__ float fr[64];
    __shared__ float gwsh[DE][E];

    if (tid < KB) { wsh[tid] = plew[n * KB + tid]; bsh[tid] = pleb[n * KB + tid]; }
    for (int i = tid; i < DE * E; i += 256)
        ((float*)gwsh)[i] = gW[(size_t)(n * DE) * E + i];
    __syncthreads();

    if (tid < 64) {
        float xv = x[(b0 + tid) * NF + n];
        int j = 0;
        #pragma unroll
        for (int k = 0; k < KB; k++) {
            float enc = bsh[k] + wsh[k] * xv;
            j += (enc >= 1.f) ? 1 : 0;
        }
        if (j > KB - 1) j = KB - 1;
        float enc = bsh[j] + wsh[j] * xv;
        jr[tid] = j;
        fr[tid] = fmaxf(fminf(enc, 1.f), 0.f);
    }
    __syncthreads();

    int c0 = (tid & 15) * 4;
    int r0 = (tid >> 4) * 4;
    int lane = tid & 31;

    float v[4][4];
    #pragma unroll
    for (int r = 0; r < 4; r++) {
        int row = r0 + r;
        int j = jr[row];
        float f = fr[row];
        size_t base = ((size_t)n * KB + j) * DE + c0;
        float4 cw = *(const float4*)&g_cw[base];
        float4 w  = *(const float4*)&embW[base];
        v[r][0] = fmaxf(cw.x + f * w.x, 0.f);
        v[r][1] = fmaxf(cw.y + f * w.y, 0.f);
        v[r][2] = fmaxf(cw.z + f * w.z, 0.f);
        v[r][3] = fmaxf(cw.w + f * w.w, 0.f);
        size_t idx = (size_t)(b0 + row) * F + n * DE + c0;
        *(uint2*)&g_flat[idx] = make_uint2(pack_h2(v[r][0], v[r][1]),
                                           pack_h2(v[r][2], v[r][3]));
    }

    float p[4][E];
    #pragma unroll
    for (int r = 0; r < 4; r++)
        #pragma unroll
        for (int e = 0; e < E; e++) p[r][e] = 0.f;

    #pragma unroll
    for (int j = 0; j < 4; j++) {
        float gw[E];
        #pragma unroll
        for (int e = 0; e < E; e++) gw[e] = gwsh[c0 + j][e];
        #pragma unroll
        for (int r = 0; r < 4; r++)
            #pragma unroll
            for (int e = 0; e < E; e++)
                p[r][e] += v[r][j] * gw[e];
    }

    #pragma unroll
    for (int off = 8; off; off >>= 1)
        #pragma unroll
        for (int r = 0; r < 4; r++)
            #pragma unroll
            for (int e = 0; e < E; e++)
                p[r][e] += __shfl_xor_sync(0xffffffffu, p[r][e], off);

    if ((lane & 15) == 0) {
        #pragma unroll
        for (int r = 0; r < 4; r++) {
            int b = b0 + r0 + r;
            float* dst = &g_pl[((size_t)b * NF + n) * E];
            *(float4*)&dst[0] = make_float4(p[r][0], p[r][1], p[r][2], p[r][3]);
            *(float4*)&dst[4] = make_float4(p[r][4], p[r][5], p[r][6], p[r][7]);
        }
    }
}

// ---------------- gate reduce + top-2 ----------------
__global__ __launch_bounds__(256) void k_gate2(const float* __restrict__ gb)
{
    int b0 = blockIdx.x * 32;
    int tid = threadIdx.x;
    int r = tid >> 3;
    int e = tid & 7;
    int b = b0 + r;

    const float* p = &g_pl[((size_t)b * NF) * E + e];
    float s = 0.f;
    #pragma unroll
    for (int n = 0; n < NF; n++) s += p[n * E];
    s += gb[e];

    __shared__ float sl[32][E];
    sl[r][e] = s;
    __syncthreads();

    if (e == 0) {
        int i0 = 0;
        #pragma unroll
        for (int q = 1; q < E; q++) if (sl[r][q] > sl[r][i0]) i0 = q;
        int i1 = (i0 == 0) ? 1 : 0;
        #pragma unroll
        for (int q = 0; q < E; q++) if (q != i0 && sl[r][q] > sl[r][i1]) i1 = q;
        float e1 = __expf(sl[r][i1] - sl[r][i0]);
        float inv = 1.f / (1.f + e1);
        g_te[b * 2 + 0] = i0;  g_tg[b * 2 + 0] = inv;
        g_te[b * 2 + 1] = i1;  g_tg[b * 2 + 1] = e1 * inv;
        atomicAdd(&g_count[i0], 1);
        atomicAdd(&g_count[i1], 1);
    }
}

__global__ void k_scan() {
    if (threadIdx.x == 0) {
        int s = 0;
        for (int e = 0; e < E; e++) { g_base[e] = s; g_cursor[e] = s; s += g_count[e]; }
    }
}

__global__ __launch_bounds__(256) void k_assign() {
    int b = blockIdx.x * 256 + threadIdx.x;
    if (b >= B) return;
    #pragma unroll
    for (int j = 0; j < 2; j++) {
        int e = g_te[b * 2 + j];
        int slot = atomicAdd(&g_cursor[e], 1);
        g_rows[slot]  = b;
        g_gates[slot] = g_tg[b * 2 + j];
        g_pair[b * 2 + j] = slot;
    }
}

// ---------------- moe combine: eo pairs -> fp16 moe[B][O] ----------------
// grid B/4, block 256: thread = (row tid>>6, 8 cols)
__global__ __launch_bounds__(256) void k_moe()
{
    int b = blockIdx.x * 4 + (threadIdx.x >> 6);
    int c = (threadIdx.x & 63) * 8;
    int s0 = g_pair[b * 2 + 0], s1 = g_pair[b * 2 + 1];
    const float* e0 = &g_eo[(size_t)s0 * O + c];
    const float* e1 = &g_eo[(size_t)s1 * O + c];
    float4 a0 = *(const float4*)&e0[0], a1 = *(const float4*)&e0[4];
    float4 b0 = *(const float4*)&e1[0], b1 = *(const float4*)&e1[4];
    uint4 outv;
    outv.x = pack_h2(a0.x + b0.x, a0.y + b0.y);
    outv.y = pack_h2(a0.z + b0.z, a0.w + b0.w);
    outv.z = pack_h2(a1.x + b1.x, a1.y + b1.y);
    outv.w = pack_h2(a1.z + b1.z, a1.w + b1.w);
    *(uint4*)&g_moe[(size_t)b * O + c] = outv;
}

// ---------------- fp16 register-MMA GEMM ----------------
// MODE 0: gathered rows -> relu fp16 g_h.  MODE 1: slot rows -> gate*(acc+bias) fp32 g_eo.
// MODE 2: direct rows (tower) -> relu fp16 g_th.
#define GBM 128
#define GKT 64
#define STG_BYTES 32768u
#define OFF_B_C   16384u

template<int KTOT, int NTOT, int MODE>
__global__ __launch_bounds__(256, 2) void k_mma_gemm(
    const __half* __restrict__ A, const __half* __restrict__ Wt,
    const float* __restrict__ bias)
{
    int e = blockIdx.z;
    int cnt = (MODE == 2) ? B : g_count[e];
    int m0 = blockIdx.y * GBM;
    if (m0 >= cnt) return;
    int base = (MODE == 2) ? 0 : g_base[e];
    int n0 = blockIdx.x * 128;

    extern __shared__ char smem[];
    uint32_t sb = smem_to_u32(smem);
    __shared__ int rows_s[GBM];

    int tid = threadIdx.x;
    int lane = tid & 31, wid = tid >> 5;

    if (MODE == 0 && tid < GBM) {
        int m = m0 + tid;
        rows_s[tid] = (m < cnt) ? g_rows[base + m] : -1;
    }
    __syncthreads();

    int lrow = tid >> 1;
    int lcb  = (tid & 1) * 4;
    const __half* arow;
    int abytes;
    if (MODE == 0) {
        int gr = rows_s[lrow];
        abytes = (gr >= 0) ? 16 : 0;
        int r = (gr >= 0) ? gr : 0;
        arow = A + (size_t)r * KTOT;
    } else {
        int m = m0 + lrow;
        abytes = (m < cnt) ? 16 : 0;
        size_t r = (m < cnt) ? (size_t)(base + m) : 0;
        arow = A + r * KTOT;
    }
    const __half* brow = Wt + ((size_t)e * NTOT + n0 + lrow) * KTOT;
    uint32_t lsw = (uint32_t)((lrow & 7) << 4);
    uint32_t lbase = (uint32_t)(lrow * 128);

    int wm = wid >> 2;
    int wn = wid & 3;
    int a_row = wm * 64 + (lane & 15);
    uint32_t a_c  = (uint32_t)((lane >> 4) * 16);
    uint32_t asw  = (uint32_t)((a_row & 7) << 4);
    int b_row = wn * 32 + (lane & 7) + ((lane >> 4) << 3);
    uint32_t b_c  = (uint32_t)(((lane >> 3) & 1) * 16);
    uint32_t bsw  = (uint32_t)((b_row & 7) << 4);

    float acc[4][4][4];
    #pragma unroll
    for (int i = 0; i < 4; i++)
        #pragma unroll
        for (int j = 0; j < 4; j++)
            #pragma unroll
            for (int q = 0; q < 4; q++) acc[i][j][q] = 0.f;

    const int NT = KTOT / GKT;

    #define LOAD_STAGE(stg_, kt_) do {                                           \
        uint32_t s_ = sb + (uint32_t)(stg_) * STG_BYTES;                          \
        int k0_ = (kt_) * GKT;                                                    \
        _Pragma("unroll")                                                         \
        for (int q = 0; q < 4; q++) {                                             \
            int ch = lcb + q;                                                     \
            uint32_t so = lbase + (((uint32_t)(ch * 16)) ^ lsw);                  \
            cp_async16(s_ + so, arow + k0_ + ch * 8, abytes);                     \
            cp_async16(s_ + OFF_B_C + so, brow + k0_ + ch * 8, 16);               \
        }                                                                         \
        CP_COMMIT();                                                              \
    } while (0)

    LOAD_STAGE(0, 0);
    if (NT > 1) LOAD_STAGE(1, 1);

    int stg = 0;
    for (int kt = 0; kt < NT; kt++) {
        if (kt + 2 < NT) {
            int ns = stg + 2; if (ns >= 3) ns -= 3;
            LOAD_STAGE(ns, kt + 2);
            CP_WAIT(2);
        } else if (kt + 1 < NT) {
            CP_WAIT(1);
        } else {
            CP_WAIT(0);
        }
        __syncthreads();

        uint32_t s0 = sb + (uint32_t)stg * STG_BYTES;
        #pragma unroll
        for (int kk = 0; kk < 4; kk++) {
            uint32_t ah[4][4], bh[2][4];
            #pragma unroll
            for (int i = 0; i < 4; i++) {
                uint32_t ro = (uint32_t)((a_row + i * 16) * 128);
                ldsm_x4(ah[i], s0 + ro + ((a_c + kk * 32) ^ asw));
            }
            #pragma unroll
            for (int p = 0; p < 2; p++) {
                uint32_t ro = (uint32_t)((b_row + p * 16) * 128);
                ldsm_x4(bh[p], s0 + OFF_B_C + ro + ((b_c + kk * 32) ^ bsw));
            }
            #pragma unroll
            for (int i = 0; i < 4; i++)
                #pragma unroll
                for (int j = 0; j < 4; j++) {
                    const uint32_t* bj = &bh[j >> 1][(j & 1) * 2];
                    mma_f16(acc[i][j], ah[i], bj);
                }
        }
        __syncthreads();
        stg = (stg == 2) ? 0 : stg + 1;
    }
    #undef LOAD_STAGE

    int g = lane >> 2;
    int cg = (lane & 3) * 2;
    #pragma unroll
    for (int i = 0; i < 4; i++) {
        #pragma unroll
        for (int half = 0; half < 2; half++) {
            int m = m0 + wm * 64 + i * 16 + g + half * 8;
            if (m < cnt) {
                int slot = base + m;
                float gate = (MODE == 1) ? g_gates[slot] : 0.f;
                #pragma unroll
                for (int j = 0; j < 4; j++) {
                    int col = n0 + wn * 32 + j * 8 + cg;
                    float bv0 = bias[(size_t)e * NTOT + col];
                    float bv1 = bias[(size_t)e * NTOT + col + 1];
                    float v0 = acc[i][j][half * 2 + 0] + bv0;
                    float v1 = acc[i][j][half * 2 + 1] + bv1;
                    if (MODE == 0) {
                        v0 = fmaxf(v0, 0.f); v1 = fmaxf(v1, 0.f);
                        *(uint32_t*)&g_h[(size_t)slot * H + col] = pack_h2(v0, v1);
                    } else if (MODE == 1) {
                        float2 v = make_float2(gate * v0, gate * v1);
                        *(float2*)&g_eo[(size_t)slot * O + col] = v;
                    } else {
                        v0 = fmaxf(v0, 0.f); v1 = fmaxf(v1, 0.f);
                        *(uint32_t*)&g_th[(size_t)e * B * NTOT + (size_t)m * NTOT + col]
                            = pack_h2(v0, v1);
                    }
                }
            }
        }
    }
}

// ---------------- tower final: out[b][t] = th[t][b][:] . tw2[t][:] + tb2[t] ----------------
// grid B/4, block 256: warp w -> (row, task)
__global__ __launch_bounds__(256) void k_tower2(
    const float* __restrict__ tw2, const float* __restrict__ tb2,
    float* __restrict__ out)
{
    int tid = threadIdx.x;
    int lane = tid & 31, wid = tid >> 5;
    int idx = blockIdx.x * 8 + wid;     // 8 (row,task) pairs per block
    int b = idx >> 1;
    int t = idx & 1;

    const __half* th = &g_th[(size_t)t * B * TH + (size_t)b * TH + lane * 8];
    uint4 hv = *(const uint4*)th;
    const float* w = &tw2[t * TH + lane * 8];
    float4 w0 = *(const float4*)&w[0], w1 = *(const float4*)&w[4];

    __half2 h01 = *(__half2*)&hv.x, h23 = *(__half2*)&hv.y;
    __half2 h45 = *(__half2*)&hv.z, h67 = *(__half2*)&hv.w;
    float s = __half2float(__low2half(h01)) * w0.x
            + __half2float(__high2half(h01)) * w0.y
            + __half2float(__low2half(h23)) * w0.z
            + __half2float(__high2half(h23)) * w0.w
            + __half2float(__low2half(h45)) * w1.x
            + __half2float(__high2half(h45)) * w1.y
            + __half2float(__low2half(h67)) * w1.z
            + __half2float(__high2half(h67)) * w1.w;
    #pragma unroll
    for (int off = 16; off; off >>= 1)
        s += __shfl_down_sync(0xffffffffu, s, off);
    if (lane == 0) out[b * T + t] = s + tb2[t];
}

// ---------------- launch ----------------
extern "C" void kernel_launch(void* const* d_in, const int* in_sizes, int n_in,
                              void* d_out, int out_size)
{
    const float* x     = (const float*)d_in[0];
    const float* plew  = (const float*)d_in[1];
    const float* pleb  = (const float*)d_in[2];
    const float* embW  = (const float*)d_in[3];
    const float* embb  = (const float*)d_in[4];
    const float* gW    = (const float*)d_in[5];
    const float* gb    = (const float*)d_in[6];
    const float* eW1   = (const float*)d_in[7];
    const float* eb1   = (const float*)d_in[8];
    const float* eW2   = (const float*)d_in[9];
    const float* eb2   = (const float*)d_in[10];
    const float* tw1   = (const float*)d_in[11];
    const float* tb1   = (const float*)d_in[12];
    const float* tw2   = (const float*)d_in[13];
    const float* tb2   = (const float*)d_in[14];
    float* out = (float*)d_out;

    const int SMEM_BYTES = 3 * (int)STG_BYTES;   // 98304
    static cudaStream_t s2 = nullptr;
    static cudaEvent_t ev_fork = nullptr, ev_join = nullptr;
    if (!s2) {
        cudaFuncSetAttribute(k_mma_gemm<F, H, 0>, cudaFuncAttributeMaxDynamicSharedMemorySize, SMEM_BYTES);
        cudaFuncSetAttribute(k_mma_gemm<H, O, 1>, cudaFuncAttributeMaxDynamicSharedMemorySize, SMEM_BYTES);
        cudaFuncSetAttribute(k_mma_gemm<O, TH, 2>, cudaFuncAttributeMaxDynamicSharedMemorySize, SMEM_BYTES);
        cudaStreamCreateWithFlags(&s2, cudaStreamNonBlocking);
        cudaEventCreateWithFlags(&ev_fork, cudaEventDisableTiming);
        cudaEventCreateWithFlags(&ev_join, cudaEventDisableTiming);
    }

    __half *w1t, *w2t, *w3t, *flat, *h_buf, *moe;
    cudaGetSymbolAddress((void**)&w1t, g_w1t);
    cudaGetSymbolAddress((void**)&w2t, g_w2t);
    cudaGetSymbolAddress((void**)&w3t, g_w3t);
    cudaGetSymbolAddress((void**)&flat, g_flat);
    cudaGetSymbolAddress((void**)&h_buf, g_h);
    cudaGetSymbolAddress((void**)&moe, g_moe);

    k_init<<<1, 32>>>();

    // fork: weight conversion runs concurrently with PLE->gate->assign
    cudaEventRecord(ev_fork, 0);
    cudaStreamWaitEvent(s2, ev_fork, 0);
    k_wsplit<<<dim3(H / 32, F / 32, E), dim3(32, 8), 0, s2>>>(eW1, w1t, F, H);
    k_wsplit<<<dim3(O / 32, H / 32, E), dim3(32, 8), 0, s2>>>(eW2, w2t, H, O);
    k_wsplit<<<dim3(TH / 32, O / 32, T), dim3(32, 8), 0, s2>>>(tw1, w3t, O, TH);
    cudaEventRecord(ev_join, s2);

    k_cumw<<<NF, 256>>>(embW, embb);
    k_ple<<<dim3(NF, B / 64), 256>>>(x, plew, pleb, embW, gW);
    k_gate2<<<B / 32, 256>>>(gb);
    k_scan<<<1, 32>>>();
    k_assign<<<(B + 255) / 256, 256>>>();

    // join before GEMM1 consumes weights
    cudaStreamWaitEvent(0, ev_join, 0);

    k_mma_gemm<F, H, 0><<<dim3(H / 128, B / GBM, E), 256, SMEM_BYTES>>>(flat, w1t, eb1);
    k_mma_gemm<H, O, 1><<<dim3(O / 128, B / GBM, E), 256, SMEM_BYTES>>>(h_buf, w2t, eb2);
    k_moe<<<B / 4, 256>>>();
    k_mma_gemm<O, TH, 2><<<dim3(TH / 128, B / GBM, T), 256, SMEM_BYTES>>>(moe, w3t, tb1);
    k_tower2<<<B / 4, 256>>>(tw2, tb2, out);
}